// round 1
// baseline (speedup 1.0000x reference)
#include <cuda_runtime.h>
#include <math.h>

#define Bn   128
#define Kn   32
#define In   12000
#define Hn   600
#define LATn 200
#define ROWS (Bn*Kn)      // 4096
#define ENCn (2*LATn)     // 400

#define Z_OFF  0
#define NO_OFF (ROWS*LATn)                 // 819200
#define KL_OFF (NO_OFF + Bn*In)            // 2355200
#define X_OFF  (KL_OFF + 1)                // 2355201

// ---------------- scratch (no allocation allowed) ----------------
__device__ float  g_h[ROWS*Hn];      // 9.83 MB
__device__ float  g_enc[ROWS*ENCn];  // 6.55 MB
__device__ float  g_zn[ROWS*LATn];   // 3.28 MB
__device__ float  g_itn[In*LATn];    // 9.60 MB
__device__ double g_kl;

// ---------------- items l2-normalize: one warp per row ----------------
__global__ void items_norm_kernel(const float* __restrict__ items, float* __restrict__ itn)
{
    int warp = (blockIdx.x * blockDim.x + threadIdx.x) >> 5;
    int lane = threadIdx.x & 31;
    if (warp >= In) return;
    const float* src = items + (long)warp * LATn;
    float v[7];
    float ss = 0.f;
    int cnt = 0;
    for (int j = lane; j < LATn; j += 32) { float t = src[j]; v[cnt++] = t; ss += t*t; }
    #pragma unroll
    for (int o = 16; o; o >>= 1) ss += __shfl_xor_sync(0xffffffffu, ss, o);
    float inv = 1.0f / fmaxf(sqrtf(ss), 1e-12f);
    float* dst = itn + (long)warp * LATn;
    cnt = 0;
    for (int j = lane; j < LATn; j += 32) dst[j] = v[cnt++] * inv;
}

// ---------------- x = masked gram row / l2norm : one block per (b,k) ----------------
__global__ void x_kernel(const float* __restrict__ rating, const int* __restrict__ items_idx,
                         const float* __restrict__ gram, float* __restrict__ x_out)
{
    int bk  = blockIdx.x;       // 0..4095
    int b   = bk >> 5;          // / Kn
    int row = items_idx[bk];
    const float* r = rating + (long)b * In;
    const float* g = gram   + (long)row * In;
    float ss = 0.f;
    for (int i = threadIdx.x; i < In; i += blockDim.x) {
        if (r[i] > 0.f) { float v = g[i]; ss += v * v; }
    }
    __shared__ float red[8];
    #pragma unroll
    for (int o = 16; o; o >>= 1) ss += __shfl_xor_sync(0xffffffffu, ss, o);
    if ((threadIdx.x & 31) == 0) red[threadIdx.x >> 5] = ss;
    __syncthreads();
    if (threadIdx.x < 8) {
        float t = red[threadIdx.x];
        #pragma unroll
        for (int o = 4; o; o >>= 1) t += __shfl_xor_sync(0xffu, t, o);
        if (threadIdx.x == 0) red[0] = t;
    }
    __syncthreads();
    float inv = 1.0f / fmaxf(sqrtf(red[0]), 1e-12f);
    float* dst = x_out + (long)bk * In;
    for (int i = threadIdx.x; i < In; i += blockDim.x) {
        float v = (r[i] > 0.f) ? g[i] : 0.f;
        dst[i] = v * inv;
    }
}

// ---------------- generic 128x128x16 fp32 GEMM, C = epi(A@B + bias) ----------------
// A [M,K] row-major, B [K,N] row-major. M assumed multiple of 128. N,K guarded.
template<int DO_TANH>
__global__ void __launch_bounds__(256) gemm_bias(const float* __restrict__ A,
                                                 const float* __restrict__ Bw,
                                                 const float* __restrict__ bias,
                                                 float* __restrict__ C,
                                                 int M, int N, int Kd)
{
    __shared__ float sA[16][129];
    __shared__ float sB[16][129];
    const int tid = threadIdx.x;
    const int tx = tid & 15, ty = tid >> 4;
    const int m0 = blockIdx.y * 128, n0 = blockIdx.x * 128;

    float acc[8][8];
    #pragma unroll
    for (int r = 0; r < 8; r++)
        #pragma unroll
        for (int c = 0; c < 8; c++) acc[r][c] = 0.f;

    const int aCol = tid & 15;   // k within tile
    const int aRow = tid >> 4;   // rows aRow + 16j
    float ra[8], rb[8];
    const int nk = (Kd + 15) >> 4;

    // prologue: load tile 0
    {
        int k0 = 0;
        #pragma unroll
        for (int j = 0; j < 8; j++) {
            int k = k0 + aCol;
            ra[j] = (k < Kd) ? A[(long)(m0 + aRow + 16*j) * Kd + k] : 0.f;
        }
        #pragma unroll
        for (int j = 0; j < 8; j++) {
            int idx = tid + 256*j;
            int brow = idx >> 7, bcol = idx & 127;
            int k = k0 + brow, n = n0 + bcol;
            rb[j] = (k < Kd && n < N) ? Bw[(long)k * N + n] : 0.f;
        }
    }
    #pragma unroll
    for (int j = 0; j < 8; j++) sA[aCol][aRow + 16*j] = ra[j];
    #pragma unroll
    for (int j = 0; j < 8; j++) {
        int idx = tid + 256*j;
        sB[idx >> 7][idx & 127] = rb[j];
    }
    __syncthreads();

    for (int kt = 0; ; kt++) {
        if (kt + 1 < nk) {
            int k0 = (kt + 1) * 16;
            #pragma unroll
            for (int j = 0; j < 8; j++) {
                int k = k0 + aCol;
                ra[j] = (k < Kd) ? A[(long)(m0 + aRow + 16*j) * Kd + k] : 0.f;
            }
            #pragma unroll
            for (int j = 0; j < 8; j++) {
                int idx = tid + 256*j;
                int brow = idx >> 7, bcol = idx & 127;
                int k = k0 + brow, n = n0 + bcol;
                rb[j] = (k < Kd && n < N) ? Bw[(long)k * N + n] : 0.f;
            }
        }
        #pragma unroll
        for (int k = 0; k < 16; k++) {
            float af[8], bf[8];
            #pragma unroll
            for (int r = 0; r < 8; r++) af[r] = sA[k][ty + 16*r];
            #pragma unroll
            for (int c = 0; c < 8; c++) bf[c] = sB[k][tx + 16*c];
            #pragma unroll
            for (int r = 0; r < 8; r++)
                #pragma unroll
                for (int c = 0; c < 8; c++) acc[r][c] += af[r] * bf[c];
        }
        if (kt + 1 == nk) break;
        __syncthreads();
        #pragma unroll
        for (int j = 0; j < 8; j++) sA[aCol][aRow + 16*j] = ra[j];
        #pragma unroll
        for (int j = 0; j < 8; j++) {
            int idx = tid + 256*j;
            sB[idx >> 7][idx & 127] = rb[j];
        }
        __syncthreads();
    }

    #pragma unroll
    for (int r = 0; r < 8; r++) {
        int m = m0 + ty + 16*r;
        #pragma unroll
        for (int c = 0; c < 8; c++) {
            int n = n0 + tx + 16*c;
            if (n < N) {
                float v = acc[r][c] + bias[n];
                if (DO_TANH) v = tanhf(v);
                C[(long)m * N + n] = v;
            }
        }
    }
}

// ---------------- enc postprocess: one warp per row ----------------
__global__ void postenc_kernel(const float* __restrict__ enc, float* __restrict__ z_out,
                               float* __restrict__ zn, double* __restrict__ kl_acc)
{
    int warp = (blockIdx.x * blockDim.x + threadIdx.x) >> 5;
    int lane = threadIdx.x & 31;
    if (warp >= ROWS) return;
    const float* e = enc + (long)warp * ENCn;
    float mv[7];
    float ss = 0.f, klp = 0.f;
    int cnt = 0;
    for (int j = lane; j < LATn; j += 32) {
        float m  = e[j];
        float lv = e[j + LATn];
        mv[cnt++] = m;
        ss  += m * m;
        klp += m * m + (expm1f(lv) - lv);   // e^lv - 1 - lv, cancellation-safe
    }
    #pragma unroll
    for (int o = 16; o; o >>= 1) {
        ss  += __shfl_xor_sync(0xffffffffu, ss, o);
        klp += __shfl_xor_sync(0xffffffffu, klp, o);
    }
    float inv = 1.0f / fmaxf(sqrtf(ss), 1e-12f);
    cnt = 0;
    for (int j = lane; j < LATn; j += 32) {
        z_out[(long)warp * LATn + j] = mv[cnt];
        zn[(long)warp * LATn + j]    = mv[cnt] * inv;
        cnt++;
    }
    if (lane == 0) atomicAdd(kl_acc, (double)klp);
}

__global__ void zero_kl_kernel(double* p) { *p = 0.0; }
__global__ void fin_kl_kernel(const double* p, float* out) { *out = (float)(0.5 * (*p) / (double)ROWS); }

// ---------------- similarity GEMM with fused exp / segmented mean / log ----------------
// A = zn [4096,200] row-major, Bt = itn [12000,200] row-major (used transposed).
// Block tile 128x128; rows m0..m0+127 span exactly users m0/32 .. m0/32+3.
__global__ void __launch_bounds__(256) sim_kernel(const float* __restrict__ A,
                                                  const float* __restrict__ Bt,
                                                  float* __restrict__ no_out)
{
    __shared__ float sA[16][129];
    __shared__ float sB[16][129];
    __shared__ float red[4][128];
    const int tid = threadIdx.x;
    const int tx = tid & 15, ty = tid >> 4;
    const int m0 = blockIdx.y * 128, n0 = blockIdx.x * 128;
    const int Kd = LATn, Nn = In;

    float acc[8][8];
    #pragma unroll
    for (int r = 0; r < 8; r++)
        #pragma unroll
        for (int c = 0; c < 8; c++) acc[r][c] = 0.f;

    const int aCol = tid & 15;
    const int aRow = tid >> 4;
    float ra[8], rb[8];
    const int nk = (Kd + 15) >> 4;  // 13

    {
        int k0 = 0;
        #pragma unroll
        for (int j = 0; j < 8; j++) {
            int k = k0 + aCol;
            ra[j] = (k < Kd) ? A[(long)(m0 + aRow + 16*j) * Kd + k] : 0.f;
        }
        #pragma unroll
        for (int j = 0; j < 8; j++) {
            int idx = tid + 256*j;
            int nl = idx >> 4, k = idx & 15;
            rb[j] = (k0 + k < Kd && n0 + nl < Nn) ? Bt[(long)(n0 + nl) * Kd + k0 + k] : 0.f;
        }
    }
    #pragma unroll
    for (int j = 0; j < 8; j++) sA[aCol][aRow + 16*j] = ra[j];
    #pragma unroll
    for (int j = 0; j < 8; j++) {
        int idx = tid + 256*j;
        sB[idx & 15][idx >> 4] = rb[j];
    }
    __syncthreads();

    for (int kt = 0; ; kt++) {
        if (kt + 1 < nk) {
            int k0 = (kt + 1) * 16;
            #pragma unroll
            for (int j = 0; j < 8; j++) {
                int k = k0 + aCol;
                ra[j] = (k < Kd) ? A[(long)(m0 + aRow + 16*j) * Kd + k] : 0.f;
            }
            #pragma unroll
            for (int j = 0; j < 8; j++) {
                int idx = tid + 256*j;
                int nl = idx >> 4, k = idx & 15;
                rb[j] = (k0 + k < Kd && n0 + nl < Nn) ? Bt[(long)(n0 + nl) * Kd + k0 + k] : 0.f;
            }
        }
        #pragma unroll
        for (int k = 0; k < 16; k++) {
            float af[8], bf[8];
            #pragma unroll
            for (int r = 0; r < 8; r++) af[r] = sA[k][ty + 16*r];
            #pragma unroll
            for (int c = 0; c < 8; c++) bf[c] = sB[k][tx + 16*c];
            #pragma unroll
            for (int r = 0; r < 8; r++)
                #pragma unroll
                for (int c = 0; c < 8; c++) acc[r][c] += af[r] * bf[c];
        }
        if (kt + 1 == nk) break;
        __syncthreads();
        #pragma unroll
        for (int j = 0; j < 8; j++) sA[aCol][aRow + 16*j] = ra[j];
        #pragma unroll
        for (int j = 0; j < 8; j++) {
            int idx = tid + 256*j;
            sB[idx & 15][idx >> 4] = rb[j];
        }
        __syncthreads();
    }

    // epilogue: p = exp(dot/TAU); segmented sum over 32 rows (= user)
    for (int i = tid; i < 4*128; i += 256) ((float*)red)[i] = 0.f;
    __syncthreads();
    #pragma unroll
    for (int c = 0; c < 8; c++) {
        int col = tx + 16*c;
        float s0 = 0.f, s1 = 0.f, s2 = 0.f, s3 = 0.f;
        #pragma unroll
        for (int r = 0; r < 8; r++) {
            float p = __expf(acc[r][c] * 10.0f);   // /TAU, TAU=0.1
            if (r < 2) s0 += p;
            else if (r < 4) s1 += p;
            else if (r < 6) s2 += p;
            else s3 += p;
        }
        atomicAdd(&red[0][col], s0);
        atomicAdd(&red[1][col], s1);
        atomicAdd(&red[2][col], s2);
        atomicAdd(&red[3][col], s3);
    }
    __syncthreads();
    for (int i = tid; i < 4*128; i += 256) {
        int u = i >> 7, col = i & 127;
        int n = n0 + col;
        if (n < Nn) {
            int b = (m0 >> 5) + u;
            no_out[(long)b * In + n] = logf(red[u][col] * (1.0f/32.0f) + 1.0f);
        }
    }
}

// ---------------- launch ----------------
extern "C" void kernel_launch(void* const* d_in, const int* in_sizes, int n_in,
                              void* d_out, int out_size)
{
    const float* rating    = (const float*)d_in[0];
    const int*   items_idx = (const int*)  d_in[1];
    const float* gram      = (const float*)d_in[2];
    const float* W1        = (const float*)d_in[3];
    const float* b1        = (const float*)d_in[4];
    const float* W2        = (const float*)d_in[5];
    const float* b2        = (const float*)d_in[6];
    const float* items     = (const float*)d_in[7];

    float* out    = (float*)d_out;
    float* z_out  = out + Z_OFF;
    float* no_out = out + NO_OFF;
    float* kl_out = out + KL_OFF;
    float* x_out  = out + X_OFF;

    float *h, *enc, *zn, *itn; double* klp;
    cudaGetSymbolAddress((void**)&h,   g_h);
    cudaGetSymbolAddress((void**)&enc, g_enc);
    cudaGetSymbolAddress((void**)&zn,  g_zn);
    cudaGetSymbolAddress((void**)&itn, g_itn);
    cudaGetSymbolAddress((void**)&klp, g_kl);

    items_norm_kernel<<<(In*32 + 255)/256, 256>>>(items, itn);
    x_kernel<<<ROWS, 256>>>(rating, items_idx, gram, x_out);
    zero_kl_kernel<<<1, 1>>>(klp);
    // h = tanh(x @ W1 + b1)
    gemm_bias<1><<<dim3((Hn + 127)/128, ROWS/128), 256>>>(x_out, W1, b1, h, ROWS, Hn, In);
    // enc = h @ W2 + b2
    gemm_bias<0><<<dim3((ENCn + 127)/128, ROWS/128), 256>>>(h, W2, b2, enc, ROWS, ENCn, Hn);
    postenc_kernel<<<(ROWS*32 + 255)/256, 256>>>(enc, z_out, zn, klp);
    fin_kl_kernel<<<1, 1>>>(klp, kl_out);
    // new_output = log(mean_k exp(zn @ itn^T / TAU) + 1)
    sim_kernel<<<dim3((In + 127)/128, ROWS/128), 256>>>(zn, itn, no_out);
}

// round 3
// speedup vs baseline: 2.2285x; 2.2285x over previous
#include <cuda_runtime.h>
#include <cuda_bf16.h>
#include <math.h>
#include <stdint.h>

#define Bn   128
#define Kn   32
#define In   12000
#define Hn   600
#define LATn 200
#define ROWS (Bn*Kn)      // 4096
#define ENCn (2*LATn)     // 400

#define KPAD1 12032       // In padded to 64
#define NPAD1 640         // Hn padded to 128
#define KPAD2 256         // LATn padded to 64
#define NPAD2 12032       // In padded to 128

#define Z_OFF  0
#define NO_OFF (ROWS*LATn)                 // 819200
#define KL_OFF (NO_OFF + Bn*In)            // 2355200
#define X_OFF  (KL_OFF + 1)                // 2355201

typedef __nv_bfloat16 BF;

// ---------------- scratch (no allocation allowed) ----------------
__device__ float  g_h[ROWS*Hn];
__device__ float  g_enc[ROWS*ENCn];
__device__ double g_kl;
__device__ BF g_xhi[(size_t)ROWS*KPAD1];
__device__ BF g_xlo[(size_t)ROWS*KPAD1];
__device__ BF g_w1hi[(size_t)NPAD1*KPAD1];
__device__ BF g_w1lo[(size_t)NPAD1*KPAD1];
__device__ BF g_znhi[(size_t)ROWS*KPAD2];
__device__ BF g_znlo[(size_t)ROWS*KPAD2];
__device__ BF g_ithi[(size_t)NPAD2*KPAD2];
__device__ BF g_itlo[(size_t)NPAD2*KPAD2];

// ==================== helpers ====================
__device__ __forceinline__ uint32_t smem_u32(const void* p) {
    uint32_t a;
    asm("{ .reg .u64 t; cvta.to.shared.u64 t, %1; cvt.u32.u64 %0, t; }" : "=r"(a) : "l"(p));
    return a;
}
#define CP16(dst, src) asm volatile("cp.async.cg.shared.global [%0], [%1], 16;" :: "r"(dst), "l"(src) : "memory")
#define CP_COMMIT()    asm volatile("cp.async.commit_group;" ::: "memory")
#define CP_WAIT1()     asm volatile("cp.async.wait_group 1;" ::: "memory")
#define CP_WAIT0()     asm volatile("cp.async.wait_group 0;" ::: "memory")

__device__ __forceinline__ void ldsm4(uint32_t r[4], uint32_t addr) {
    asm volatile("ldmatrix.sync.aligned.m8n8.x4.shared.b16 {%0,%1,%2,%3}, [%4];"
        : "=r"(r[0]), "=r"(r[1]), "=r"(r[2]), "=r"(r[3]) : "r"(addr));
}
__device__ __forceinline__ void mma16816(float d[4], const uint32_t a[4], uint32_t b0, uint32_t b1) {
    asm volatile("mma.sync.aligned.m16n8k16.row.col.f32.bf16.bf16.f32 "
        "{%0,%1,%2,%3}, {%4,%5,%6,%7}, {%8,%9}, {%0,%1,%2,%3};"
        : "+f"(d[0]), "+f"(d[1]), "+f"(d[2]), "+f"(d[3])
        : "r"(a[0]), "r"(a[1]), "r"(a[2]), "r"(a[3]), "r"(b0), "r"(b1));
}

// smem stage layout: Ahi[128*80] Alo Bhi Blo, stage stride 40960, 2 stages.
#define ROWB80   80
#define OFF_ALO  10240
#define OFF_BHI  20480
#define OFF_BLO  30720
#define STAGE_B  40960
#define SMEM_SZ  (2*STAGE_B)

// ---------------- split-bf16 mma mainloop: acc += Ah*Bh + Ah*Bl + Al*Bh ----------------
// A [.][kpad] rows m0..m0+127, B [.][kpad] rows n0..n0+127, both K-major bf16.
__device__ __forceinline__ void mma_mainloop(float acc[2][8][4],
    const BF* __restrict__ Ahi, const BF* __restrict__ Alo,
    const BF* __restrict__ Bhi, const BF* __restrict__ Blo,
    long m0, long n0, int kpad, int nch, uint32_t smem_base)
{
    const int tid  = threadIdx.x;
    const int lane = tid & 31, wid = tid >> 5;
    const int wm = wid & 3, wn = wid >> 2;
    const int r0  = tid >> 2;           // 0..63
    const int c16 = (tid & 3) * 16;     // byte col in 64B row
    const long rowb = (long)kpad * 2;

    const char* pAh = (const char*)(Ahi + (m0 + r0) * (long)kpad) + c16;
    const char* pAl = (const char*)(Alo + (m0 + r0) * (long)kpad) + c16;
    const char* pBh = (const char*)(Bhi + (n0 + r0) * (long)kpad) + c16;
    const char* pBl = (const char*)(Blo + (n0 + r0) * (long)kpad) + c16;
    const uint32_t dlo = r0 * ROWB80 + c16;
    const uint32_t dhi = (r0 + 64) * ROWB80 + c16;
    const long rskip = 64 * rowb;

    // issue chunk 0
    {
        uint32_t st = smem_base;
        CP16(st + dlo,            pAh);          CP16(st + dhi,            pAh + rskip);
        CP16(st + OFF_ALO + dlo,  pAl);          CP16(st + OFF_ALO + dhi,  pAl + rskip);
        CP16(st + OFF_BHI + dlo,  pBh);          CP16(st + OFF_BHI + dhi,  pBh + rskip);
        CP16(st + OFF_BLO + dlo,  pBl);          CP16(st + OFF_BLO + dhi,  pBl + rskip);
        CP_COMMIT();
    }

    for (int c = 0; c < nch; c++) {
        if (c + 1 < nch) {
            uint32_t st = smem_base + ((c + 1) & 1) * STAGE_B;
            long go = (long)(c + 1) * 64;
            CP16(st + dlo,           pAh + go);   CP16(st + dhi,           pAh + rskip + go);
            CP16(st + OFF_ALO + dlo, pAl + go);   CP16(st + OFF_ALO + dhi, pAl + rskip + go);
            CP16(st + OFF_BHI + dlo, pBh + go);   CP16(st + OFF_BHI + dhi, pBh + rskip + go);
            CP16(st + OFF_BLO + dlo, pBl + go);   CP16(st + OFF_BLO + dhi, pBl + rskip + go);
            CP_COMMIT();
            CP_WAIT1();
        } else {
            CP_WAIT0();
        }
        __syncthreads();

        uint32_t sA = smem_base + (c & 1) * STAGE_B;
        uint32_t sB = sA + OFF_BHI;
        #pragma unroll
        for (int s = 0; s < 2; s++) {
            uint32_t ah[2][4], al[2][4];
            #pragma unroll
            for (int t = 0; t < 2; t++) {
                uint32_t row = wm * 32 + t * 16 + (lane & 15);
                uint32_t ad = sA + row * ROWB80 + s * 32 + ((lane >> 4) & 1) * 16;
                ldsm4(ah[t], ad);
                ldsm4(al[t], ad + OFF_ALO);
            }
            uint32_t bh[4][4], bl[4][4];
            #pragma unroll
            for (int p = 0; p < 4; p++) {
                uint32_t row = wn * 64 + p * 16 + (lane & 7) + ((lane & 16) ? 8 : 0);
                uint32_t ad = sB + row * ROWB80 + s * 32 + ((lane & 8) ? 16 : 0);
                ldsm4(bh[p], ad);
                ldsm4(bl[p], ad + OFF_ALO);   // Blo is +10240 after Bhi
            }
            #pragma unroll
            for (int t = 0; t < 2; t++)
                #pragma unroll
                for (int p = 0; p < 4; p++)
                    #pragma unroll
                    for (int hh = 0; hh < 2; hh++) {
                        int j = p * 2 + hh;
                        mma16816(acc[t][j], ah[t], bh[p][hh * 2], bh[p][hh * 2 + 1]);
                        mma16816(acc[t][j], ah[t], bl[p][hh * 2], bl[p][hh * 2 + 1]);
                        mma16816(acc[t][j], al[t], bh[p][hh * 2], bh[p][hh * 2 + 1]);
                    }
        }
        __syncthreads();
    }
}

// ---------------- GEMM1: h = tanh(x @ W1 + b1) ----------------
__global__ void __launch_bounds__(256) gemm1_mma(const BF* __restrict__ Ahi, const BF* __restrict__ Alo,
                                                 const BF* __restrict__ Bhi, const BF* __restrict__ Blo,
                                                 const float* __restrict__ bias, float* __restrict__ H)
{
    extern __shared__ char smem[];
    float acc[2][8][4];
    #pragma unroll
    for (int t = 0; t < 2; t++)
        #pragma unroll
        for (int j = 0; j < 8; j++)
            #pragma unroll
            for (int v = 0; v < 4; v++) acc[t][j][v] = 0.f;

    long m0 = (long)blockIdx.y * 128, n0 = (long)blockIdx.x * 128;
    mma_mainloop(acc, Ahi, Alo, Bhi, Blo, m0, n0, KPAD1, KPAD1 / 32, smem_u32(smem));

    const int tid = threadIdx.x, lane = tid & 31, wid = tid >> 5;
    const int wm = wid & 3, wn = wid >> 2;
    const int rr = lane >> 2, q = lane & 3;
    #pragma unroll
    for (int t = 0; t < 2; t++) {
        long m = m0 + wm * 32 + t * 16 + rr;
        #pragma unroll
        for (int j = 0; j < 8; j++) {
            int n = (int)n0 + wn * 64 + j * 8 + 2 * q;
            if (n < Hn) {
                H[m * Hn + n]       = tanhf(acc[t][j][0] + bias[n]);
                H[(m + 8) * Hn + n] = tanhf(acc[t][j][2] + bias[n]);
            }
            if (n + 1 < Hn) {
                H[m * Hn + n + 1]       = tanhf(acc[t][j][1] + bias[n + 1]);
                H[(m + 8) * Hn + n + 1] = tanhf(acc[t][j][3] + bias[n + 1]);
            }
        }
    }
}

// ---------------- sim: new_output = log(mean_k exp(zn @ itn^T / tau) + 1) ----------------
__global__ void __launch_bounds__(256) sim_mma(const BF* __restrict__ Ahi, const BF* __restrict__ Alo,
                                               const BF* __restrict__ Bhi, const BF* __restrict__ Blo,
                                               float* __restrict__ no_out)
{
    extern __shared__ char smem[];
    float acc[2][8][4];
    #pragma unroll
    for (int t = 0; t < 2; t++)
        #pragma unroll
        for (int j = 0; j < 8; j++)
            #pragma unroll
            for (int v = 0; v < 4; v++) acc[t][j][v] = 0.f;

    long m0 = (long)blockIdx.y * 128, n0 = (long)blockIdx.x * 128;
    mma_mainloop(acc, Ahi, Alo, Bhi, Blo, m0, n0, KPAD2, KPAD2 / 32, smem_u32(smem));

    const int tid = threadIdx.x, lane = tid & 31, wid = tid >> 5;
    const int wm = wid & 3, wn = wid >> 2;
    const int q = lane & 3;
    long b = blockIdx.y * 4 + wm;     // user; warp's 32 m-rows = this user's K rows
    #pragma unroll
    for (int j = 0; j < 8; j++) {
        float s0 = __expf(10.0f * acc[0][j][0]) + __expf(10.0f * acc[0][j][2])
                 + __expf(10.0f * acc[1][j][0]) + __expf(10.0f * acc[1][j][2]);
        float s1 = __expf(10.0f * acc[0][j][1]) + __expf(10.0f * acc[0][j][3])
                 + __expf(10.0f * acc[1][j][1]) + __expf(10.0f * acc[1][j][3]);
        #pragma unroll
        for (int off = 4; off < 32; off <<= 1) {
            s0 += __shfl_xor_sync(0xffffffffu, s0, off);
            s1 += __shfl_xor_sync(0xffffffffu, s1, off);
        }
        if (lane < 4) {
            int n = (int)n0 + wn * 64 + j * 8 + 2 * q;
            if (n < In)     no_out[b * In + n]     = logf(s0 * (1.0f / 32.0f) + 1.0f);
            if (n + 1 < In) no_out[b * In + n + 1] = logf(s1 * (1.0f / 32.0f) + 1.0f);
        }
    }
}

// ---------------- items l2-normalize -> bf16 hi/lo, padded [NPAD2][KPAD2] ----------------
__global__ void items_norm_kernel(const float* __restrict__ items, BF* __restrict__ hi, BF* __restrict__ lo)
{
    int warp = (blockIdx.x * blockDim.x + threadIdx.x) >> 5;
    int lane = threadIdx.x & 31;
    if (warp >= NPAD2) return;
    BF* dh = hi + (size_t)warp * KPAD2;
    BF* dl = lo + (size_t)warp * KPAD2;
    if (warp >= In) {
        for (int j = lane; j < KPAD2; j += 32) { dh[j] = __float2bfloat16(0.f); dl[j] = __float2bfloat16(0.f); }
        return;
    }
    const float* src = items + (long)warp * LATn;
    float v[7];
    float ss = 0.f;
    int cnt = 0;
    for (int j = lane; j < LATn; j += 32) { float t = src[j]; v[cnt++] = t; ss += t * t; }
    #pragma unroll
    for (int o = 16; o; o >>= 1) ss += __shfl_xor_sync(0xffffffffu, ss, o);
    float inv = 1.0f / fmaxf(sqrtf(ss), 1e-12f);
    cnt = 0;
    for (int j = lane; j < KPAD2; j += 32) {
        float t = (j < LATn) ? v[cnt++] * inv : 0.f;
        BF h = __float2bfloat16(t);
        dh[j] = h;
        dl[j] = __float2bfloat16(t - __bfloat162float(h));
    }
}

// ---------------- W1 [In,Hn] f32 -> W1^T hi/lo bf16 [NPAD1][KPAD1] ----------------
__global__ void convW1_kernel(const float* __restrict__ W1, BF* __restrict__ hi, BF* __restrict__ lo)
{
    __shared__ float t[32][33];
    int kb = blockIdx.x * 32, nb = blockIdx.y * 32;
    int tx = threadIdx.x, ty = threadIdx.y;   // (32, 8)
    for (int j = ty; j < 32; j += 8) {
        int k = kb + j, n = nb + tx;
        t[j][tx] = (k < In && n < Hn) ? W1[(long)k * Hn + n] : 0.f;
    }
    __syncthreads();
    for (int j = ty; j < 32; j += 8) {
        int n = nb + j, k = kb + tx;
        if (n < NPAD1 && k < KPAD1) {
            float v = t[tx][j];
            BF h = __float2bfloat16(v);
            hi[(size_t)n * KPAD1 + k] = h;
            lo[(size_t)n * KPAD1 + k] = __float2bfloat16(v - __bfloat162float(h));
        }
    }
}

// ---------------- x = masked gram row / l2norm ----------------
__global__ void x_kernel(const float* __restrict__ rating, const int* __restrict__ items_idx,
                         const float* __restrict__ gram, float* __restrict__ x_out,
                         BF* __restrict__ xhi, BF* __restrict__ xlo)
{
    int bk  = blockIdx.x;
    int b   = bk >> 5;
    int row = items_idx[bk];
    const float* r = rating + (long)b * In;
    const float* g = gram   + (long)row * In;
    float ss = 0.f;
    for (int i = threadIdx.x; i < In; i += blockDim.x) {
        if (r[i] > 0.f) { float v = g[i]; ss += v * v; }
    }
    __shared__ float red[8];
    #pragma unroll
    for (int o = 16; o; o >>= 1) ss += __shfl_xor_sync(0xffffffffu, ss, o);
    if ((threadIdx.x & 31) == 0) red[threadIdx.x >> 5] = ss;
    __syncthreads();
    if (threadIdx.x < 8) {
        float t = red[threadIdx.x];
        #pragma unroll
        for (int o = 4; o; o >>= 1) t += __shfl_xor_sync(0xffu, t, o);
        if (threadIdx.x == 0) red[0] = t;
    }
    __syncthreads();
    float inv = 1.0f / fmaxf(sqrtf(red[0]), 1e-12f);
    float* dst = x_out + (long)bk * In;
    BF* dh = xhi + (size_t)bk * KPAD1;
    BF* dl = xlo + (size_t)bk * KPAD1;
    for (int i = threadIdx.x; i < KPAD1; i += blockDim.x) {
        float v = 0.f;
        if (i < In) {
            v = (r[i] > 0.f) ? g[i] * inv : 0.f;
            dst[i] = v;
        }
        BF h = __float2bfloat16(v);
        dh[i] = h;
        dl[i] = __float2bfloat16(v - __bfloat162float(h));
    }
}

// ---------------- SIMT GEMM for GEMM2 (small) ----------------
template<int DO_TANH>
__global__ void __launch_bounds__(256) gemm_bias(const float* __restrict__ A,
                                                 const float* __restrict__ Bw,
                                                 const float* __restrict__ bias,
                                                 float* __restrict__ C,
                                                 int M, int N, int Kd)
{
    __shared__ float sA[16][129];
    __shared__ float sB[16][129];
    const int tid = threadIdx.x;
    const int tx = tid & 15, ty = tid >> 4;
    const int m0 = blockIdx.y * 128, n0 = blockIdx.x * 128;

    float acc[8][8];
    #pragma unroll
    for (int r = 0; r < 8; r++)
        #pragma unroll
        for (int c = 0; c < 8; c++) acc[r][c] = 0.f;

    const int aCol = tid & 15;
    const int aRow = tid >> 4;
    float ra[8], rb[8];
    const int nk = (Kd + 15) >> 4;

    {
        #pragma unroll
        for (int j = 0; j < 8; j++) {
            int k = aCol;
            ra[j] = (k < Kd) ? A[(long)(m0 + aRow + 16 * j) * Kd + k] : 0.f;
        }
        #pragma unroll
        for (int j = 0; j < 8; j++) {
            int idx = tid + 256 * j;
            int brow = idx >> 7, bcol = idx & 127;
            rb[j] = (brow < Kd && n0 + bcol < N) ? Bw[(long)brow * N + n0 + bcol] : 0.f;
        }
    }
    #pragma unroll
    for (int j = 0; j < 8; j++) sA[aCol][aRow + 16 * j] = ra[j];
    #pragma unroll
    for (int j = 0; j < 8; j++) {
        int idx = tid + 256 * j;
        sB[idx >> 7][idx & 127] = rb[j];
    }
    __syncthreads();

    for (int kt = 0; ; kt++) {
        if (kt + 1 < nk) {
            int k0 = (kt + 1) * 16;
            #pragma unroll
            for (int j = 0; j < 8; j++) {
                int k = k0 + aCol;
                ra[j] = (k < Kd) ? A[(long)(m0 + aRow + 16 * j) * Kd + k] : 0.f;
            }
            #pragma unroll
            for (int j = 0; j < 8; j++) {
                int idx = tid + 256 * j;
                int brow = idx >> 7, bcol = idx & 127;
                int k = k0 + brow, n = n0 + bcol;
                rb[j] = (k < Kd && n < N) ? Bw[(long)k * N + n] : 0.f;
            }
        }
        #pragma unroll
        for (int k = 0; k < 16; k++) {
            float af[8], bf[8];
            #pragma unroll
            for (int r = 0; r < 8; r++) af[r] = sA[k][ty + 16 * r];
            #pragma unroll
            for (int c = 0; c < 8; c++) bf[c] = sB[k][tx + 16 * c];
            #pragma unroll
            for (int r = 0; r < 8; r++)
                #pragma unroll
                for (int c = 0; c < 8; c++) acc[r][c] += af[r] * bf[c];
        }
        if (kt + 1 == nk) break;
        __syncthreads();
        #pragma unroll
        for (int j = 0; j < 8; j++) sA[aCol][aRow + 16 * j] = ra[j];
        #pragma unroll
        for (int j = 0; j < 8; j++) {
            int idx = tid + 256 * j;
            sB[idx >> 7][idx & 127] = rb[j];
        }
        __syncthreads();
    }

    #pragma unroll
    for (int r = 0; r < 8; r++) {
        int m = m0 + ty + 16 * r;
        #pragma unroll
        for (int c = 0; c < 8; c++) {
            int n = n0 + tx + 16 * c;
            if (n < N) {
                float v = acc[r][c] + bias[n];
                if (DO_TANH) v = tanhf(v);
                C[(long)m * N + n] = v;
            }
        }
    }
}

// ---------------- enc postprocess: z, zn(hi/lo), kl ----------------
__global__ void postenc_kernel(const float* __restrict__ enc, float* __restrict__ z_out,
                               BF* __restrict__ znhi, BF* __restrict__ znlo, double* __restrict__ kl_acc)
{
    int warp = (blockIdx.x * blockDim.x + threadIdx.x) >> 5;
    int lane = threadIdx.x & 31;
    if (warp >= ROWS) return;
    const float* e = enc + (long)warp * ENCn;
    float mv[7];
    float ss = 0.f, klp = 0.f;
    int cnt = 0;
    for (int j = lane; j < LATn; j += 32) {
        float m  = e[j];
        float lv = e[j + LATn];
        mv[cnt++] = m;
        ss  += m * m;
        klp += m * m + (expm1f(lv) - lv);
    }
    #pragma unroll
    for (int o = 16; o; o >>= 1) {
        ss  += __shfl_xor_sync(0xffffffffu, ss, o);
        klp += __shfl_xor_sync(0xffffffffu, klp, o);
    }
    float inv = 1.0f / fmaxf(sqrtf(ss), 1e-12f);
    cnt = 0;
    for (int j = lane; j < KPAD2; j += 32) {
        float t = 0.f;
        if (j < LATn) {
            z_out[(long)warp * LATn + j] = mv[cnt];
            t = mv[cnt++] * inv;
        }
        BF h = __float2bfloat16(t);
        znhi[(size_t)warp * KPAD2 + j] = h;
        znlo[(size_t)warp * KPAD2 + j] = __float2bfloat16(t - __bfloat162float(h));
    }
    if (lane == 0) atomicAdd(kl_acc, (double)klp);
}

__global__ void zero_kl_kernel(double* p) { *p = 0.0; }
__global__ void fin_kl_kernel(const double* p, float* out) { *out = (float)(0.5 * (*p) / (double)ROWS); }

// ---------------- launch ----------------
extern "C" void kernel_launch(void* const* d_in, const int* in_sizes, int n_in,
                              void* d_out, int out_size)
{
    const float* rating    = (const float*)d_in[0];
    const int*   items_idx = (const int*)  d_in[1];
    const float* gram      = (const float*)d_in[2];
    const float* W1        = (const float*)d_in[3];
    const float* b1        = (const float*)d_in[4];
    const float* W2        = (const float*)d_in[5];
    const float* b2        = (const float*)d_in[6];
    const float* items     = (const float*)d_in[7];

    float* out    = (float*)d_out;
    float* z_out  = out + Z_OFF;
    float* no_out = out + NO_OFF;
    float* kl_out = out + KL_OFF;
    float* x_out  = out + X_OFF;

    float *h, *enc; double* klp;
    BF *xhi, *xlo, *w1hi, *w1lo, *znhi, *znlo, *ithi, *itlo;
    cudaGetSymbolAddress((void**)&h,    g_h);
    cudaGetSymbolAddress((void**)&enc,  g_enc);
    cudaGetSymbolAddress((void**)&klp,  g_kl);
    cudaGetSymbolAddress((void**)&xhi,  g_xhi);
    cudaGetSymbolAddress((void**)&xlo,  g_xlo);
    cudaGetSymbolAddress((void**)&w1hi, g_w1hi);
    cudaGetSymbolAddress((void**)&w1lo, g_w1lo);
    cudaGetSymbolAddress((void**)&znhi, g_znhi);
    cudaGetSymbolAddress((void**)&znlo, g_znlo);
    cudaGetSymbolAddress((void**)&ithi, g_ithi);
    cudaGetSymbolAddress((void**)&itlo, g_itlo);

    cudaFuncSetAttribute(gemm1_mma, cudaFuncAttributeMaxDynamicSharedMemorySize, SMEM_SZ);
    cudaFuncSetAttribute(sim_mma,   cudaFuncAttributeMaxDynamicSharedMemorySize, SMEM_SZ);

    items_norm_kernel<<<(NPAD2 * 32 + 255) / 256, 256>>>(items, ithi, itlo);
    convW1_kernel<<<dim3(KPAD1 / 32, NPAD1 / 32), dim3(32, 8)>>>(W1, w1hi, w1lo);
    x_kernel<<<ROWS, 256>>>(rating, items_idx, gram, x_out, xhi, xlo);
    zero_kl_kernel<<<1, 1>>>(klp);
    // h = tanh(x @ W1 + b1): split-bf16 HMMA
    gemm1_mma<<<dim3(NPAD1 / 128, ROWS / 128), 256, SMEM_SZ>>>(xhi, xlo, w1hi, w1lo, b1, h);
    // enc = h @ W2 + b2 (small, SIMT)
    gemm_bias<0><<<dim3((ENCn + 127) / 128, ROWS / 128), 256>>>(h, W2, b2, enc, ROWS, ENCn, Hn);
    postenc_kernel<<<(ROWS * 32 + 255) / 256, 256>>>(enc, z_out, znhi, znlo, klp);
    fin_kl_kernel<<<1, 1>>>(klp, kl_out);
    // new_output: split-bf16 HMMA with fused exp/mean/log epilogue
    sim_mma<<<dim3(NPAD2 / 128, ROWS / 128), 256, SMEM_SZ>>>(znhi, znlo, ithi, itlo, no_out);
}

// round 7
// speedup vs baseline: 2.5723x; 1.1543x over previous
#include <cuda_runtime.h>
#include <cuda_bf16.h>
#include <math.h>
#include <stdint.h>

#define Bn   128
#define Kn   32
#define In   12000
#define Hn   600
#define LATn 200
#define ROWS (Bn*Kn)      // 4096
#define ENCn (2*LATn)     // 400

#define KPAD1 12032       // In padded to 64
#define NPAD1 640         // Hn padded to 128
#define KPAD2 256         // LATn padded to 64
#define NPAD2 12032       // In padded to 128
#define HPADK 608         // Hn padded to 32  (K of gemm2)
#define NPADW 512         // ENCn padded to 128 (N of gemm2)

#define Z_OFF  0
#define NO_OFF (ROWS*LATn)                 // 819200
#define KL_OFF (NO_OFF + Bn*In)            // 2355200
#define X_OFF  (KL_OFF + 1)                // 2355201

typedef __nv_bfloat16 BF;

// ---------------- scratch (no allocation allowed) ----------------
__device__ float  g_enc[ROWS*ENCn];
__device__ double g_kl;
__device__ BF g_xhi[(size_t)ROWS*KPAD1];
__device__ BF g_xlo[(size_t)ROWS*KPAD1];
__device__ BF g_w1hi[(size_t)NPAD1*KPAD1];
__device__ BF g_w1lo[(size_t)NPAD1*KPAD1];
__device__ BF g_hhi[(size_t)ROWS*HPADK];
__device__ BF g_hlo[(size_t)ROWS*HPADK];
__device__ BF g_w2hi[(size_t)NPADW*HPADK];
__device__ BF g_w2lo[(size_t)NPADW*HPADK];
__device__ BF g_znhi[(size_t)ROWS*KPAD2];
__device__ BF g_znlo[(size_t)ROWS*KPAD2];
__device__ BF g_ithi[(size_t)NPAD2*KPAD2];
__device__ BF g_itlo[(size_t)NPAD2*KPAD2];

// ==================== helpers ====================
__device__ __forceinline__ uint32_t smem_u32(const void* p) {
    uint32_t a;
    asm("{ .reg .u64 t; cvta.to.shared.u64 t, %1; cvt.u32.u64 %0, t; }" : "=r"(a) : "l"(p));
    return a;
}
#define CP16(dst, src) asm volatile("cp.async.cg.shared.global [%0], [%1], 16;" :: "r"(dst), "l"(src) : "memory")
#define CP_COMMIT()    asm volatile("cp.async.commit_group;" ::: "memory")
#define CP_WAIT1()     asm volatile("cp.async.wait_group 1;" ::: "memory")
#define CP_WAIT0()     asm volatile("cp.async.wait_group 0;" ::: "memory")

__device__ __forceinline__ void ldsm4(uint32_t r[4], uint32_t addr) {
    asm volatile("ldmatrix.sync.aligned.m8n8.x4.shared.b16 {%0,%1,%2,%3}, [%4];"
        : "=r"(r[0]), "=r"(r[1]), "=r"(r[2]), "=r"(r[3]) : "r"(addr));
}
__device__ __forceinline__ void mma16816(float d[4], const uint32_t a[4], uint32_t b0, uint32_t b1) {
    asm volatile("mma.sync.aligned.m16n8k16.row.col.f32.bf16.bf16.f32 "
        "{%0,%1,%2,%3}, {%4,%5,%6,%7}, {%8,%9}, {%0,%1,%2,%3};"
        : "+f"(d[0]), "+f"(d[1]), "+f"(d[2]), "+f"(d[3])
        : "r"(a[0]), "r"(a[1]), "r"(a[2]), "r"(a[3]), "r"(b0), "r"(b1));
}

// smem stage layout: Ahi[128*80] Alo Bhi Blo, stage stride 40960, 3 stages.
#define ROWB80   80
#define OFF_ALO  10240
#define OFF_BHI  20480
#define OFF_BLO  30720
#define STAGE_B  40960
#define NSTAGE   3
#define SMEM_SZ  (NSTAGE*STAGE_B)

// ---------------- split-bf16 mma mainloop: acc += Ah*Bh + Ah*Bl + Al*Bh ----------------
// A [.][kpad] rows m0..m0+127, B [.][kpad] rows n0..n0+127, both K-major bf16.
// 3-stage pipeline, one __syncthreads per chunk.
__device__ __forceinline__ void mma_mainloop(float acc[2][8][4],
    const BF* __restrict__ Ahi, const BF* __restrict__ Alo,
    const BF* __restrict__ Bhi, const BF* __restrict__ Blo,
    long m0, long n0, int kpad, int nch, uint32_t smem_base)
{
    const int tid  = threadIdx.x;
    const int lane = tid & 31, wid = tid >> 5;
    const int wm = wid & 3, wn = wid >> 2;
    const int r0  = tid >> 2;           // 0..63
    const int c16 = (tid & 3) * 16;     // byte col in 64B chunk row
    const long rowb = (long)kpad * 2;

    const char* pAh = (const char*)(Ahi + (m0 + r0) * (long)kpad) + c16;
    const char* pAl = (const char*)(Alo + (m0 + r0) * (long)kpad) + c16;
    const char* pBh = (const char*)(Bhi + (n0 + r0) * (long)kpad) + c16;
    const char* pBl = (const char*)(Blo + (n0 + r0) * (long)kpad) + c16;
    const uint32_t dlo = r0 * ROWB80 + c16;
    const uint32_t dhi = (r0 + 64) * ROWB80 + c16;
    const long rskip = 64 * rowb;

    // prologue: issue chunks 0 and 1
    #pragma unroll
    for (int c = 0; c < 2; c++) {
        if (c < nch) {
            uint32_t st = smem_base + c * STAGE_B;
            long go = (long)c * 64;
            CP16(st + dlo,           pAh + go);   CP16(st + dhi,           pAh + rskip + go);
            CP16(st + OFF_ALO + dlo, pAl + go);   CP16(st + OFF_ALO + dhi, pAl + rskip + go);
            CP16(st + OFF_BHI + dlo, pBh + go);   CP16(st + OFF_BHI + dhi, pBh + rskip + go);
            CP16(st + OFF_BLO + dlo, pBl + go);   CP16(st + OFF_BLO + dhi, pBl + rskip + go);
            CP_COMMIT();
        }
    }

    for (int c = 0; c < nch; c++) {
        if (c + 1 < nch) CP_WAIT1(); else CP_WAIT0();
        __syncthreads();

        uint32_t sA = smem_base + (c % NSTAGE) * STAGE_B;
        uint32_t sB = sA + OFF_BHI;
        #pragma unroll
        for (int s = 0; s < 2; s++) {
            uint32_t ah[2][4], al[2][4];
            #pragma unroll
            for (int t = 0; t < 2; t++) {
                uint32_t row = wm * 32 + t * 16 + (lane & 15);
                uint32_t ad = sA + row * ROWB80 + s * 32 + ((lane >> 4) & 1) * 16;
                ldsm4(ah[t], ad);
                ldsm4(al[t], ad + OFF_ALO);
            }
            uint32_t bh[4][4], bl[4][4];
            #pragma unroll
            for (int p = 0; p < 4; p++) {
                uint32_t row = wn * 64 + p * 16 + (lane & 7) + ((lane & 16) ? 8 : 0);
                uint32_t ad = sB + row * ROWB80 + s * 32 + ((lane & 8) ? 16 : 0);
                ldsm4(bh[p], ad);
                ldsm4(bl[p], ad + OFF_ALO);   // Blo is +10240 after Bhi
            }
            #pragma unroll
            for (int t = 0; t < 2; t++)
                #pragma unroll
                for (int p = 0; p < 4; p++)
                    #pragma unroll
                    for (int hh = 0; hh < 2; hh++) {
                        int j = p * 2 + hh;
                        mma16816(acc[t][j], ah[t], bh[p][hh * 2], bh[p][hh * 2 + 1]);
                        mma16816(acc[t][j], ah[t], bl[p][hh * 2], bl[p][hh * 2 + 1]);
                        mma16816(acc[t][j], al[t], bh[p][hh * 2], bh[p][hh * 2 + 1]);
                    }
        }
        if (c + 2 < nch) {
            uint32_t st = smem_base + ((c + 2) % NSTAGE) * STAGE_B;
            long go = (long)(c + 2) * 64;
            CP16(st + dlo,           pAh + go);   CP16(st + dhi,           pAh + rskip + go);
            CP16(st + OFF_ALO + dlo, pAl + go);   CP16(st + OFF_ALO + dhi, pAl + rskip + go);
            CP16(st + OFF_BHI + dlo, pBh + go);   CP16(st + OFF_BHI + dhi, pBh + rskip + go);
            CP16(st + OFF_BLO + dlo, pBl + go);   CP16(st + OFF_BLO + dhi, pBl + rskip + go);
            CP_COMMIT();
        }
    }
}

// ---------------- GEMM1: h = tanh(x @ W1 + b1), output bf16 hi/lo [4096][608] ----------------
__global__ void __launch_bounds__(256) gemm1_mma(const BF* __restrict__ Ahi, const BF* __restrict__ Alo,
                                                 const BF* __restrict__ Bhi, const BF* __restrict__ Blo,
                                                 const float* __restrict__ bias,
                                                 BF* __restrict__ Hhi, BF* __restrict__ Hlo)
{
    extern __shared__ char smem[];
    float acc[2][8][4];
    #pragma unroll
    for (int t = 0; t < 2; t++)
        #pragma unroll
        for (int j = 0; j < 8; j++)
            #pragma unroll
            for (int v = 0; v < 4; v++) acc[t][j][v] = 0.f;

    long m0 = (long)blockIdx.y * 128, n0 = (long)blockIdx.x * 128;
    mma_mainloop(acc, Ahi, Alo, Bhi, Blo, m0, n0, KPAD1, KPAD1 / 32, smem_u32(smem));

    const int tid = threadIdx.x, lane = tid & 31, wid = tid >> 5;
    const int wm = wid & 3, wn = wid >> 2;
    const int rr = lane >> 2, q = lane & 3;
    #pragma unroll
    for (int t = 0; t < 2; t++) {
        long m = m0 + wm * 32 + t * 16 + rr;
        #pragma unroll
        for (int j = 0; j < 8; j++) {
            int n = (int)n0 + wn * 64 + j * 8 + 2 * q;
            #pragma unroll
            for (int e = 0; e < 2; e++) {
                int nn = n + e;
                if (nn < HPADK) {
                    float v0 = (nn < Hn) ? tanhf(acc[t][j][e]     + bias[nn]) : 0.f;
                    float v1 = (nn < Hn) ? tanhf(acc[t][j][e + 2] + bias[nn]) : 0.f;
                    BF h0 = __float2bfloat16(v0), h1 = __float2bfloat16(v1);
                    Hhi[m * HPADK + nn]       = h0;
                    Hlo[m * HPADK + nn]       = __float2bfloat16(v0 - __bfloat162float(h0));
                    Hhi[(m + 8) * HPADK + nn] = h1;
                    Hlo[(m + 8) * HPADK + nn] = __float2bfloat16(v1 - __bfloat162float(h1));
                }
            }
        }
    }
}

// ---------------- GEMM2: enc = h @ W2 + b2 (fp32 out) ----------------
__global__ void __launch_bounds__(256) gemm2_mma(const BF* __restrict__ Ahi, const BF* __restrict__ Alo,
                                                 const BF* __restrict__ Bhi, const BF* __restrict__ Blo,
                                                 const float* __restrict__ bias, float* __restrict__ E)
{
    extern __shared__ char smem[];
    float acc[2][8][4];
    #pragma unroll
    for (int t = 0; t < 2; t++)
        #pragma unroll
        for (int j = 0; j < 8; j++)
            #pragma unroll
            for (int v = 0; v < 4; v++) acc[t][j][v] = 0.f;

    long m0 = (long)blockIdx.y * 128, n0 = (long)blockIdx.x * 128;
    mma_mainloop(acc, Ahi, Alo, Bhi, Blo, m0, n0, HPADK, HPADK / 32, smem_u32(smem));

    const int tid = threadIdx.x, lane = tid & 31, wid = tid >> 5;
    const int wm = wid & 3, wn = wid >> 2;
    const int rr = lane >> 2, q = lane & 3;
    #pragma unroll
    for (int t = 0; t < 2; t++) {
        long m = m0 + wm * 32 + t * 16 + rr;
        #pragma unroll
        for (int j = 0; j < 8; j++) {
            int n = (int)n0 + wn * 64 + j * 8 + 2 * q;
            #pragma unroll
            for (int e = 0; e < 2; e++) {
                int nn = n + e;
                if (nn < ENCn) {
                    E[m * ENCn + nn]       = acc[t][j][e]     + bias[nn];
                    E[(m + 8) * ENCn + nn] = acc[t][j][e + 2] + bias[nn];
                }
            }
        }
    }
}

// ---------------- sim: new_output = log(mean_k exp(zn @ itn^T / tau) + 1) ----------------
__global__ void __launch_bounds__(256) sim_mma(const BF* __restrict__ Ahi, const BF* __restrict__ Alo,
                                               const BF* __restrict__ Bhi, const BF* __restrict__ Blo,
                                               float* __restrict__ no_out)
{
    extern __shared__ char smem[];
    float acc[2][8][4];
    #pragma unroll
    for (int t = 0; t < 2; t++)
        #pragma unroll
        for (int j = 0; j < 8; j++)
            #pragma unroll
            for (int v = 0; v < 4; v++) acc[t][j][v] = 0.f;

    long m0 = (long)blockIdx.y * 128, n0 = (long)blockIdx.x * 128;
    mma_mainloop(acc, Ahi, Alo, Bhi, Blo, m0, n0, KPAD2, KPAD2 / 32, smem_u32(smem));

    const int tid = threadIdx.x, lane = tid & 31, wid = tid >> 5;
    const int wm = wid & 3, wn = wid >> 2;
    const int q = lane & 3;
    long b = blockIdx.y * 4 + wm;     // user; warp's 32 m-rows = this user's 32 K rows
    #pragma unroll
    for (int j = 0; j < 8; j++) {
        float s0 = __expf(10.0f * acc[0][j][0]) + __expf(10.0f * acc[0][j][2])
                 + __expf(10.0f * acc[1][j][0]) + __expf(10.0f * acc[1][j][2]);
        float s1 = __expf(10.0f * acc[0][j][1]) + __expf(10.0f * acc[0][j][3])
                 + __expf(10.0f * acc[1][j][1]) + __expf(10.0f * acc[1][j][3]);
        #pragma unroll
        for (int off = 4; off < 32; off <<= 1) {
            s0 += __shfl_xor_sync(0xffffffffu, s0, off);
            s1 += __shfl_xor_sync(0xffffffffu, s1, off);
        }
        if (lane < 4) {
            int n = (int)n0 + wn * 64 + j * 8 + 2 * q;
            if (n < In)     no_out[b * In + n]     = logf(s0 * (1.0f / 32.0f) + 1.0f);
            if (n + 1 < In) no_out[b * In + n + 1] = logf(s1 * (1.0f / 32.0f) + 1.0f);
        }
    }
}

// ---------------- items l2-normalize -> bf16 hi/lo, padded [NPAD2][KPAD2] ----------------
__global__ void items_norm_kernel(const float* __restrict__ items, BF* __restrict__ hi, BF* __restrict__ lo)
{
    int warp = (blockIdx.x * blockDim.x + threadIdx.x) >> 5;
    int lane = threadIdx.x & 31;
    if (warp >= NPAD2) return;
    BF* dh = hi + (size_t)warp * KPAD2;
    BF* dl = lo + (size_t)warp * KPAD2;
    if (warp >= In) {
        for (int j = lane; j < KPAD2; j += 32) { dh[j] = __float2bfloat16(0.f); dl[j] = __float2bfloat16(0.f); }
        return;
    }
    const float* src = items + (long)warp * LATn;
    float v[7];
    float ss = 0.f;
    int cnt = 0;
    for (int j = lane; j < LATn; j += 32) { float t = src[j]; v[cnt++] = t; ss += t * t; }
    #pragma unroll
    for (int o = 16; o; o >>= 1) ss += __shfl_xor_sync(0xffffffffu, ss, o);
    float inv = 1.0f / fmaxf(sqrtf(ss), 1e-12f);
    cnt = 0;
    for (int j = lane; j < KPAD2; j += 32) {
        float t = (j < LATn) ? v[cnt++] * inv : 0.f;
        BF h = __float2bfloat16(t);
        dh[j] = h;
        dl[j] = __float2bfloat16(t - __bfloat162float(h));
    }
}

// ---------------- W1 [In,Hn] f32 -> W1^T hi/lo bf16 [NPAD1][KPAD1] ----------------
__global__ void convW1_kernel(const float* __restrict__ W1, BF* __restrict__ hi, BF* __restrict__ lo)
{
    __shared__ float t[32][33];
    int kb = blockIdx.x * 32, nb = blockIdx.y * 32;
    int tx = threadIdx.x, ty = threadIdx.y;   // (32, 8)
    for (int j = ty; j < 32; j += 8) {
        int k = kb + j, n = nb + tx;
        t[j][tx] = (k < In && n < Hn) ? W1[(long)k * Hn + n] : 0.f;
    }
    __syncthreads();
    for (int j = ty; j < 32; j += 8) {
        int n = nb + j, k = kb + tx;
        if (n < NPAD1 && k < KPAD1) {
            float v = t[tx][j];
            BF h = __float2bfloat16(v);
            hi[(size_t)n * KPAD1 + k] = h;
            lo[(size_t)n * KPAD1 + k] = __float2bfloat16(v - __bfloat162float(h));
        }
    }
}

// ---------------- W2 [Hn,ENCn] f32 -> W2^T hi/lo bf16 [NPADW][HPADK] ----------------
__global__ void convW2_kernel(const float* __restrict__ W2, BF* __restrict__ hi, BF* __restrict__ lo)
{
    __shared__ float t[32][33];
    int kb = blockIdx.x * 32, nb = blockIdx.y * 32;
    int tx = threadIdx.x, ty = threadIdx.y;   // (32, 8)
    for (int j = ty; j < 32; j += 8) {
        int k = kb + j, n = nb + tx;
        t[j][tx] = (k < Hn && n < ENCn) ? W2[(long)k * ENCn + n] : 0.f;
    }
    __syncthreads();
    for (int j = ty; j < 32; j += 8) {
        int n = nb + j, k = kb + tx;
        if (n < NPADW && k < HPADK) {
            float v = t[tx][j];
            BF h = __float2bfloat16(v);
            hi[(size_t)n * HPADK + k] = h;
            lo[(size_t)n * HPADK + k] = __float2bfloat16(v - __bfloat162float(h));
        }
    }
}

// ---------------- x = masked gram row / l2norm : single gram read via smem ----------------
__global__ void __launch_bounds__(512) x_kernel(const float* __restrict__ rating, const int* __restrict__ items_idx,
                                                const float* __restrict__ gram, float* __restrict__ x_out,
                                                BF* __restrict__ xhi, BF* __restrict__ xlo)
{
    __shared__ float sg[In];      // 48000 B
    __shared__ float red[16];
    const int tid = threadIdx.x;
    int bk  = blockIdx.x;
    int b   = bk >> 5;
    int row = items_idx[bk];
    const float4* r4 = (const float4*)(rating + (long)b * In);
    const float4* g4 = (const float4*)(gram + (long)row * In);
    float ss = 0.f;
    for (int i = tid; i < In / 4; i += 512) {
        float4 rv = r4[i];
        float4 gv = g4[i];
        float4 m;
        m.x = (rv.x > 0.f) ? gv.x : 0.f;
        m.y = (rv.y > 0.f) ? gv.y : 0.f;
        m.z = (rv.z > 0.f) ? gv.z : 0.f;
        m.w = (rv.w > 0.f) ? gv.w : 0.f;
        ss += m.x * m.x + m.y * m.y + m.z * m.z + m.w * m.w;
        *(float4*)&sg[i * 4] = m;
    }
    #pragma unroll
    for (int o = 16; o; o >>= 1) ss += __shfl_xor_sync(0xffffffffu, ss, o);
    if ((tid & 31) == 0) red[tid >> 5] = ss;
    __syncthreads();
    if (tid < 16) {
        float t = red[tid];
        #pragma unroll
        for (int o = 8; o; o >>= 1) t += __shfl_xor_sync(0xffffu, t, o);
        if (tid == 0) red[0] = t;
    }
    __syncthreads();
    float inv = 1.0f / fmaxf(sqrtf(red[0]), 1e-12f);
    float* dst = x_out + (long)bk * In;        // 4B-aligned only (odd base offset)
    for (int i = tid; i < In; i += 512) dst[i] = sg[i] * inv;
    uint32_t* dh = (uint32_t*)(xhi + (size_t)bk * KPAD1);
    uint32_t* dl = (uint32_t*)(xlo + (size_t)bk * KPAD1);
    for (int i = tid; i < KPAD1 / 2; i += 512) {
        int i0 = 2 * i;
        float v0 = (i0     < In) ? sg[i0]     * inv : 0.f;
        float v1 = (i0 + 1 < In) ? sg[i0 + 1] * inv : 0.f;
        BF h0 = __float2bfloat16(v0), h1 = __float2bfloat16(v1);
        __nv_bfloat162 hp; hp.x = h0; hp.y = h1;
        __nv_bfloat162 lp;
        lp.x = __float2bfloat16(v0 - __bfloat162float(h0));
        lp.y = __float2bfloat16(v1 - __bfloat162float(h1));
        dh[i] = *(uint32_t*)&hp;
        dl[i] = *(uint32_t*)&lp;
    }
}

// ---------------- enc postprocess: z, zn(hi/lo), kl ----------------
__global__ void postenc_kernel(const float* __restrict__ enc, float* __restrict__ z_out,
                               BF* __restrict__ znhi, BF* __restrict__ znlo, double* __restrict__ kl_acc)
{
    int warp = (blockIdx.x * blockDim.x + threadIdx.x) >> 5;
    int lane = threadIdx.x & 31;
    if (warp >= ROWS) return;
    const float* e = enc + (long)warp * ENCn;
    float mv[7];
    float ss = 0.f, klp = 0.f;
    int cnt = 0;
    for (int j = lane; j < LATn; j += 32) {
        float m  = e[j];
        float lv = e[j + LATn];
        mv[cnt++] = m;
        ss  += m * m;
        klp += m * m + (expm1f(lv) - lv);
    }
    #pragma unroll
    for (int o = 16; o; o >>= 1) {
        ss  += __shfl_xor_sync(0xffffffffu, ss, o);
        klp += __shfl_xor_sync(0xffffffffu, klp, o);
    }
    float inv = 1.0f / fmaxf(sqrtf(ss), 1e-12f);
    cnt = 0;
    for (int j = lane; j < KPAD2; j += 32) {
        float t = 0.f;
        if (j < LATn) {
            z_out[(long)warp * LATn + j] = mv[cnt];
            t = mv[cnt++] * inv;
        }
        BF h = __float2bfloat16(t);
        znhi[(size_t)warp * KPAD2 + j] = h;
        znlo[(size_t)warp * KPAD2 + j] = __float2bfloat16(t - __bfloat162float(h));
    }
    if (lane == 0) atomicAdd(kl_acc, (double)klp);
}

__global__ void zero_kl_kernel(double* p) { *p = 0.0; }
__global__ void fin_kl_kernel(const double* p, float* out) { *out = (float)(0.5 * (*p) / (double)ROWS); }

// ---------------- launch ----------------
extern "C" void kernel_launch(void* const* d_in, const int* in_sizes, int n_in,
                              void* d_out, int out_size)
{
    const float* rating    = (const float*)d_in[0];
    const int*   items_idx = (const int*)  d_in[1];
    const float* gram      = (const float*)d_in[2];
    const float* W1        = (const float*)d_in[3];
    const float* b1        = (const float*)d_in[4];
    const float* W2        = (const float*)d_in[5];
    const float* b2        = (const float*)d_in[6];
    const float* items     = (const float*)d_in[7];

    float* out    = (float*)d_out;
    float* z_out  = out + Z_OFF;
    float* no_out = out + NO_OFF;
    float* kl_out = out + KL_OFF;
    float* x_out  = out + X_OFF;

    float* enc; double* klp;
    BF *xhi, *xlo, *w1hi, *w1lo, *hhi, *hlo, *w2hi, *w2lo, *znhi, *znlo, *ithi, *itlo;
    cudaGetSymbolAddress((void**)&enc,  g_enc);
    cudaGetSymbolAddress((void**)&klp,  g_kl);
    cudaGetSymbolAddress((void**)&xhi,  g_xhi);
    cudaGetSymbolAddress((void**)&xlo,  g_xlo);
    cudaGetSymbolAddress((void**)&w1hi, g_w1hi);
    cudaGetSymbolAddress((void**)&w1lo, g_w1lo);
    cudaGetSymbolAddress((void**)&hhi,  g_hhi);
    cudaGetSymbolAddress((void**)&hlo,  g_hlo);
    cudaGetSymbolAddress((void**)&w2hi, g_w2hi);
    cudaGetSymbolAddress((void**)&w2lo, g_w2lo);
    cudaGetSymbolAddress((void**)&znhi, g_znhi);
    cudaGetSymbolAddress((void**)&znlo, g_znlo);
    cudaGetSymbolAddress((void**)&ithi, g_ithi);
    cudaGetSymbolAddress((void**)&itlo, g_itlo);

    cudaFuncSetAttribute(gemm1_mma, cudaFuncAttributeMaxDynamicSharedMemorySize, SMEM_SZ);
    cudaFuncSetAttribute(gemm2_mma, cudaFuncAttributeMaxDynamicSharedMemorySize, SMEM_SZ);
    cudaFuncSetAttribute(sim_mma,   cudaFuncAttributeMaxDynamicSharedMemorySize, SMEM_SZ);

    zero_kl_kernel<<<1, 1>>>(klp);
    items_norm_kernel<<<(NPAD2 * 32 + 255) / 256, 256>>>(items, ithi, itlo);
    convW1_kernel<<<dim3(KPAD1 / 32, NPAD1 / 32), dim3(32, 8)>>>(W1, w1hi, w1lo);
    convW2_kernel<<<dim3(HPADK / 32, NPADW / 32), dim3(32, 8)>>>(W2, w2hi, w2lo);
    x_kernel<<<ROWS, 512>>>(rating, items_idx, gram, x_out, xhi, xlo);
    // h = tanh(x @ W1 + b1): split-bf16 HMMA, emits h hi/lo directly
    gemm1_mma<<<dim3(NPAD1 / 128, ROWS / 128), 256, SMEM_SZ>>>(xhi, xlo, w1hi, w1lo, b1, hhi, hlo);
    // enc = h @ W2 + b2: split-bf16 HMMA
    gemm2_mma<<<dim3(NPADW / 128, ROWS / 128), 256, SMEM_SZ>>>(hhi, hlo, w2hi, w2lo, b2, enc);
    postenc_kernel<<<(ROWS * 32 + 255) / 256, 256>>>(enc, z_out, znhi, znlo, klp);
    fin_kl_kernel<<<1, 1>>>(klp, kl_out);
    // new_output: split-bf16 HMMA with fused exp/mean/log epilogue
    sim_mma<<<dim3(NPAD2 / 128, ROWS / 128), 256, SMEM_SZ>>>(znhi, znlo, ithi, itlo, no_out);
}

// round 9
// speedup vs baseline: 4.3311x; 1.6838x over previous
#include <cuda_runtime.h>
#include <cuda_bf16.h>
#include <math.h>
#include <stdint.h>

#define Bn   128
#define Kn   32
#define In   12000
#define Hn   600
#define LATn 200
#define ROWS (Bn*Kn)      // 4096
#define ENCn (2*LATn)     // 400

#define KPAD1 12032       // In padded to 64
#define NPAD1 640         // Hn padded to 160
#define KPAD2 224         // LATn padded to 32-chunk (7 chunks)
#define NPAD2 12032       // In padded to 128
#define HPADK 608         // Hn padded to 32  (K of gemm2)
#define NPADW 512         // ENCn padded to 128 (N of gemm2)

#define Z_OFF  0
#define NO_OFF (ROWS*LATn)                 // 819200
#define KL_OFF (NO_OFF + Bn*In)            // 2355200
#define X_OFF  (KL_OFF + 1)                // 2355201

typedef __nv_bfloat16 BF;

// ---------------- scratch (no allocation allowed) ----------------
__device__ float  g_enc[ROWS*ENCn];
__device__ double g_kl;
__device__ BF g_xhi[(size_t)ROWS*KPAD1];
__device__ BF g_xlo[(size_t)ROWS*KPAD1];
__device__ BF g_w1hi[(size_t)NPAD1*KPAD1];
__device__ BF g_w1lo[(size_t)NPAD1*KPAD1];
__device__ BF g_hhi[(size_t)ROWS*HPADK];
__device__ BF g_hlo[(size_t)ROWS*HPADK];
__device__ BF g_w2hi[(size_t)NPADW*HPADK];
__device__ BF g_w2lo[(size_t)NPADW*HPADK];
__device__ BF g_znhi[(size_t)ROWS*KPAD2];
__device__ BF g_znlo[(size_t)ROWS*KPAD2];
__device__ BF g_ithi[(size_t)NPAD2*KPAD2];
__device__ BF g_itlo[(size_t)NPAD2*KPAD2];

// ==================== helpers ====================
__device__ __forceinline__ uint32_t smem_u32(const void* p) {
    uint32_t a;
    asm("{ .reg .u64 t; cvta.to.shared.u64 t, %1; cvt.u32.u64 %0, t; }" : "=r"(a) : "l"(p));
    return a;
}
#define CP16(dst, src) asm volatile("cp.async.cg.shared.global [%0], [%1], 16;" :: "r"(dst), "l"(src) : "memory")
#define CP_COMMIT()    asm volatile("cp.async.commit_group;" ::: "memory")
#define CP_WAIT1()     asm volatile("cp.async.wait_group 1;" ::: "memory")
#define CP_WAIT0()     asm volatile("cp.async.wait_group 0;" ::: "memory")

__device__ __forceinline__ void ldsm4(uint32_t r[4], uint32_t addr) {
    asm volatile("ldmatrix.sync.aligned.m8n8.x4.shared.b16 {%0,%1,%2,%3}, [%4];"
        : "=r"(r[0]), "=r"(r[1]), "=r"(r[2]), "=r"(r[3]) : "r"(addr));
}
__device__ __forceinline__ void mma16816(float d[4], const uint32_t a[4], uint32_t b0, uint32_t b1) {
    asm volatile("mma.sync.aligned.m16n8k16.row.col.f32.bf16.bf16.f32 "
        "{%0,%1,%2,%3}, {%4,%5,%6,%7}, {%8,%9}, {%0,%1,%2,%3};"
        : "+f"(d[0]), "+f"(d[1]), "+f"(d[2]), "+f"(d[3])
        : "r"(a[0]), "r"(a[1]), "r"(a[2]), "r"(a[3]), "r"(b0), "r"(b1));
}

#define NSTAGE 3

// ---------------- split-bf16 mma mainloop (generalized) ----------------
// A: 128 rows (m0..m0+127), B: BR rows (n0..n0+BR-1), both K-major bf16 [.][kpad].
// Warp layout: 8 warps = 4(m) x 2(n); warp tile 32 x BR/2.
// TERMS==3: acc += Ah*Bh + Ah*Bl + Al*Bh.  TERMS==2: acc += Ah*Bh + Ah*Bl (A-lo never loaded).
// K chunk = 32 elements (64 B per row per chunk). 3-stage cp.async pipeline.
template<int BR, int TERMS>
__device__ __forceinline__ void mma_mainloop(float (&acc)[2][BR/16][4],
    const BF* __restrict__ Ahi, const BF* __restrict__ Alo,
    const BF* __restrict__ Bhi, const BF* __restrict__ Blo,
    long m0, long n0, int kpad, int nch, uint32_t smem_base)
{
    constexpr int A_SZ  = (TERMS == 3) ? 20480 : 10240;
    constexpr int OFF_B = A_SZ;
    constexpr int STAGE = A_SZ + 2 * BR * 80;
    constexpr int NP = BR / 32;       // 16-col ldsm groups per warp

    const int tid = threadIdx.x, lane = tid & 31, wid = tid >> 5;
    const int wm = wid & 3, wn = wid >> 2;
    const long rowb = (long)kpad * 2;

    const char* bAh = (const char*)(Ahi + m0 * (long)kpad);
    const char* bAl = (const char*)(Alo + m0 * (long)kpad);
    const char* bBh = (const char*)(Bhi + n0 * (long)kpad);
    const char* bBl = (const char*)(Blo + n0 * (long)kpad);

    const int rA = tid >> 2, ccA = (tid & 3) * 16;

    auto issue = [&](int c) {
        uint32_t st = smem_base + (c % NSTAGE) * STAGE;
        long go = (long)c * 64;
        // A: 128 rows, 512 16B-chunks -> 2 per thread
        CP16(st + rA * 80 + ccA,        bAh + rA * rowb + ccA + go);
        CP16(st + (rA + 64) * 80 + ccA, bAh + (rA + 64) * rowb + ccA + go);
        if (TERMS == 3) {
            CP16(st + 10240 + rA * 80 + ccA,        bAl + rA * rowb + ccA + go);
            CP16(st + 10240 + (rA + 64) * 80 + ccA, bAl + (rA + 64) * rowb + ccA + go);
        }
        // B hi+lo: BR*4 chunks each
        #pragma unroll
        for (int i = 0; i < (BR * 4 + 255) / 256; i++) {
            int idx = tid + i * 256;
            if ((BR * 4) % 256 == 0 || idx < BR * 4) {
                int r = idx >> 2, cc = (idx & 3) * 16;
                CP16(st + OFF_B + r * 80 + cc,           bBh + r * rowb + cc + go);
                CP16(st + OFF_B + BR * 80 + r * 80 + cc, bBl + r * rowb + cc + go);
            }
        }
        CP_COMMIT();
    };

    issue(0);
    if (nch > 1) issue(1);

    for (int c = 0; c < nch; c++) {
        if (c + 1 < nch) CP_WAIT1(); else CP_WAIT0();
        __syncthreads();

        uint32_t sA = smem_base + (c % NSTAGE) * STAGE;
        uint32_t sB = sA + OFF_B;
        #pragma unroll
        for (int s = 0; s < 2; s++) {
            uint32_t ah[2][4], al[2][4];
            #pragma unroll
            for (int t = 0; t < 2; t++) {
                uint32_t row = wm * 32 + t * 16 + (lane & 15);
                uint32_t ad = sA + row * 80 + s * 32 + ((lane >> 4) & 1) * 16;
                ldsm4(ah[t], ad);
                if (TERMS == 3) ldsm4(al[t], ad + 10240);
            }
            uint32_t bh[NP][4], bl[NP][4];
            #pragma unroll
            for (int p = 0; p < NP; p++) {
                uint32_t row = wn * (BR / 2) + p * 16 + (lane & 7) + ((lane & 16) ? 8 : 0);
                uint32_t ad = sB + row * 80 + s * 32 + ((lane & 8) ? 16 : 0);
                ldsm4(bh[p], ad);
                ldsm4(bl[p], ad + BR * 80);
            }
            #pragma unroll
            for (int t = 0; t < 2; t++)
                #pragma unroll
                for (int p = 0; p < NP; p++)
                    #pragma unroll
                    for (int hh = 0; hh < 2; hh++) {
                        int j = p * 2 + hh;
                        mma16816(acc[t][j], ah[t], bh[p][hh * 2], bh[p][hh * 2 + 1]);
                        mma16816(acc[t][j], ah[t], bl[p][hh * 2], bl[p][hh * 2 + 1]);
                        if (TERMS == 3)
                            mma16816(acc[t][j], al[t], bh[p][hh * 2], bh[p][hh * 2 + 1]);
                    }
        }
        if (c + 2 < nch) issue(c + 2);
    }
}

#define SMEM1 (NSTAGE*(20480 + 2*160*80))   // gemm1: 138240
#define SMEM2 (NSTAGE*(20480 + 2*128*80))   // gemm2: 122880
#define SMEMS (NSTAGE*(10240 + 2*128*80))   // sim:    92160

// ---------------- GEMM1: h = tanh(x @ W1 + b1), N-tile 160, grid (4,32)=128 CTAs ----------------
__global__ void __launch_bounds__(256) gemm1_mma(const BF* __restrict__ Ahi, const BF* __restrict__ Alo,
                                                 const BF* __restrict__ Bhi, const BF* __restrict__ Blo,
                                                 const float* __restrict__ bias,
                                                 BF* __restrict__ Hhi, BF* __restrict__ Hlo)
{
    extern __shared__ char smem[];
    float acc[2][10][4];
    #pragma unroll
    for (int t = 0; t < 2; t++)
        #pragma unroll
        for (int j = 0; j < 10; j++)
            #pragma unroll
            for (int v = 0; v < 4; v++) acc[t][j][v] = 0.f;

    long m0 = (long)blockIdx.y * 128, n0 = (long)blockIdx.x * 160;
    mma_mainloop<160, 3>(acc, Ahi, Alo, Bhi, Blo, m0, n0, KPAD1, KPAD1 / 32, smem_u32(smem));

    const int tid = threadIdx.x, lane = tid & 31, wid = tid >> 5;
    const int wm = wid & 3, wn = wid >> 2;
    const int rr = lane >> 2, q = lane & 3;
    #pragma unroll
    for (int t = 0; t < 2; t++) {
        long m = m0 + wm * 32 + t * 16 + rr;
        #pragma unroll
        for (int j = 0; j < 10; j++) {
            int n = (int)n0 + wn * 80 + j * 8 + 2 * q;
            #pragma unroll
            for (int e = 0; e < 2; e++) {
                int nn = n + e;
                if (nn < HPADK) {
                    float v0 = (nn < Hn) ? tanhf(acc[t][j][e]     + bias[nn]) : 0.f;
                    float v1 = (nn < Hn) ? tanhf(acc[t][j][e + 2] + bias[nn]) : 0.f;
                    BF h0 = __float2bfloat16(v0), h1 = __float2bfloat16(v1);
                    Hhi[m * HPADK + nn]       = h0;
                    Hlo[m * HPADK + nn]       = __float2bfloat16(v0 - __bfloat162float(h0));
                    Hhi[(m + 8) * HPADK + nn] = h1;
                    Hlo[(m + 8) * HPADK + nn] = __float2bfloat16(v1 - __bfloat162float(h1));
                }
            }
        }
    }
}

// ---------------- GEMM2: enc = h @ W2 + b2 (fp32 out), grid (4,32)=128 CTAs ----------------
__global__ void __launch_bounds__(256) gemm2_mma(const BF* __restrict__ Ahi, const BF* __restrict__ Alo,
                                                 const BF* __restrict__ Bhi, const BF* __restrict__ Blo,
                                                 const float* __restrict__ bias, float* __restrict__ E)
{
    extern __shared__ char smem[];
    float acc[2][8][4];
    #pragma unroll
    for (int t = 0; t < 2; t++)
        #pragma unroll
        for (int j = 0; j < 8; j++)
            #pragma unroll
            for (int v = 0; v < 4; v++) acc[t][j][v] = 0.f;

    long m0 = (long)blockIdx.y * 128, n0 = (long)blockIdx.x * 128;
    mma_mainloop<128, 3>(acc, Ahi, Alo, Bhi, Blo, m0, n0, HPADK, HPADK / 32, smem_u32(smem));

    const int tid = threadIdx.x, lane = tid & 31, wid = tid >> 5;
    const int wm = wid & 3, wn = wid >> 2;
    const int rr = lane >> 2, q = lane & 3;
    #pragma unroll
    for (int t = 0; t < 2; t++) {
        long m = m0 + wm * 32 + t * 16 + rr;
        #pragma unroll
        for (int j = 0; j < 8; j++) {
            int n = (int)n0 + wn * 64 + j * 8 + 2 * q;
            #pragma unroll
            for (int e = 0; e < 2; e++) {
                int nn = n + e;
                if (nn < ENCn) {
                    E[m * ENCn + nn]       = acc[t][j][e]     + bias[nn];
                    E[(m + 8) * ENCn + nn] = acc[t][j][e + 2] + bias[nn];
                }
            }
        }
    }
}

// ---------------- sim: new_output = log(mean_k exp(zn @ itn^T / tau) + 1) ----------------
// 2-term split: zn-lo dropped (z output itself is exact; error only touches new_output).
__global__ void __launch_bounds__(256) sim_mma(const BF* __restrict__ Ahi, const BF* __restrict__ Alo,
                                               const BF* __restrict__ Bhi, const BF* __restrict__ Blo,
                                               float* __restrict__ no_out)
{
    extern __shared__ char smem[];
    float acc[2][8][4];
    #pragma unroll
    for (int t = 0; t < 2; t++)
        #pragma unroll
        for (int j = 0; j < 8; j++)
            #pragma unroll
            for (int v = 0; v < 4; v++) acc[t][j][v] = 0.f;

    long m0 = (long)blockIdx.y * 128, n0 = (long)blockIdx.x * 128;
    mma_mainloop<128, 2>(acc, Ahi, Alo, Bhi, Blo, m0, n0, KPAD2, KPAD2 / 32, smem_u32(smem));

    const int tid = threadIdx.x, lane = tid & 31, wid = tid >> 5;
    const int wm = wid & 3, wn = wid >> 2;
    const int q = lane & 3;
    long b = blockIdx.y * 4 + wm;     // user; warp's 32 m-rows = this user's 32 K rows
    #pragma unroll
    for (int j = 0; j < 8; j++) {
        float s0 = __expf(10.0f * acc[0][j][0]) + __expf(10.0f * acc[0][j][2])
                 + __expf(10.0f * acc[1][j][0]) + __expf(10.0f * acc[1][j][2]);
        float s1 = __expf(10.0f * acc[0][j][1]) + __expf(10.0f * acc[0][j][3])
                 + __expf(10.0f * acc[1][j][1]) + __expf(10.0f * acc[1][j][3]);
        #pragma unroll
        for (int off = 4; off < 32; off <<= 1) {
            s0 += __shfl_xor_sync(0xffffffffu, s0, off);
            s1 += __shfl_xor_sync(0xffffffffu, s1, off);
        }
        if (lane < 4) {
            int n = (int)n0 + wn * 64 + j * 8 + 2 * q;
            if (n < In)     no_out[b * In + n]     = logf(s0 * (1.0f / 32.0f) + 1.0f);
            if (n + 1 < In) no_out[b * In + n + 1] = logf(s1 * (1.0f / 32.0f) + 1.0f);
        }
    }
}

// ---------------- items l2-normalize -> bf16 hi/lo, padded [NPAD2][KPAD2] ----------------
__global__ void items_norm_kernel(const float* __restrict__ items, BF* __restrict__ hi, BF* __restrict__ lo)
{
    int warp = (blockIdx.x * blockDim.x + threadIdx.x) >> 5;
    int lane = threadIdx.x & 31;
    if (warp >= NPAD2) return;
    BF* dh = hi + (size_t)warp * KPAD2;
    BF* dl = lo + (size_t)warp * KPAD2;
    if (warp >= In) {
        for (int j = lane; j < KPAD2; j += 32) { dh[j] = __float2bfloat16(0.f); dl[j] = __float2bfloat16(0.f); }
        return;
    }
    const float* src = items + (long)warp * LATn;
    float v[7];
    float ss = 0.f;
    int cnt = 0;
    for (int j = lane; j < LATn; j += 32) { float t = src[j]; v[cnt++] = t; ss += t * t; }
    #pragma unroll
    for (int o = 16; o; o >>= 1) ss += __shfl_xor_sync(0xffffffffu, ss, o);
    float inv = 1.0f / fmaxf(sqrtf(ss), 1e-12f);
    cnt = 0;
    for (int j = lane; j < KPAD2; j += 32) {
        float t = (j < LATn) ? v[cnt++] * inv : 0.f;
        BF h = __float2bfloat16(t);
        dh[j] = h;
        dl[j] = __float2bfloat16(t - __bfloat162float(h));
    }
}

// ---------------- W1 [In,Hn] f32 -> W1^T hi/lo bf16 [NPAD1][KPAD1] ----------------
__global__ void convW1_kernel(const float* __restrict__ W1, BF* __restrict__ hi, BF* __restrict__ lo)
{
    __shared__ float t[32][33];
    int kb = blockIdx.x * 32, nb = blockIdx.y * 32;
    int tx = threadIdx.x, ty = threadIdx.y;   // (32, 8)
    for (int j = ty; j < 32; j += 8) {
        int k = kb + j, n = nb + tx;
        t[j][tx] = (k < In && n < Hn) ? W1[(long)k * Hn + n] : 0.f;
    }
    __syncthreads();
    for (int j = ty; j < 32; j += 8) {
        int n = nb + j, k = kb + tx;
        if (n < NPAD1 && k < KPAD1) {
            float v = t[tx][j];
            BF h = __float2bfloat16(v);
            hi[(size_t)n * KPAD1 + k] = h;
            lo[(size_t)n * KPAD1 + k] = __float2bfloat16(v - __bfloat162float(h));
        }
    }
}

// ---------------- W2 [Hn,ENCn] f32 -> W2^T hi/lo bf16 [NPADW][HPADK] ----------------
__global__ void convW2_kernel(const float* __restrict__ W2, BF* __restrict__ hi, BF* __restrict__ lo)
{
    __shared__ float t[32][33];
    int kb = blockIdx.x * 32, nb = blockIdx.y * 32;
    int tx = threadIdx.x, ty = threadIdx.y;   // (32, 8)
    for (int j = ty; j < 32; j += 8) {
        int k = kb + j, n = nb + tx;
        t[j][tx] = (k < Hn && n < ENCn) ? W2[(long)k * ENCn + n] : 0.f;
    }
    __syncthreads();
    for (int j = ty; j < 32; j += 8) {
        int n = nb + j, k = kb + tx;
        if (n < NPADW && k < HPADK) {
            float v = t[tx][j];
            BF h = __float2bfloat16(v);
            hi[(size_t)n * HPADK + k] = h;
            lo[(size_t)n * HPADK + k] = __float2bfloat16(v - __bfloat162float(h));
        }
    }
}

// ---------------- x = masked gram row / l2norm : single gram read via smem ----------------
__global__ void __launch_bounds__(512) x_kernel(const float* __restrict__ rating, const int* __restrict__ items_idx,
                                                const float* __restrict__ gram, float* __restrict__ x_out,
                                                BF* __restrict__ xhi, BF* __restrict__ xlo)
{
    __shared__ float sg[In];      // 48000 B
    __shared__ float red[16];
    const int tid = threadIdx.x;
    int bk  = blockIdx.x;
    int b   = bk >> 5;
    int row = items_idx[bk];
    const float4* r4 = (const float4*)(rating + (long)b * In);
    const float4* g4 = (const float4*)(gram + (long)row * In);
    float ss = 0.f;
    for (int i = tid; i < In / 4; i += 512) {
        float4 rv = r4[i];
        float4 gv = g4[i];
        float4 m;
        m.x = (rv.x > 0.f) ? gv.x : 0.f;
        m.y = (rv.y > 0.f) ? gv.y : 0.f;
        m.z = (rv.z > 0.f) ? gv.z : 0.f;
        m.w = (rv.w > 0.f) ? gv.w : 0.f;
        ss += m.x * m.x + m.y * m.y + m.z * m.z + m.w * m.w;
        *(float4*)&sg[i * 4] = m;
    }
    #pragma unroll
    for (int o = 16; o; o >>= 1) ss += __shfl_xor_sync(0xffffffffu, ss, o);
    if ((tid & 31) == 0) red[tid >> 5] = ss;
    __syncthreads();
    if (tid < 16) {
        float t = red[tid];
        #pragma unroll
        for (int o = 8; o; o >>= 1) t += __shfl_xor_sync(0xffffu, t, o);
        if (tid == 0) red[0] = t;
    }
    __syncthreads();
    float inv = 1.0f / fmaxf(sqrtf(red[0]), 1e-12f);
    float* dst = x_out + (long)bk * In;        // 4B-aligned only (odd base offset)
    for (int i = tid; i < In; i += 512) dst[i] = sg[i] * inv;
    uint32_t* dh = (uint32_t*)(xhi + (size_t)bk * KPAD1);
    uint32_t* dl = (uint32_t*)(xlo + (size_t)bk * KPAD1);
    for (int i = tid; i < KPAD1 / 2; i += 512) {
        int i0 = 2 * i;
        float v0 = (i0     < In) ? sg[i0]     * inv : 0.f;
        float v1 = (i0 + 1 < In) ? sg[i0 + 1] * inv : 0.f;
        BF h0 = __float2bfloat16(v0), h1 = __float2bfloat16(v1);
        __nv_bfloat162 hp; hp.x = h0; hp.y = h1;
        __nv_bfloat162 lp;
        lp.x = __float2bfloat16(v0 - __bfloat162float(h0));
        lp.y = __float2bfloat16(v1 - __bfloat162float(h1));
        dh[i] = *(uint32_t*)&hp;
        dl[i] = *(uint32_t*)&lp;
    }
}

// ---------------- enc postprocess: z, zn(hi/lo), kl ----------------
__global__ void postenc_kernel(const float* __restrict__ enc, float* __restrict__ z_out,
                               BF* __restrict__ znhi, BF* __restrict__ znlo, double* __restrict__ kl_acc)
{
    int warp = (blockIdx.x * blockDim.x + threadIdx.x) >> 5;
    int lane = threadIdx.x & 31;
    if (warp >= ROWS) return;
    const float* e = enc + (long)warp * ENCn;
    float mv[7];
    float ss = 0.f, klp = 0.f;
    int cnt = 0;
    for (int j = lane; j < LATn; j += 32) {
        float m  = e[j];
        float lv = e[j + LATn];
        mv[cnt++] = m;
        ss  += m * m;
        klp += m * m + (expm1f(lv) - lv);
    }
    #pragma unroll
    for (int o = 16; o; o >>= 1) {
        ss  += __shfl_xor_sync(0xffffffffu, ss, o);
        klp += __shfl_xor_sync(0xffffffffu, klp, o);
    }
    float inv = 1.0f / fmaxf(sqrtf(ss), 1e-12f);
    cnt = 0;
    for (int j = lane; j < KPAD2; j += 32) {
        float t = 0.f;
        if (j < LATn) {
            z_out[(long)warp * LATn + j] = mv[cnt];
            t = mv[cnt++] * inv;
        }
        BF h = __float2bfloat16(t);
        znhi[(size_t)warp * KPAD2 + j] = h;
        znlo[(size_t)warp * KPAD2 + j] = __float2bfloat16(t - __bfloat162float(h));
    }
    if (lane == 0) atomicAdd(kl_acc, (double)klp);
}

__global__ void zero_kl_kernel(double* p) { *p = 0.0; }
__global__ void fin_kl_kernel(const double* p, float* out) { *out = (float)(0.5 * (*p) / (double)ROWS); }

// ---------------- launch ----------------
extern "C" void kernel_launch(void* const* d_in, const int* in_sizes, int n_in,
                              void* d_out, int out_size)
{
    const float* rating    = (const float*)d_in[0];
    const int*   items_idx = (const int*)  d_in[1];
    const float* gram      = (const float*)d_in[2];
    const float* W1        = (const float*)d_in[3];
    const float* b1        = (const float*)d_in[4];
    const float* W2        = (const float*)d_in[5];
    const float* b2        = (const float*)d_in[6];
    const float* items     = (const float*)d_in[7];

    float* out    = (float*)d_out;
    float* z_out  = out + Z_OFF;
    float* no_out = out + NO_OFF;
    float* kl_out = out + KL_OFF;
    float* x_out  = out + X_OFF;

    float* enc; double* klp;
    BF *xhi, *xlo, *w1hi, *w1lo, *hhi, *hlo, *w2hi, *w2lo, *znhi, *znlo, *ithi, *itlo;
    cudaGetSymbolAddress((void**)&enc,  g_enc);
    cudaGetSymbolAddress((void**)&klp,  g_kl);
    cudaGetSymbolAddress((void**)&xhi,  g_xhi);
    cudaGetSymbolAddress((void**)&xlo,  g_xlo);
    cudaGetSymbolAddress((void**)&w1hi, g_w1hi);
    cudaGetSymbolAddress((void**)&w1lo, g_w1lo);
    cudaGetSymbolAddress((void**)&hhi,  g_hhi);
    cudaGetSymbolAddress((void**)&hlo,  g_hlo);
    cudaGetSymbolAddress((void**)&w2hi, g_w2hi);
    cudaGetSymbolAddress((void**)&w2lo, g_w2lo);
    cudaGetSymbolAddress((void**)&znhi, g_znhi);
    cudaGetSymbolAddress((void**)&znlo, g_znlo);
    cudaGetSymbolAddress((void**)&ithi, g_ithi);
    cudaGetSymbolAddress((void**)&itlo, g_itlo);

    cudaFuncSetAttribute(gemm1_mma, cudaFuncAttributeMaxDynamicSharedMemorySize, SMEM1);
    cudaFuncSetAttribute(gemm2_mma, cudaFuncAttributeMaxDynamicSharedMemorySize, SMEM2);
    cudaFuncSetAttribute(sim_mma,   cudaFuncAttributeMaxDynamicSharedMemorySize, SMEMS);

    zero_kl_kernel<<<1, 1>>>(klp);
    items_norm_kernel<<<(NPAD2 * 32 + 255) / 256, 256>>>(items, ithi, itlo);
    convW1_kernel<<<dim3(KPAD1 / 32, NPAD1 / 32), dim3(32, 8)>>>(W1, w1hi, w1lo);
    convW2_kernel<<<dim3(HPADK / 32, NPADW / 32), dim3(32, 8)>>>(W2, w2hi, w2lo);
    x_kernel<<<ROWS, 512>>>(rating, items_idx, gram, x_out, xhi, xlo);
    // h = tanh(x @ W1 + b1): split-bf16 HMMA, N-tile 160, single wave (128 CTAs)
    gemm1_mma<<<dim3(NPAD1 / 160, ROWS / 128), 256, SMEM1>>>(xhi, xlo, w1hi, w1lo, b1, hhi, hlo);
    // enc = h @ W2 + b2: split-bf16 HMMA (128 CTAs, single wave)
    gemm2_mma<<<dim3(NPADW / 128, ROWS / 128), 256, SMEM2>>>(hhi, hlo, w2hi, w2lo, b2, enc);
    postenc_kernel<<<(ROWS * 32 + 255) / 256, 256>>>(enc, z_out, znhi, znlo, klp);
    fin_kl_kernel<<<1, 1>>>(klp, kl_out);
    // new_output: 2-term split-bf16 HMMA with fused exp/mean/log epilogue
    sim_mma<<<dim3(NPAD2 / 128, ROWS / 128), 256, SMEMS>>>(znhi, znlo, ithi, itlo, no_out);
}

// round 10
// speedup vs baseline: 4.9904x; 1.1522x over previous
#include <cuda_runtime.h>
#include <cuda_fp16.h>
#include <math.h>
#include <stdint.h>

#define Bn   128
#define Kn   32
#define In   12000
#define Hn   600
#define LATn 200
#define ROWS (Bn*Kn)      // 4096
#define ENCn (2*LATn)     // 400

#define KPAD1 12032       // In padded to 64
#define NPAD1 640         // Hn padded to 160
#define KPAD2 224         // LATn padded to 32-chunk (7 chunks)
#define NPAD2 12032       // In padded to 128
#define HPADK 608         // Hn padded to 32  (K of gemm2)
#define NPADW 512         // ENCn padded to 128 (N of gemm2)

#define Z_OFF  0
#define NO_OFF (ROWS*LATn)                 // 819200
#define KL_OFF (NO_OFF + Bn*In)            // 2355200
#define X_OFF  (KL_OFF + 1)                // 2355201

#define LO_SCALE   512.0f
#define LO_INV     (1.0f/512.0f)

typedef __half HF;

// ---------------- scratch (no allocation allowed) ----------------
__device__ float  g_enc[ROWS*ENCn];
__device__ double g_kl;
__device__ HF g_xh [(size_t)ROWS*KPAD1];
__device__ HF g_w1h[(size_t)NPAD1*KPAD1];
__device__ HF g_w1l[(size_t)NPAD1*KPAD1];    // lo * 512
__device__ HF g_hh [(size_t)ROWS*HPADK];
__device__ HF g_w2h[(size_t)NPADW*HPADK];
__device__ HF g_w2l[(size_t)NPADW*HPADK];    // lo * 512
__device__ HF g_znh[(size_t)ROWS*KPAD2];
__device__ HF g_ith[(size_t)NPAD2*KPAD2];
__device__ HF g_itl[(size_t)NPAD2*KPAD2];    // lo * 512

// ==================== helpers ====================
__device__ __forceinline__ uint32_t smem_u32(const void* p) {
    uint32_t a;
    asm("{ .reg .u64 t; cvta.to.shared.u64 t, %1; cvt.u32.u64 %0, t; }" : "=r"(a) : "l"(p));
    return a;
}
#define CP16(dst, src) asm volatile("cp.async.cg.shared.global [%0], [%1], 16;" :: "r"(dst), "l"(src) : "memory")
#define CP_COMMIT()    asm volatile("cp.async.commit_group;" ::: "memory")
#define CP_WAIT1()     asm volatile("cp.async.wait_group 1;" ::: "memory")
#define CP_WAIT0()     asm volatile("cp.async.wait_group 0;" ::: "memory")

__device__ __forceinline__ void ldsm4(uint32_t r[4], uint32_t addr) {
    asm volatile("ldmatrix.sync.aligned.m8n8.x4.shared.b16 {%0,%1,%2,%3}, [%4];"
        : "=r"(r[0]), "=r"(r[1]), "=r"(r[2]), "=r"(r[3]) : "r"(addr));
}
__device__ __forceinline__ void mma16816h(float d[4], const uint32_t a[4], uint32_t b0, uint32_t b1) {
    asm volatile("mma.sync.aligned.m16n8k16.row.col.f32.f16.f16.f32 "
        "{%0,%1,%2,%3}, {%4,%5,%6,%7}, {%8,%9}, {%0,%1,%2,%3};"
        : "+f"(d[0]), "+f"(d[1]), "+f"(d[2]), "+f"(d[3])
        : "r"(a[0]), "r"(a[1]), "r"(a[2]), "r"(a[3]), "r"(b0), "r"(b1));
}

__device__ __forceinline__ void split_hf(float v, HF& hi, HF& lo) {
    hi = __float2half(v);
    lo = __float2half((v - __half2float(hi)) * LO_SCALE);
}

#define NSTAGE 3

// ---------------- fp16 dual-acc mma mainloop ----------------
// A: 128 rows (hi only). B: BR rows, hi + lo(*512).
// accM += Ah*Bh ; accC += Ah*Bl.  Final value = accM + accC/512.
// K chunk = 32 elements (64 B/row). 3-stage cp.async pipeline. Smem row stride 80 B.
template<int BR>
__device__ __forceinline__ void mma_mainloop2(float (&accM)[2][BR/16][4], float (&accC)[2][BR/16][4],
    const HF* __restrict__ Ah, const HF* __restrict__ Bh, const HF* __restrict__ Bl,
    long m0, long n0, int kpad, int nch, uint32_t smem_base)
{
    constexpr int OFF_B  = 10240;            // A hi = 128*80
    constexpr int OFF_BL = 10240 + BR * 80;
    constexpr int STAGE  = 10240 + 2 * BR * 80;
    constexpr int NP = BR / 32;              // 16-row ldsm groups per wn warp

    const int tid = threadIdx.x, lane = tid & 31, wid = tid >> 5;
    const int wm = wid & 3, wn = wid >> 2;
    const long rowb = (long)kpad * 2;

    const char* bA  = (const char*)(Ah + m0 * (long)kpad);
    const char* bBh = (const char*)(Bh + n0 * (long)kpad);
    const char* bBl = (const char*)(Bl + n0 * (long)kpad);

    const int rA = tid >> 2, ccA = (tid & 3) * 16;

    auto issue = [&](int c) {
        uint32_t st = smem_base + (c % NSTAGE) * STAGE;
        long go = (long)c * 64;
        CP16(st + rA * 80 + ccA,        bA + rA * rowb + ccA + go);
        CP16(st + (rA + 64) * 80 + ccA, bA + (rA + 64) * rowb + ccA + go);
        #pragma unroll
        for (int i = 0; i < (BR * 4 + 255) / 256; i++) {
            int idx = tid + i * 256;
            if ((BR * 4) % 256 == 0 || idx < BR * 4) {
                int r = idx >> 2, cc = (idx & 3) * 16;
                CP16(st + OFF_B  + r * 80 + cc, bBh + r * rowb + cc + go);
                CP16(st + OFF_BL + r * 80 + cc, bBl + r * rowb + cc + go);
            }
        }
        CP_COMMIT();
    };

    issue(0);
    if (nch > 1) issue(1);

    for (int c = 0; c < nch; c++) {
        if (c + 1 < nch) CP_WAIT1(); else CP_WAIT0();
        __syncthreads();

        uint32_t sA = smem_base + (c % NSTAGE) * STAGE;
        #pragma unroll
        for (int s = 0; s < 2; s++) {
            uint32_t ah[2][4];
            #pragma unroll
            for (int t = 0; t < 2; t++) {
                uint32_t row = wm * 32 + t * 16 + (lane & 15);
                uint32_t ad = sA + row * 80 + s * 32 + ((lane >> 4) & 1) * 16;
                ldsm4(ah[t], ad);
            }
            #pragma unroll
            for (int p = 0; p < NP; p++) {
                uint32_t bh[4], bl[4];
                uint32_t row = wn * (BR / 2) + p * 16 + (lane & 7) + ((lane & 16) ? 8 : 0);
                uint32_t ad = sA + OFF_B + row * 80 + s * 32 + ((lane & 8) ? 16 : 0);
                ldsm4(bh, ad);
                ldsm4(bl, ad + BR * 80);
                #pragma unroll
                for (int t = 0; t < 2; t++)
                    #pragma unroll
                    for (int hh = 0; hh < 2; hh++) {
                        int j = p * 2 + hh;
                        mma16816h(accM[t][j], ah[t], bh[hh * 2], bh[hh * 2 + 1]);
                        mma16816h(accC[t][j], ah[t], bl[hh * 2], bl[hh * 2 + 1]);
                    }
            }
        }
        if (c + 2 < nch) issue(c + 2);
    }
}

#define SMEM1 (NSTAGE*(10240 + 2*160*80))   // gemm1: 107520
#define SMEM2 (NSTAGE*(10240 + 2*128*80))   // gemm2 / sim: 92160

// ---------------- GEMM1: h = tanh(x @ W1 + b1), N-tile 160, grid (4,32)=128 CTAs ----------------
__global__ void __launch_bounds__(256) gemm1_mma(const HF* __restrict__ Ah,
                                                 const HF* __restrict__ Bh, const HF* __restrict__ Bl,
                                                 const float* __restrict__ bias,
                                                 HF* __restrict__ Hh)
{
    extern __shared__ char smem[];
    float accM[2][10][4], accC[2][10][4];
    #pragma unroll
    for (int t = 0; t < 2; t++)
        #pragma unroll
        for (int j = 0; j < 10; j++)
            #pragma unroll
            for (int v = 0; v < 4; v++) { accM[t][j][v] = 0.f; accC[t][j][v] = 0.f; }

    long m0 = (long)blockIdx.y * 128, n0 = (long)blockIdx.x * 160;
    mma_mainloop2<160>(accM, accC, Ah, Bh, Bl, m0, n0, KPAD1, KPAD1 / 32, smem_u32(smem));

    const int tid = threadIdx.x, lane = tid & 31, wid = tid >> 5;
    const int wm = wid & 3, wn = wid >> 2;
    const int rr = lane >> 2, q = lane & 3;
    #pragma unroll
    for (int t = 0; t < 2; t++) {
        long m = m0 + wm * 32 + t * 16 + rr;
        #pragma unroll
        for (int j = 0; j < 10; j++) {
            int n = (int)n0 + wn * 80 + j * 8 + 2 * q;
            #pragma unroll
            for (int e = 0; e < 2; e++) {
                int nn = n + e;
                if (nn < HPADK) {
                    float p0 = accM[t][j][e]     + accC[t][j][e]     * LO_INV;
                    float p1 = accM[t][j][e + 2] + accC[t][j][e + 2] * LO_INV;
                    float v0 = (nn < Hn) ? tanhf(p0 + bias[nn]) : 0.f;
                    float v1 = (nn < Hn) ? tanhf(p1 + bias[nn]) : 0.f;
                    Hh[m * HPADK + nn]       = __float2half(v0);
                    Hh[(m + 8) * HPADK + nn] = __float2half(v1);
                }
            }
        }
    }
}

// ---------------- GEMM2: enc = h @ W2 + b2 (fp32 out), grid (4,32)=128 CTAs ----------------
__global__ void __launch_bounds__(256) gemm2_mma(const HF* __restrict__ Ah,
                                                 const HF* __restrict__ Bh, const HF* __restrict__ Bl,
                                                 const float* __restrict__ bias, float* __restrict__ E)
{
    extern __shared__ char smem[];
    float accM[2][8][4], accC[2][8][4];
    #pragma unroll
    for (int t = 0; t < 2; t++)
        #pragma unroll
        for (int j = 0; j < 8; j++)
            #pragma unroll
            for (int v = 0; v < 4; v++) { accM[t][j][v] = 0.f; accC[t][j][v] = 0.f; }

    long m0 = (long)blockIdx.y * 128, n0 = (long)blockIdx.x * 128;
    mma_mainloop2<128>(accM, accC, Ah, Bh, Bl, m0, n0, HPADK, HPADK / 32, smem_u32(smem));

    const int tid = threadIdx.x, lane = tid & 31, wid = tid >> 5;
    const int wm = wid & 3, wn = wid >> 2;
    const int rr = lane >> 2, q = lane & 3;
    #pragma unroll
    for (int t = 0; t < 2; t++) {
        long m = m0 + wm * 32 + t * 16 + rr;
        #pragma unroll
        for (int j = 0; j < 8; j++) {
            int n = (int)n0 + wn * 64 + j * 8 + 2 * q;
            #pragma unroll
            for (int e = 0; e < 2; e++) {
                int nn = n + e;
                if (nn < ENCn) {
                    E[m * ENCn + nn]       = accM[t][j][e]     + accC[t][j][e]     * LO_INV + bias[nn];
                    E[(m + 8) * ENCn + nn] = accM[t][j][e + 2] + accC[t][j][e + 2] * LO_INV + bias[nn];
                }
            }
        }
    }
}

// ---------------- sim: new_output = log(mean_k exp(zn @ itn^T / tau) + 1) ----------------
__global__ void __launch_bounds__(256) sim_mma(const HF* __restrict__ Ah,
                                               const HF* __restrict__ Bh, const HF* __restrict__ Bl,
                                               float* __restrict__ no_out)
{
    extern __shared__ char smem[];
    float accM[2][8][4], accC[2][8][4];
    #pragma unroll
    for (int t = 0; t < 2; t++)
        #pragma unroll
        for (int j = 0; j < 8; j++)
            #pragma unroll
            for (int v = 0; v < 4; v++) { accM[t][j][v] = 0.f; accC[t][j][v] = 0.f; }

    long m0 = (long)blockIdx.y * 128, n0 = (long)blockIdx.x * 128;
    mma_mainloop2<128>(accM, accC, Ah, Bh, Bl, m0, n0, KPAD2, KPAD2 / 32, smem_u32(smem));

    const int tid = threadIdx.x, lane = tid & 31, wid = tid >> 5;
    const int wm = wid & 3, wn = wid >> 2;
    const int q = lane & 3;
    long b = blockIdx.y * 4 + wm;     // user; warp's 32 m-rows = this user's 32 K rows
    #pragma unroll
    for (int j = 0; j < 8; j++) {
        float s0 = __expf(10.0f * (accM[0][j][0] + accC[0][j][0] * LO_INV))
                 + __expf(10.0f * (accM[0][j][2] + accC[0][j][2] * LO_INV))
                 + __expf(10.0f * (accM[1][j][0] + accC[1][j][0] * LO_INV))
                 + __expf(10.0f * (accM[1][j][2] + accC[1][j][2] * LO_INV));
        float s1 = __expf(10.0f * (accM[0][j][1] + accC[0][j][1] * LO_INV))
                 + __expf(10.0f * (accM[0][j][3] + accC[0][j][3] * LO_INV))
                 + __expf(10.0f * (accM[1][j][1] + accC[1][j][1] * LO_INV))
                 + __expf(10.0f * (accM[1][j][3] + accC[1][j][3] * LO_INV));
        #pragma unroll
        for (int off = 4; off < 32; off <<= 1) {
            s0 += __shfl_xor_sync(0xffffffffu, s0, off);
            s1 += __shfl_xor_sync(0xffffffffu, s1, off);
        }
        if (lane < 4) {
            int n = (int)n0 + wn * 64 + j * 8 + 2 * q;
            if (n < In)     no_out[b * In + n]     = logf(s0 * (1.0f / 32.0f) + 1.0f);
            if (n + 1 < In) no_out[b * In + n + 1] = logf(s1 * (1.0f / 32.0f) + 1.0f);
        }
    }
}

// ---------------- items l2-normalize -> fp16 hi / lo*512, padded [NPAD2][KPAD2] ----------------
__global__ void items_norm_kernel(const float* __restrict__ items, HF* __restrict__ hi, HF* __restrict__ lo)
{
    int warp = (blockIdx.x * blockDim.x + threadIdx.x) >> 5;
    int lane = threadIdx.x & 31;
    if (warp >= NPAD2) return;
    HF* dh = hi + (size_t)warp * KPAD2;
    HF* dl = lo + (size_t)warp * KPAD2;
    if (warp >= In) {
        for (int j = lane; j < KPAD2; j += 32) { dh[j] = __float2half(0.f); dl[j] = __float2half(0.f); }
        return;
    }
    const float* src = items + (long)warp * LATn;
    float v[7];
    float ss = 0.f;
    int cnt = 0;
    for (int j = lane; j < LATn; j += 32) { float t = src[j]; v[cnt++] = t; ss += t * t; }
    #pragma unroll
    for (int o = 16; o; o >>= 1) ss += __shfl_xor_sync(0xffffffffu, ss, o);
    float inv = 1.0f / fmaxf(sqrtf(ss), 1e-12f);
    cnt = 0;
    for (int j = lane; j < KPAD2; j += 32) {
        float t = (j < LATn) ? v[cnt++] * inv : 0.f;
        HF h, l;
        split_hf(t, h, l);
        dh[j] = h;
        dl[j] = l;
    }
}

// ---------------- W1 [In,Hn] f32 -> W1^T hi / lo*512 fp16 [NPAD1][KPAD1] ----------------
__global__ void convW1_kernel(const float* __restrict__ W1, HF* __restrict__ hi, HF* __restrict__ lo)
{
    __shared__ float t[32][33];
    int kb = blockIdx.x * 32, nb = blockIdx.y * 32;
    int tx = threadIdx.x, ty = threadIdx.y;   // (32, 8)
    for (int j = ty; j < 32; j += 8) {
        int k = kb + j, n = nb + tx;
        t[j][tx] = (k < In && n < Hn) ? W1[(long)k * Hn + n] : 0.f;
    }
    __syncthreads();
    for (int j = ty; j < 32; j += 8) {
        int n = nb + j, k = kb + tx;
        if (n < NPAD1 && k < KPAD1) {
            HF h, l;
            split_hf(t[tx][j], h, l);
            hi[(size_t)n * KPAD1 + k] = h;
            lo[(size_t)n * KPAD1 + k] = l;
        }
    }
}

// ---------------- W2 [Hn,ENCn] f32 -> W2^T hi / lo*512 fp16 [NPADW][HPADK] ----------------
__global__ void convW2_kernel(const float* __restrict__ W2, HF* __restrict__ hi, HF* __restrict__ lo)
{
    __shared__ float t[32][33];
    int kb = blockIdx.x * 32, nb = blockIdx.y * 32;
    int tx = threadIdx.x, ty = threadIdx.y;   // (32, 8)
    for (int j = ty; j < 32; j += 8) {
        int k = kb + j, n = nb + tx;
        t[j][tx] = (k < Hn && n < ENCn) ? W2[(long)k * ENCn + n] : 0.f;
    }
    __syncthreads();
    for (int j = ty; j < 32; j += 8) {
        int n = nb + j, k = kb + tx;
        if (n < NPADW && k < HPADK) {
            HF h, l;
            split_hf(t[tx][j], h, l);
            hi[(size_t)n * HPADK + k] = h;
            lo[(size_t)n * HPADK + k] = l;
        }
    }
}

// ---------------- x = masked gram row / l2norm : single gram read via smem ----------------
__global__ void __launch_bounds__(512) x_kernel(const float* __restrict__ rating, const int* __restrict__ items_idx,
                                                const float* __restrict__ gram, float* __restrict__ x_out,
                                                HF* __restrict__ xh)
{
    __shared__ float sg[In];      // 48000 B
    __shared__ float red[16];
    const int tid = threadIdx.x;
    int bk  = blockIdx.x;
    int b   = bk >> 5;
    int row = items_idx[bk];
    const float4* r4 = (const float4*)(rating + (long)b * In);
    const float4* g4 = (const float4*)(gram + (long)row * In);
    float ss = 0.f;
    for (int i = tid; i < In / 4; i += 512) {
        float4 rv = r4[i];
        float4 gv = g4[i];
        float4 m;
        m.x = (rv.x > 0.f) ? gv.x : 0.f;
        m.y = (rv.y > 0.f) ? gv.y : 0.f;
        m.z = (rv.z > 0.f) ? gv.z : 0.f;
        m.w = (rv.w > 0.f) ? gv.w : 0.f;
        ss += m.x * m.x + m.y * m.y + m.z * m.z + m.w * m.w;
        *(float4*)&sg[i * 4] = m;
    }
    #pragma unroll
    for (int o = 16; o; o >>= 1) ss += __shfl_xor_sync(0xffffffffu, ss, o);
    if ((tid & 31) == 0) red[tid >> 5] = ss;
    __syncthreads();
    if (tid < 16) {
        float t = red[tid];
        #pragma unroll
        for (int o = 8; o; o >>= 1) t += __shfl_xor_sync(0xffffu, t, o);
        if (tid == 0) red[0] = t;
    }
    __syncthreads();
    float inv = 1.0f / fmaxf(sqrtf(red[0]), 1e-12f);
    float* dst = x_out + (long)bk * In;        // 4B-aligned only (odd base offset)
    for (int i = tid; i < In; i += 512) dst[i] = sg[i] * inv;
    uint32_t* dh = (uint32_t*)(xh + (size_t)bk * KPAD1);
    for (int i = tid; i < KPAD1 / 2; i += 512) {
        int i0 = 2 * i;
        float v0 = (i0     < In) ? sg[i0]     * inv : 0.f;
        float v1 = (i0 + 1 < In) ? sg[i0 + 1] * inv : 0.f;
        __half2 hp;
        hp.x = __float2half(v0);
        hp.y = __float2half(v1);
        dh[i] = *(uint32_t*)&hp;
    }
}

// ---------------- enc postprocess: z, zn-hi(fp16), kl ----------------
__global__ void postenc_kernel(const float* __restrict__ enc, float* __restrict__ z_out,
                               HF* __restrict__ znh, double* __restrict__ kl_acc)
{
    int warp = (blockIdx.x * blockDim.x + threadIdx.x) >> 5;
    int lane = threadIdx.x & 31;
    if (warp >= ROWS) return;
    const float* e = enc + (long)warp * ENCn;
    float mv[7];
    float ss = 0.f, klp = 0.f;
    int cnt = 0;
    for (int j = lane; j < LATn; j += 32) {
        float m  = e[j];
        float lv = e[j + LATn];
        mv[cnt++] = m;
        ss  += m * m;
        klp += m * m + (expm1f(lv) - lv);
    }
    #pragma unroll
    for (int o = 16; o; o >>= 1) {
        ss  += __shfl_xor_sync(0xffffffffu, ss, o);
        klp += __shfl_xor_sync(0xffffffffu, klp, o);
    }
    float inv = 1.0f / fmaxf(sqrtf(ss), 1e-12f);
    cnt = 0;
    for (int j = lane; j < KPAD2; j += 32) {
        float t = 0.f;
        if (j < LATn) {
            z_out[(long)warp * LATn + j] = mv[cnt];
            t = mv[cnt++] * inv;
        }
        znh[(size_t)warp * KPAD2 + j] = __float2half(t);
    }
    if (lane == 0) atomicAdd(kl_acc, (double)klp);
}

__global__ void zero_kl_kernel(double* p) { *p = 0.0; }
__global__ void fin_kl_kernel(const double* p, float* out) { *out = (float)(0.5 * (*p) / (double)ROWS); }

// ---------------- launch ----------------
extern "C" void kernel_launch(void* const* d_in, const int* in_sizes, int n_in,
                              void* d_out, int out_size)
{
    const float* rating    = (const float*)d_in[0];
    const int*   items_idx = (const int*)  d_in[1];
    const float* gram      = (const float*)d_in[2];
    const float* W1        = (const float*)d_in[3];
    const float* b1        = (const float*)d_in[4];
    const float* W2        = (const float*)d_in[5];
    const float* b2        = (const float*)d_in[6];
    const float* items     = (const float*)d_in[7];

    float* out    = (float*)d_out;
    float* z_out  = out + Z_OFF;
    float* no_out = out + NO_OFF;
    float* kl_out = out + KL_OFF;
    float* x_out  = out + X_OFF;

    float* enc; double* klp;
    HF *xh, *w1h, *w1l, *hh, *w2h, *w2l, *znh, *ith, *itl;
    cudaGetSymbolAddress((void**)&enc, g_enc);
    cudaGetSymbolAddress((void**)&klp, g_kl);
    cudaGetSymbolAddress((void**)&xh,  g_xh);
    cudaGetSymbolAddress((void**)&w1h, g_w1h);
    cudaGetSymbolAddress((void**)&w1l, g_w1l);
    cudaGetSymbolAddress((void**)&hh,  g_hh);
    cudaGetSymbolAddress((void**)&w2h, g_w2h);
    cudaGetSymbolAddress((void**)&w2l, g_w2l);
    cudaGetSymbolAddress((void**)&znh, g_znh);
    cudaGetSymbolAddress((void**)&ith, g_ith);
    cudaGetSymbolAddress((void**)&itl, g_itl);

    cudaFuncSetAttribute(gemm1_mma, cudaFuncAttributeMaxDynamicSharedMemorySize, SMEM1);
    cudaFuncSetAttribute(gemm2_mma, cudaFuncAttributeMaxDynamicSharedMemorySize, SMEM2);
    cudaFuncSetAttribute(sim_mma,   cudaFuncAttributeMaxDynamicSharedMemorySize, SMEM2);

    zero_kl_kernel<<<1, 1>>>(klp);
    items_norm_kernel<<<(NPAD2 * 32 + 255) / 256, 256>>>(items, ith, itl);
    convW1_kernel<<<dim3(KPAD1 / 32, NPAD1 / 32), dim3(32, 8)>>>(W1, w1h, w1l);
    convW2_kernel<<<dim3(HPADK / 32, NPADW / 32), dim3(32, 8)>>>(W2, w2h, w2l);
    x_kernel<<<ROWS, 512>>>(rating, items_idx, gram, x_out, xh);
    // h = tanh(x @ W1 + b1): fp16 dual-acc HMMA, N-tile 160, single wave (128 CTAs)
    gemm1_mma<<<dim3(NPAD1 / 160, ROWS / 128), 256, SMEM1>>>(xh, w1h, w1l, b1, hh);
    // enc = h @ W2 + b2 (128 CTAs, single wave)
    gemm2_mma<<<dim3(NPADW / 128, ROWS / 128), 256, SMEM2>>>(hh, w2h, w2l, b2, enc);
    postenc_kernel<<<(ROWS * 32 + 255) / 256, 256>>>(enc, z_out, znh, klp);
    fin_kl_kernel<<<1, 1>>>(klp, kl_out);
    // new_output: fp16 dual-acc HMMA with fused exp/mean/log epilogue
    sim_mma<<<dim3(NPAD2 / 128, ROWS / 128), 256, SMEM2>>>(znh, ith, itl, no_out);
}

// round 11
// speedup vs baseline: 6.6180x; 1.3262x over previous
#include <cuda_runtime.h>
#include <cuda_fp16.h>
#include <math.h>
#include <stdint.h>

#define Bn   128
#define Kn   32
#define In   12000
#define Hn   600
#define LATn 200
#define ROWS (Bn*Kn)      // 4096
#define ENCn (2*LATn)     // 400

#define KPAD1 12032       // In padded to 64
#define NPAD1 640         // Hn padded to 160
#define KPAD2 224         // LATn padded (7 x 32-chunks)
#define NPAD2 12032       // In padded to 128
#define HPADK 608         // Hn padded to 32  (K of gemm2)
#define NPADW 512         // ENCn padded to 128 (N of gemm2)

#define Z_OFF  0
#define NO_OFF (ROWS*LATn)                 // 819200
#define KL_OFF (NO_OFF + Bn*In)            // 2355200
#define X_OFF  (KL_OFF + 1)                // 2355201

#define LO_SCALE   512.0f
#define LO_INV     (1.0f/512.0f)

typedef __half HF;

// ---------------- scratch (no allocation allowed) ----------------
__device__ float  g_enc[ROWS*ENCn];
__device__ double g_klp[512];
__device__ HF g_xh [(size_t)ROWS*KPAD1];
__device__ HF g_w1h[(size_t)NPAD1*KPAD1];
__device__ HF g_hh [(size_t)ROWS*HPADK];
__device__ HF g_w2h[(size_t)NPADW*HPADK];
__device__ HF g_w2l[(size_t)NPADW*HPADK];    // lo * 512
__device__ HF g_znh[(size_t)ROWS*KPAD2];
__device__ HF g_ith[(size_t)NPAD2*KPAD2];
__device__ HF g_itl[(size_t)NPAD2*KPAD2];    // lo * 512

// ==================== helpers ====================
__device__ __forceinline__ uint32_t smem_u32(const void* p) {
    uint32_t a;
    asm("{ .reg .u64 t; cvta.to.shared.u64 t, %1; cvt.u32.u64 %0, t; }" : "=r"(a) : "l"(p));
    return a;
}
#define CP16(dst, src) asm volatile("cp.async.cg.shared.global [%0], [%1], 16;" :: "r"(dst), "l"(src) : "memory")
#define CP_COMMIT()    asm volatile("cp.async.commit_group;" ::: "memory")
#define CP_WAIT1()     asm volatile("cp.async.wait_group 1;" ::: "memory")
#define CP_WAIT0()     asm volatile("cp.async.wait_group 0;" ::: "memory")

__device__ __forceinline__ void ldsm4(uint32_t r[4], uint32_t addr) {
    asm volatile("ldmatrix.sync.aligned.m8n8.x4.shared.b16 {%0,%1,%2,%3}, [%4];"
        : "=r"(r[0]), "=r"(r[1]), "=r"(r[2]), "=r"(r[3]) : "r"(addr));
}
__device__ __forceinline__ void mma16816h(float d[4], const uint32_t a[4], uint32_t b0, uint32_t b1) {
    asm volatile("mma.sync.aligned.m16n8k16.row.col.f32.f16.f16.f32 "
        "{%0,%1,%2,%3}, {%4,%5,%6,%7}, {%8,%9}, {%0,%1,%2,%3};"
        : "+f"(d[0]), "+f"(d[1]), "+f"(d[2]), "+f"(d[3])
        : "r"(a[0]), "r"(a[1]), "r"(a[2]), "r"(a[3]), "r"(b0), "r"(b1));
}
__device__ __forceinline__ void split_hf(float v, HF& hi, HF& lo) {
    hi = __float2half(v);
    lo = __float2half((v - __half2float(hi)) * LO_SCALE);
}

#define NSTAGE 3

// ---------------- fp16 mma mainloop (1- or 2-term) ----------------
// A: 128 rows (hi only). B: BR rows, hi (+ lo*512 when TERMS==2).
// accM += Ah*Bh ; (TERMS==2) accC += Ah*Bl.  Final = accM + accC/512.
// K chunk = 32 elems (64 B/row). 3-stage cp.async pipeline. Smem row stride 80 B.
template<int BR, int TERMS>
__device__ __forceinline__ void mma_mainloop2(float (&accM)[2][BR/16][4], float (&accC)[2][BR/16][4],
    const HF* __restrict__ Ah, const HF* __restrict__ Bh, const HF* __restrict__ Bl,
    long m0, long n0, int kpad, int nch, uint32_t smem_base)
{
    constexpr int OFF_B  = 10240;            // A hi = 128*80
    constexpr int STAGE  = 10240 + TERMS * BR * 80;
    constexpr int NP = BR / 32;

    const int tid = threadIdx.x, lane = tid & 31, wid = tid >> 5;
    const int wm = wid & 3, wn = wid >> 2;
    const long rowb = (long)kpad * 2;

    const char* bA  = (const char*)(Ah + m0 * (long)kpad);
    const char* bBh = (const char*)(Bh + n0 * (long)kpad);
    const char* bBl = (const char*)(Bl + n0 * (long)kpad);

    const int rA = tid >> 2, ccA = (tid & 3) * 16;

    auto issue = [&](int c) {
        uint32_t st = smem_base + (c % NSTAGE) * STAGE;
        long go = (long)c * 64;
        CP16(st + rA * 80 + ccA,        bA + rA * rowb + ccA + go);
        CP16(st + (rA + 64) * 80 + ccA, bA + (rA + 64) * rowb + ccA + go);
        #pragma unroll
        for (int i = 0; i < (BR * 4 + 255) / 256; i++) {
            int idx = tid + i * 256;
            if ((BR * 4) % 256 == 0 || idx < BR * 4) {
                int r = idx >> 2, cc = (idx & 3) * 16;
                CP16(st + OFF_B + r * 80 + cc, bBh + r * rowb + cc + go);
                if (TERMS == 2)
                    CP16(st + OFF_B + BR * 80 + r * 80 + cc, bBl + r * rowb + cc + go);
            }
        }
        CP_COMMIT();
    };

    issue(0);
    if (nch > 1) issue(1);

    for (int c = 0; c < nch; c++) {
        if (c + 1 < nch) CP_WAIT1(); else CP_WAIT0();
        __syncthreads();

        uint32_t sA = smem_base + (c % NSTAGE) * STAGE;
        #pragma unroll
        for (int s = 0; s < 2; s++) {
            uint32_t ah[2][4];
            #pragma unroll
            for (int t = 0; t < 2; t++) {
                uint32_t row = wm * 32 + t * 16 + (lane & 15);
                uint32_t ad = sA + row * 80 + s * 32 + ((lane >> 4) & 1) * 16;
                ldsm4(ah[t], ad);
            }
            #pragma unroll
            for (int p = 0; p < NP; p++) {
                uint32_t bh[4], bl[4];
                uint32_t row = wn * (BR / 2) + p * 16 + (lane & 7) + ((lane & 16) ? 8 : 0);
                uint32_t ad = sA + OFF_B + row * 80 + s * 32 + ((lane & 8) ? 16 : 0);
                ldsm4(bh, ad);
                if (TERMS == 2) ldsm4(bl, ad + BR * 80);
                #pragma unroll
                for (int t = 0; t < 2; t++)
                    #pragma unroll
                    for (int hh = 0; hh < 2; hh++) {
                        int j = p * 2 + hh;
                        mma16816h(accM[t][j], ah[t], bh[hh * 2], bh[hh * 2 + 1]);
                        if (TERMS == 2)
                            mma16816h(accC[t][j], ah[t], bl[hh * 2], bl[hh * 2 + 1]);
                    }
            }
        }
        if (c + 2 < nch) issue(c + 2);
    }
}

#define SMEM1 (NSTAGE*(10240 + 160*80))      // gemm1 (1-term): 69120
#define SMEM2 (NSTAGE*(10240 + 2*128*80))    // gemm2 / sim (2-term): 92160

// ---------------- GEMM1: h = tanh(x @ W1 + b1), 1-term fp16, N-tile 160 ----------------
__global__ void __launch_bounds__(256) gemm1_mma(const HF* __restrict__ Ah,
                                                 const HF* __restrict__ Bh,
                                                 const float* __restrict__ bias,
                                                 HF* __restrict__ Hh)
{
    extern __shared__ char smem[];
    float accM[2][10][4];
    #pragma unroll
    for (int t = 0; t < 2; t++)
        #pragma unroll
        for (int j = 0; j < 10; j++)
            #pragma unroll
            for (int v = 0; v < 4; v++) accM[t][j][v] = 0.f;

    long m0 = (long)blockIdx.y * 128, n0 = (long)blockIdx.x * 160;
    mma_mainloop2<160, 1>(accM, accM, Ah, Bh, Bh, m0, n0, KPAD1, KPAD1 / 32, smem_u32(smem));

    const int tid = threadIdx.x, lane = tid & 31, wid = tid >> 5;
    const int wm = wid & 3, wn = wid >> 2;
    const int rr = lane >> 2, q = lane & 3;
    #pragma unroll
    for (int t = 0; t < 2; t++) {
        long m = m0 + wm * 32 + t * 16 + rr;
        #pragma unroll
        for (int j = 0; j < 10; j++) {
            int n = (int)n0 + wn * 80 + j * 8 + 2 * q;
            #pragma unroll
            for (int e = 0; e < 2; e++) {
                int nn = n + e;
                if (nn < HPADK) {
                    float v0 = (nn < Hn) ? tanhf(accM[t][j][e]     + bias[nn]) : 0.f;
                    float v1 = (nn < Hn) ? tanhf(accM[t][j][e + 2] + bias[nn]) : 0.f;
                    Hh[m * HPADK + nn]       = __float2half(v0);
                    Hh[(m + 8) * HPADK + nn] = __float2half(v1);
                }
            }
        }
    }
}

// ---------------- GEMM2: enc = h @ W2 + b2 (fp32 out), 2-term ----------------
__global__ void __launch_bounds__(256) gemm2_mma(const HF* __restrict__ Ah,
                                                 const HF* __restrict__ Bh, const HF* __restrict__ Bl,
                                                 const float* __restrict__ bias, float* __restrict__ E)
{
    extern __shared__ char smem[];
    float accM[2][8][4], accC[2][8][4];
    #pragma unroll
    for (int t = 0; t < 2; t++)
        #pragma unroll
        for (int j = 0; j < 8; j++)
            #pragma unroll
            for (int v = 0; v < 4; v++) { accM[t][j][v] = 0.f; accC[t][j][v] = 0.f; }

    long m0 = (long)blockIdx.y * 128, n0 = (long)blockIdx.x * 128;
    mma_mainloop2<128, 2>(accM, accC, Ah, Bh, Bl, m0, n0, HPADK, HPADK / 32, smem_u32(smem));

    const int tid = threadIdx.x, lane = tid & 31, wid = tid >> 5;
    const int wm = wid & 3, wn = wid >> 2;
    const int rr = lane >> 2, q = lane & 3;
    #pragma unroll
    for (int t = 0; t < 2; t++) {
        long m = m0 + wm * 32 + t * 16 + rr;
        #pragma unroll
        for (int j = 0; j < 8; j++) {
            int n = (int)n0 + wn * 64 + j * 8 + 2 * q;
            #pragma unroll
            for (int e = 0; e < 2; e++) {
                int nn = n + e;
                if (nn < ENCn) {
                    E[m * ENCn + nn]       = accM[t][j][e]     + accC[t][j][e]     * LO_INV + bias[nn];
                    E[(m + 8) * ENCn + nn] = accM[t][j][e + 2] + accC[t][j][e + 2] * LO_INV + bias[nn];
                }
            }
        }
    }
}

// ---------------- sim: new_output = log(mean_k exp(zn @ itn^T / tau) + 1), 2-term ----------------
__global__ void __launch_bounds__(256) sim_mma(const HF* __restrict__ Ah,
                                               const HF* __restrict__ Bh, const HF* __restrict__ Bl,
                                               float* __restrict__ no_out)
{
    extern __shared__ char smem[];
    float accM[2][8][4], accC[2][8][4];
    #pragma unroll
    for (int t = 0; t < 2; t++)
        #pragma unroll
        for (int j = 0; j < 8; j++)
            #pragma unroll
            for (int v = 0; v < 4; v++) { accM[t][j][v] = 0.f; accC[t][j][v] = 0.f; }

    long m0 = (long)blockIdx.y * 128, n0 = (long)blockIdx.x * 128;
    mma_mainloop2<128, 2>(accM, accC, Ah, Bh, Bl, m0, n0, KPAD2, KPAD2 / 32, smem_u32(smem));

    const int tid = threadIdx.x, lane = tid & 31, wid = tid >> 5;
    const int wm = wid & 3, wn = wid >> 2;
    const int q = lane & 3;
    long b = blockIdx.y * 4 + wm;     // user; warp's 32 m-rows = this user's 32 K rows
    #pragma unroll
    for (int j = 0; j < 8; j++) {
        float s0 = __expf(10.0f * (accM[0][j][0] + accC[0][j][0] * LO_INV))
                 + __expf(10.0f * (accM[0][j][2] + accC[0][j][2] * LO_INV))
                 + __expf(10.0f * (accM[1][j][0] + accC[1][j][0] * LO_INV))
                 + __expf(10.0f * (accM[1][j][2] + accC[1][j][2] * LO_INV));
        float s1 = __expf(10.0f * (accM[0][j][1] + accC[0][j][1] * LO_INV))
                 + __expf(10.0f * (accM[0][j][3] + accC[0][j][3] * LO_INV))
                 + __expf(10.0f * (accM[1][j][1] + accC[1][j][1] * LO_INV))
                 + __expf(10.0f * (accM[1][j][3] + accC[1][j][3] * LO_INV));
        #pragma unroll
        for (int off = 4; off < 32; off <<= 1) {
            s0 += __shfl_xor_sync(0xffffffffu, s0, off);
            s1 += __shfl_xor_sync(0xffffffffu, s1, off);
        }
        if (lane < 4) {
            int n = (int)n0 + wn * 64 + j * 8 + 2 * q;
            if (n < In)     no_out[b * In + n]     = logf(s0 * (1.0f / 32.0f) + 1.0f);
            if (n + 1 < In) no_out[b * In + n + 1] = logf(s1 * (1.0f / 32.0f) + 1.0f);
        }
    }
}

// ---------------- fused prep: x | convW1(hi) | convW2(hi+lo) | items_norm ----------------
#define X_BLKS  ROWS                       // 4096
#define W1_KT   (KPAD1/32)                 // 376
#define W1_BLKS (W1_KT*(NPAD1/32))         // 7520
#define W2_KT   (HPADK/32)                 // 19
#define W2_BLKS (W2_KT*(NPADW/32))         // 304
#define IT_BLKS (NPAD2/16)                 // 752
#define PREP_GRID (X_BLKS + W1_BLKS + W2_BLKS + IT_BLKS)

__global__ void __launch_bounds__(512) prep_kernel(
    const float* __restrict__ rating, const int* __restrict__ items_idx,
    const float* __restrict__ gram,   const float* __restrict__ W1,
    const float* __restrict__ W2,     const float* __restrict__ items,
    float* __restrict__ x_out, HF* __restrict__ xh,
    HF* __restrict__ w1h, HF* __restrict__ w2h, HF* __restrict__ w2l,
    HF* __restrict__ ith, HF* __restrict__ itl)
{
    __shared__ float sbuf[12032];
    const int tid = threadIdx.x;
    int blk = blockIdx.x;

    if (blk < X_BLKS) {
        // ---- x = masked gram row / l2norm ----
        int bk = blk, b = bk >> 5;
        int row = items_idx[bk];
        const float4* r4 = (const float4*)(rating + (long)b * In);
        const float4* g4 = (const float4*)(gram + (long)row * In);
        float ss = 0.f;
        for (int i = tid; i < In / 4; i += 512) {
            float4 rv = r4[i];
            float4 gv = g4[i];
            float4 m;
            m.x = (rv.x > 0.f) ? gv.x : 0.f;
            m.y = (rv.y > 0.f) ? gv.y : 0.f;
            m.z = (rv.z > 0.f) ? gv.z : 0.f;
            m.w = (rv.w > 0.f) ? gv.w : 0.f;
            ss += m.x * m.x + m.y * m.y + m.z * m.z + m.w * m.w;
            *(float4*)&sbuf[i * 4] = m;
        }
        __shared__ float red[16];
        #pragma unroll
        for (int o = 16; o; o >>= 1) ss += __shfl_xor_sync(0xffffffffu, ss, o);
        if ((tid & 31) == 0) red[tid >> 5] = ss;
        __syncthreads();
        if (tid < 16) {
            float t = red[tid];
            #pragma unroll
            for (int o = 8; o; o >>= 1) t += __shfl_xor_sync(0xffffu, t, o);
            if (tid == 0) red[0] = t;
        }
        __syncthreads();
        float inv = 1.0f / fmaxf(sqrtf(red[0]), 1e-12f);
        float* dst = x_out + (long)bk * In;   // 4B-aligned only
        for (int i = tid; i < In; i += 512) dst[i] = sbuf[i] * inv;
        uint32_t* dh = (uint32_t*)(xh + (size_t)bk * KPAD1);
        for (int i = tid; i < KPAD1 / 2; i += 512) {
            int i0 = 2 * i;
            float v0 = (i0     < In) ? sbuf[i0]     * inv : 0.f;
            float v1 = (i0 + 1 < In) ? sbuf[i0 + 1] * inv : 0.f;
            __half2 hp;
            hp.x = __float2half(v0);
            hp.y = __float2half(v1);
            dh[i] = *(uint32_t*)&hp;
        }
    } else if (blk < X_BLKS + W1_BLKS) {
        // ---- W1 [In,Hn] -> W1^T hi fp16 [NPAD1][KPAD1] ----
        int i = blk - X_BLKS;
        int kb = (i % W1_KT) * 32, nb = (i / W1_KT) * 32;
        int tx = tid & 31, ty = tid >> 5;    // 16 rows
        float (*t)[33] = (float(*)[33])sbuf;
        for (int j = ty; j < 32; j += 16) {
            int k = kb + j, n = nb + tx;
            t[j][tx] = (k < In && n < Hn) ? W1[(long)k * Hn + n] : 0.f;
        }
        __syncthreads();
        for (int j = ty; j < 32; j += 16) {
            int n = nb + j, k = kb + tx;
            w1h[(size_t)n * KPAD1 + k] = __float2half(t[tx][j]);
        }
    } else if (blk < X_BLKS + W1_BLKS + W2_BLKS) {
        // ---- W2 [Hn,ENCn] -> W2^T hi/lo*512 fp16 [NPADW][HPADK] ----
        int i = blk - X_BLKS - W1_BLKS;
        int kb = (i % W2_KT) * 32, nb = (i / W2_KT) * 32;
        int tx = tid & 31, ty = tid >> 5;
        float (*t)[33] = (float(*)[33])sbuf;
        for (int j = ty; j < 32; j += 16) {
            int k = kb + j, n = nb + tx;
            t[j][tx] = (k < Hn && n < ENCn) ? W2[(long)k * ENCn + n] : 0.f;
        }
        __syncthreads();
        for (int j = ty; j < 32; j += 16) {
            int n = nb + j, k = kb + tx;
            HF h, l;
            split_hf(t[tx][j], h, l);
            w2h[(size_t)n * HPADK + k] = h;
            w2l[(size_t)n * HPADK + k] = l;
        }
    } else {
        // ---- items l2-normalize -> fp16 hi/lo*512, [NPAD2][KPAD2] ----
        int i = blk - X_BLKS - W1_BLKS - W2_BLKS;
        int warp = i * 16 + (tid >> 5);
        int lane = tid & 31;
        if (warp >= NPAD2) return;
        HF* dh = ith + (size_t)warp * KPAD2;
        HF* dl = itl + (size_t)warp * KPAD2;
        if (warp >= In) {
            for (int j = lane; j < KPAD2; j += 32) { dh[j] = __float2half(0.f); dl[j] = __float2half(0.f); }
            return;
        }
        const float* src = items + (long)warp * LATn;
        float v[7];
        float ss = 0.f;
        int cnt = 0;
        for (int j = lane; j < LATn; j += 32) { float t = src[j]; v[cnt++] = t; ss += t * t; }
        #pragma unroll
        for (int o = 16; o; o >>= 1) ss += __shfl_xor_sync(0xffffffffu, ss, o);
        float inv = 1.0f / fmaxf(sqrtf(ss), 1e-12f);
        cnt = 0;
        for (int j = lane; j < KPAD2; j += 32) {
            float t = (j < LATn) ? v[cnt++] * inv : 0.f;
            HF h, l;
            split_hf(t, h, l);
            dh[j] = h;
            dl[j] = l;
        }
    }
}

// ---------------- enc postprocess: z, zn-hi(fp16), kl partial per block ----------------
__global__ void postenc_kernel(const float* __restrict__ enc, float* __restrict__ z_out,
                               HF* __restrict__ znh, double* __restrict__ klp)
{
    __shared__ float kred[8];
    int wib  = threadIdx.x >> 5;                      // warp in block (8)
    int warp = blockIdx.x * 8 + wib;                  // global row
    int lane = threadIdx.x & 31;
    const float* e = enc + (long)warp * ENCn;
    float mv[7];
    float ss = 0.f, kl = 0.f;
    int cnt = 0;
    for (int j = lane; j < LATn; j += 32) {
        float m  = e[j];
        float lv = e[j + LATn];
        mv[cnt++] = m;
        ss += m * m;
        kl += m * m + (expm1f(lv) - lv);
    }
    #pragma unroll
    for (int o = 16; o; o >>= 1) {
        ss += __shfl_xor_sync(0xffffffffu, ss, o);
        kl += __shfl_xor_sync(0xffffffffu, kl, o);
    }
    float inv = 1.0f / fmaxf(sqrtf(ss), 1e-12f);
    cnt = 0;
    for (int j = lane; j < KPAD2; j += 32) {
        float t = 0.f;
        if (j < LATn) {
            z_out[(long)warp * LATn + j] = mv[cnt];
            t = mv[cnt++] * inv;
        }
        znh[(size_t)warp * KPAD2 + j] = __float2half(t);
    }
    if (lane == 0) kred[wib] = kl;
    __syncthreads();
    if (threadIdx.x < 8) {
        float t = kred[threadIdx.x];
        #pragma unroll
        for (int o = 4; o; o >>= 1) t += __shfl_xor_sync(0xffu, t, o);
        if (threadIdx.x == 0) klp[blockIdx.x] = (double)t;
    }
}

__global__ void fin_kl_kernel(const double* __restrict__ klp, float* __restrict__ out)
{
    __shared__ double red[8];
    int tid = threadIdx.x;             // 256
    double s = klp[tid] + klp[tid + 256];
    #pragma unroll
    for (int o = 16; o; o >>= 1) s += __shfl_xor_sync(0xffffffffu, s, o);
    if ((tid & 31) == 0) red[tid >> 5] = s;
    __syncthreads();
    if (tid < 8) {
        double t = red[tid];
        #pragma unroll
        for (int o = 4; o; o >>= 1) t += __shfl_xor_sync(0xffu, t, o);
        if (tid == 0) *out = (float)(0.5 * t / (double)ROWS);
    }
}

// ---------------- launch ----------------
extern "C" void kernel_launch(void* const* d_in, const int* in_sizes, int n_in,
                              void* d_out, int out_size)
{
    const float* rating    = (const float*)d_in[0];
    const int*   items_idx = (const int*)  d_in[1];
    const float* gram      = (const float*)d_in[2];
    const float* W1        = (const float*)d_in[3];
    const float* b1        = (const float*)d_in[4];
    const float* W2        = (const float*)d_in[5];
    const float* b2        = (const float*)d_in[6];
    const float* items     = (const float*)d_in[7];

    float* out    = (float*)d_out;
    float* z_out  = out + Z_OFF;
    float* no_out = out + NO_OFF;
    float* kl_out = out + KL_OFF;
    float* x_out  = out + X_OFF;

    float* enc; double* klp;
    HF *xh, *w1h, *hh, *w2h, *w2l, *znh, *ith, *itl;
    cudaGetSymbolAddress((void**)&enc, g_enc);
    cudaGetSymbolAddress((void**)&klp, g_klp);
    cudaGetSymbolAddress((void**)&xh,  g_xh);
    cudaGetSymbolAddress((void**)&w1h, g_w1h);
    cudaGetSymbolAddress((void**)&hh,  g_hh);
    cudaGetSymbolAddress((void**)&w2h, g_w2h);
    cudaGetSymbolAddress((void**)&w2l, g_w2l);
    cudaGetSymbolAddress((void**)&znh, g_znh);
    cudaGetSymbolAddress((void**)&ith, g_ith);
    cudaGetSymbolAddress((void**)&itl, g_itl);

    cudaFuncSetAttribute(gemm1_mma, cudaFuncAttributeMaxDynamicSharedMemorySize, SMEM1);
    cudaFuncSetAttribute(gemm2_mma, cudaFuncAttributeMaxDynamicSharedMemorySize, SMEM2);
    cudaFuncSetAttribute(sim_mma,   cudaFuncAttributeMaxDynamicSharedMemorySize, SMEM2);

    // fused prep: x + W1^T(hi) + W2^T(hi/lo) + items norm
    prep_kernel<<<PREP_GRID, 512>>>(rating, items_idx, gram, W1, W2, items,
                                    x_out, xh, w1h, w2h, w2l, ith, itl);
    // h = tanh(x @ W1 + b1): 1-term fp16 HMMA, N-tile 160, single wave (128 CTAs)
    gemm1_mma<<<dim3(NPAD1 / 160, ROWS / 128), 256, SMEM1>>>(xh, w1h, b1, hh);
    // enc = h @ W2 + b2: 2-term (128 CTAs)
    gemm2_mma<<<dim3(NPADW / 128, ROWS / 128), 256, SMEM2>>>(hh, w2h, w2l, b2, enc);
    postenc_kernel<<<ROWS / 8, 256>>>(enc, z_out, znh, klp);
    fin_kl_kernel<<<1, 256>>>(klp, kl_out);
    // new_output: 2-term fp16 HMMA with fused exp/mean/log epilogue
    sim_mma<<<dim3(NPAD2 / 128, ROWS / 128), 256, SMEM2>>>(znh, ith, itl, no_out);
}

// round 12
// speedup vs baseline: 7.3933x; 1.1171x over previous
#include <cuda_runtime.h>
#include <cuda_fp16.h>
#include <math.h>
#include <stdint.h>

#define Bn   128
#define Kn   32
#define In   12000
#define Hn   600
#define LATn 200
#define ROWS (Bn*Kn)      // 4096
#define ENCn (2*LATn)     // 400

#define KPAD1 12032       // In padded to 64 (188 x 64-chunks)
#define NPAD1 640         // Hn padded to 160
#define KPAD2 224         // LATn padded (7 x 32-chunks)
#define NPAD2 12032       // In padded to 128
#define HPADK 608         // Hn padded to 32  (K of gemm2)
#define NPADW 512         // ENCn padded to 128 (N of gemm2)

#define Z_OFF  0
#define NO_OFF (ROWS*LATn)                 // 819200
#define KL_OFF (NO_OFF + Bn*In)            // 2355200
#define X_OFF  (KL_OFF + 1)                // 2355201

#define LO_SCALE   512.0f
#define LO_INV     (1.0f/512.0f)

typedef __half HF;

// ---------------- scratch (no allocation allowed) ----------------
__device__ float  g_enc[ROWS*ENCn];
__device__ double g_klp[512];
__device__ HF g_xh [(size_t)ROWS*KPAD1];
__device__ HF g_w1h[(size_t)NPAD1*KPAD1];
__device__ HF g_hh [(size_t)ROWS*HPADK];
__device__ HF g_w2h[(size_t)NPADW*HPADK];
__device__ HF g_w2l[(size_t)NPADW*HPADK];    // lo * 512
__device__ HF g_znh[(size_t)ROWS*KPAD2];
__device__ HF g_ith[(size_t)NPAD2*KPAD2];
__device__ HF g_itl[(size_t)NPAD2*KPAD2];    // lo * 512

// ==================== helpers ====================
__device__ __forceinline__ uint32_t smem_u32(const void* p) {
    uint32_t a;
    asm("{ .reg .u64 t; cvta.to.shared.u64 t, %1; cvt.u32.u64 %0, t; }" : "=r"(a) : "l"(p));
    return a;
}
#define CP16(dst, src) asm volatile("cp.async.cg.shared.global [%0], [%1], 16;" :: "r"(dst), "l"(src) : "memory")
#define CP_COMMIT()    asm volatile("cp.async.commit_group;" ::: "memory")
#define CP_WAIT1()     asm volatile("cp.async.wait_group 1;" ::: "memory")
#define CP_WAIT0()     asm volatile("cp.async.wait_group 0;" ::: "memory")

__device__ __forceinline__ void ldsm4(uint32_t r[4], uint32_t addr) {
    asm volatile("ldmatrix.sync.aligned.m8n8.x4.shared.b16 {%0,%1,%2,%3}, [%4];"
        : "=r"(r[0]), "=r"(r[1]), "=r"(r[2]), "=r"(r[3]) : "r"(addr));
}
__device__ __forceinline__ void mma16816h(float d[4], const uint32_t a[4], uint32_t b0, uint32_t b1) {
    asm volatile("mma.sync.aligned.m16n8k16.row.col.f32.f16.f16.f32 "
        "{%0,%1,%2,%3}, {%4,%5,%6,%7}, {%8,%9}, {%0,%1,%2,%3};"
        : "+f"(d[0]), "+f"(d[1]), "+f"(d[2]), "+f"(d[3])
        : "r"(a[0]), "r"(a[1]), "r"(a[2]), "r"(a[3]), "r"(b0), "r"(b1));
}
__device__ __forceinline__ void split_hf(float v, HF& hi, HF& lo) {
    hi = __float2half(v);
    lo = __float2half((v - __half2float(hi)) * LO_SCALE);
}

#define NSTAGE 3

// ================ gemm1 mainloop: 1-term fp16, K-chunk 64, row stride 144 ================
// A 128 rows, B 160 rows. Warp grid 4m x 2n; warp tile 32 x 80.
#define G1_ROWB  144
#define G1_OFF_B (128*G1_ROWB)                     // 18432
#define G1_STAGE (G1_OFF_B + 160*G1_ROWB)          // 41472
#define SMEM1    (NSTAGE*G1_STAGE)                 // 124416

__device__ __forceinline__ void mma_mainloop_g1(float (&acc)[2][10][4],
    const HF* __restrict__ Ah, const HF* __restrict__ Bh,
    long m0, long n0, uint32_t smem_base)
{
    const int tid = threadIdx.x, lane = tid & 31, wid = tid >> 5;
    const int wm = wid & 3, wn = wid >> 2;
    const long rowb = (long)KPAD1 * 2;
    const int nch = KPAD1 / 64;                    // 188

    const char* bA = (const char*)(Ah + m0 * (long)KPAD1);
    const char* bB = (const char*)(Bh + n0 * (long)KPAD1);

    auto issue = [&](int c) {
        uint32_t st = smem_base + (c % NSTAGE) * G1_STAGE;
        long go = (long)c * 128;
        #pragma unroll
        for (int i = 0; i < 4; i++) {              // A: 1024 16B units
            int idx = tid + i * 256;
            int r = idx >> 3, cc = (idx & 7) * 16;
            CP16(st + r * G1_ROWB + cc, bA + r * rowb + cc + go);
        }
        #pragma unroll
        for (int i = 0; i < 5; i++) {              // B: 1280 16B units
            int idx = tid + i * 256;
            int r = idx >> 3, cc = (idx & 7) * 16;
            CP16(st + G1_OFF_B + r * G1_ROWB + cc, bB + r * rowb + cc + go);
        }
        CP_COMMIT();
    };

    issue(0);
    issue(1);

    for (int c = 0; c < nch; c++) {
        if (c + 1 < nch) CP_WAIT1(); else CP_WAIT0();
        __syncthreads();

        uint32_t sA = smem_base + (c % NSTAGE) * G1_STAGE;
        #pragma unroll
        for (int s = 0; s < 4; s++) {
            uint32_t ah[2][4];
            #pragma unroll
            for (int t = 0; t < 2; t++) {
                uint32_t row = wm * 32 + t * 16 + (lane & 15);
                ldsm4(ah[t], sA + row * G1_ROWB + s * 32 + ((lane >> 4) & 1) * 16);
            }
            #pragma unroll
            for (int p = 0; p < 5; p++) {
                uint32_t bh[4];
                uint32_t row = wn * 80 + p * 16 + (lane & 7) + ((lane & 16) ? 8 : 0);
                ldsm4(bh, sA + G1_OFF_B + row * G1_ROWB + s * 32 + ((lane & 8) ? 16 : 0));
                #pragma unroll
                for (int t = 0; t < 2; t++)
                    #pragma unroll
                    for (int hh = 0; hh < 2; hh++)
                        mma16816h(acc[t][p * 2 + hh], ah[t], bh[hh * 2], bh[hh * 2 + 1]);
            }
        }
        if (c + 2 < nch) issue(c + 2);
    }
}

// ================ generic 2-term mainloop (gemm2 / sim), K-chunk 32, stride 80 ================
template<int BR>
__device__ __forceinline__ void mma_mainloop2(float (&accM)[2][BR/16][4], float (&accC)[2][BR/16][4],
    const HF* __restrict__ Ah, const HF* __restrict__ Bh, const HF* __restrict__ Bl,
    long m0, long n0, int kpad, int nch, uint32_t smem_base)
{
    constexpr int OFF_B  = 10240;            // A hi = 128*80
    constexpr int STAGE  = 10240 + 2 * BR * 80;
    constexpr int NP = BR / 32;

    const int tid = threadIdx.x, lane = tid & 31, wid = tid >> 5;
    const int wm = wid & 3, wn = wid >> 2;
    const long rowb = (long)kpad * 2;

    const char* bA  = (const char*)(Ah + m0 * (long)kpad);
    const char* bBh = (const char*)(Bh + n0 * (long)kpad);
    const char* bBl = (const char*)(Bl + n0 * (long)kpad);

    const int rA = tid >> 2, ccA = (tid & 3) * 16;

    auto issue = [&](int c) {
        uint32_t st = smem_base + (c % NSTAGE) * STAGE;
        long go = (long)c * 64;
        CP16(st + rA * 80 + ccA,        bA + rA * rowb + ccA + go);
        CP16(st + (rA + 64) * 80 + ccA, bA + (rA + 64) * rowb + ccA + go);
        #pragma unroll
        for (int i = 0; i < (BR * 4 + 255) / 256; i++) {
            int idx = tid + i * 256;
            if ((BR * 4) % 256 == 0 || idx < BR * 4) {
                int r = idx >> 2, cc = (idx & 3) * 16;
                CP16(st + OFF_B + r * 80 + cc,           bBh + r * rowb + cc + go);
                CP16(st + OFF_B + BR * 80 + r * 80 + cc, bBl + r * rowb + cc + go);
            }
        }
        CP_COMMIT();
    };

    issue(0);
    if (nch > 1) issue(1);

    for (int c = 0; c < nch; c++) {
        if (c + 1 < nch) CP_WAIT1(); else CP_WAIT0();
        __syncthreads();

        uint32_t sA = smem_base + (c % NSTAGE) * STAGE;
        #pragma unroll
        for (int s = 0; s < 2; s++) {
            uint32_t ah[2][4];
            #pragma unroll
            for (int t = 0; t < 2; t++) {
                uint32_t row = wm * 32 + t * 16 + (lane & 15);
                ldsm4(ah[t], sA + row * 80 + s * 32 + ((lane >> 4) & 1) * 16);
            }
            #pragma unroll
            for (int p = 0; p < NP; p++) {
                uint32_t bh[4], bl[4];
                uint32_t row = wn * (BR / 2) + p * 16 + (lane & 7) + ((lane & 16) ? 8 : 0);
                uint32_t ad = sA + OFF_B + row * 80 + s * 32 + ((lane & 8) ? 16 : 0);
                ldsm4(bh, ad);
                ldsm4(bl, ad + BR * 80);
                #pragma unroll
                for (int t = 0; t < 2; t++)
                    #pragma unroll
                    for (int hh = 0; hh < 2; hh++) {
                        int j = p * 2 + hh;
                        mma16816h(accM[t][j], ah[t], bh[hh * 2], bh[hh * 2 + 1]);
                        mma16816h(accC[t][j], ah[t], bl[hh * 2], bl[hh * 2 + 1]);
                    }
            }
        }
        if (c + 2 < nch) issue(c + 2);
    }
}

#define SMEM2 (NSTAGE*(10240 + 2*128*80))    // gemm2 / sim (2-term): 92160

// ---------------- GEMM1: h = tanh(x @ W1 + b1), 1-term fp16, N-tile 160 ----------------
__global__ void __launch_bounds__(256) gemm1_mma(const HF* __restrict__ Ah,
                                                 const HF* __restrict__ Bh,
                                                 const float* __restrict__ bias,
                                                 HF* __restrict__ Hh)
{
    extern __shared__ char smem[];
    float acc[2][10][4];
    #pragma unroll
    for (int t = 0; t < 2; t++)
        #pragma unroll
        for (int j = 0; j < 10; j++)
            #pragma unroll
            for (int v = 0; v < 4; v++) acc[t][j][v] = 0.f;

    long m0 = (long)blockIdx.y * 128, n0 = (long)blockIdx.x * 160;
    mma_mainloop_g1(acc, Ah, Bh, m0, n0, smem_u32(smem));

    const int tid = threadIdx.x, lane = tid & 31, wid = tid >> 5;
    const int wm = wid & 3, wn = wid >> 2;
    const int rr = lane >> 2, q = lane & 3;
    #pragma unroll
    for (int t = 0; t < 2; t++) {
        long m = m0 + wm * 32 + t * 16 + rr;
        #pragma unroll
        for (int j = 0; j < 10; j++) {
            int n = (int)n0 + wn * 80 + j * 8 + 2 * q;   // even
            if (n < HPADK) {
                float a0 = (n     < Hn) ? tanhf(acc[t][j][0] + bias[n])     : 0.f;
                float a1 = (n + 1 < Hn) ? tanhf(acc[t][j][1] + bias[n + 1]) : 0.f;
                float b0 = (n     < Hn) ? tanhf(acc[t][j][2] + bias[n])     : 0.f;
                float b1 = (n + 1 < Hn) ? tanhf(acc[t][j][3] + bias[n + 1]) : 0.f;
                __half2 ha; ha.x = __float2half(a0); ha.y = __float2half(a1);
                __half2 hb; hb.x = __float2half(b0); hb.y = __float2half(b1);
                *(__half2*)(Hh + m * HPADK + n)       = ha;
                *(__half2*)(Hh + (m + 8) * HPADK + n) = hb;
            }
        }
    }
}

// ---------------- GEMM2: enc = h @ W2 + b2 (fp32 out), 2-term ----------------
__global__ void __launch_bounds__(256) gemm2_mma(const HF* __restrict__ Ah,
                                                 const HF* __restrict__ Bh, const HF* __restrict__ Bl,
                                                 const float* __restrict__ bias, float* __restrict__ E)
{
    extern __shared__ char smem[];
    float accM[2][8][4], accC[2][8][4];
    #pragma unroll
    for (int t = 0; t < 2; t++)
        #pragma unroll
        for (int j = 0; j < 8; j++)
            #pragma unroll
            for (int v = 0; v < 4; v++) { accM[t][j][v] = 0.f; accC[t][j][v] = 0.f; }

    long m0 = (long)blockIdx.y * 128, n0 = (long)blockIdx.x * 128;
    mma_mainloop2<128>(accM, accC, Ah, Bh, Bl, m0, n0, HPADK, HPADK / 32, smem_u32(smem));

    const int tid = threadIdx.x, lane = tid & 31, wid = tid >> 5;
    const int wm = wid & 3, wn = wid >> 2;
    const int rr = lane >> 2, q = lane & 3;
    #pragma unroll
    for (int t = 0; t < 2; t++) {
        long m = m0 + wm * 32 + t * 16 + rr;
        #pragma unroll
        for (int j = 0; j < 8; j++) {
            int n = (int)n0 + wn * 64 + j * 8 + 2 * q;   // even
            if (n < ENCn) {
                float2 va, vb;
                va.x = accM[t][j][0] + accC[t][j][0] * LO_INV + bias[n];
                va.y = accM[t][j][1] + accC[t][j][1] * LO_INV + bias[n + 1];
                vb.x = accM[t][j][2] + accC[t][j][2] * LO_INV + bias[n];
                vb.y = accM[t][j][3] + accC[t][j][3] * LO_INV + bias[n + 1];
                *(float2*)(E + m * ENCn + n)       = va;
                *(float2*)(E + (m + 8) * ENCn + n) = vb;
            }
        }
    }
}

// ---------------- sim: new_output = log(mean_k exp(zn @ itn^T / tau) + 1), 2-term ----------------
// Block (0,0) additionally finalizes kl from the postenc partials.
__global__ void __launch_bounds__(256) sim_mma(const HF* __restrict__ Ah,
                                               const HF* __restrict__ Bh, const HF* __restrict__ Bl,
                                               float* __restrict__ no_out,
                                               const double* __restrict__ klp, float* __restrict__ kl_out)
{
    extern __shared__ char smem[];
    if (blockIdx.x == 0 && blockIdx.y == 0) {
        // fin_kl: reduce 512 partials with 256 threads
        __shared__ double red[8];
        int tid = threadIdx.x;
        double s = klp[tid] + klp[tid + 256];
        #pragma unroll
        for (int o = 16; o; o >>= 1) s += __shfl_xor_sync(0xffffffffu, s, o);
        if ((tid & 31) == 0) red[tid >> 5] = s;
        __syncthreads();
        if (tid < 8) {
            double t = red[tid];
            #pragma unroll
            for (int o = 4; o; o >>= 1) t += __shfl_xor_sync(0xffu, t, o);
            if (tid == 0) *kl_out = (float)(0.5 * t / (double)ROWS);
        }
        __syncthreads();
    }

    float accM[2][8][4], accC[2][8][4];
    #pragma unroll
    for (int t = 0; t < 2; t++)
        #pragma unroll
        for (int j = 0; j < 8; j++)
            #pragma unroll
            for (int v = 0; v < 4; v++) { accM[t][j][v] = 0.f; accC[t][j][v] = 0.f; }

    long m0 = (long)blockIdx.y * 128, n0 = (long)blockIdx.x * 128;
    mma_mainloop2<128>(accM, accC, Ah, Bh, Bl, m0, n0, KPAD2, KPAD2 / 32, smem_u32(smem));

    const int tid = threadIdx.x, lane = tid & 31, wid = tid >> 5;
    const int wm = wid & 3, wn = wid >> 2;
    const int q = lane & 3;
    long b = blockIdx.y * 4 + wm;     // user; warp's 32 m-rows = this user's 32 K rows
    #pragma unroll
    for (int j = 0; j < 8; j++) {
        float s0 = __expf(10.0f * (accM[0][j][0] + accC[0][j][0] * LO_INV))
                 + __expf(10.0f * (accM[0][j][2] + accC[0][j][2] * LO_INV))
                 + __expf(10.0f * (accM[1][j][0] + accC[1][j][0] * LO_INV))
                 + __expf(10.0f * (accM[1][j][2] + accC[1][j][2] * LO_INV));
        float s1 = __expf(10.0f * (accM[0][j][1] + accC[0][j][1] * LO_INV))
                 + __expf(10.0f * (accM[0][j][3] + accC[0][j][3] * LO_INV))
                 + __expf(10.0f * (accM[1][j][1] + accC[1][j][1] * LO_INV))
                 + __expf(10.0f * (accM[1][j][3] + accC[1][j][3] * LO_INV));
        #pragma unroll
        for (int off = 4; off < 32; off <<= 1) {
            s0 += __shfl_xor_sync(0xffffffffu, s0, off);
            s1 += __shfl_xor_sync(0xffffffffu, s1, off);
        }
        if (lane < 4) {
            int n = (int)n0 + wn * 64 + j * 8 + 2 * q;   // even
            if (n + 1 < In) {
                float2 v;
                v.x = logf(s0 * (1.0f / 32.0f) + 1.0f);
                v.y = logf(s1 * (1.0f / 32.0f) + 1.0f);
                *(float2*)(no_out + b * In + n) = v;
            } else if (n < In) {
                no_out[b * In + n] = logf(s0 * (1.0f / 32.0f) + 1.0f);
            }
        }
    }
}

// ---------------- fused prep: x | convW1(hi) | convW2(hi+lo) | items_norm ----------------
#define X_BLKS  ROWS                       // 4096
#define W1_KT   (KPAD1/32)                 // 376
#define W1_BLKS (W1_KT*(NPAD1/32))         // 7520
#define W2_KT   (HPADK/32)                 // 19
#define W2_BLKS (W2_KT*(NPADW/32))         // 304
#define IT_BLKS (NPAD2/16)                 // 752
#define PREP_GRID (X_BLKS + W1_BLKS + W2_BLKS + IT_BLKS)

__global__ void __launch_bounds__(512) prep_kernel(
    const float* __restrict__ rating, const int* __restrict__ items_idx,
    const float* __restrict__ gram,   const float* __restrict__ W1,
    const float* __restrict__ W2,     const float* __restrict__ items,
    float* __restrict__ x_out, HF* __restrict__ xh,
    HF* __restrict__ w1h, HF* __restrict__ w2h, HF* __restrict__ w2l,
    HF* __restrict__ ith, HF* __restrict__ itl)
{
    __shared__ float sbuf[12032];
    const int tid = threadIdx.x;
    int blk = blockIdx.x;

    if (blk < X_BLKS) {
        // ---- x = masked gram row / l2norm ----
        int bk = blk, b = bk >> 5;
        int row = items_idx[bk];
        const float4* r4 = (const float4*)(rating + (long)b * In);
        const float4* g4 = (const float4*)(gram + (long)row * In);
        float ss = 0.f;
        for (int i = tid; i < In / 4; i += 512) {
            float4 rv = r4[i];
            float4 gv = g4[i];
            float4 m;
            m.x = (rv.x > 0.f) ? gv.x : 0.f;
            m.y = (rv.y > 0.f) ? gv.y : 0.f;
            m.z = (rv.z > 0.f) ? gv.z : 0.f;
            m.w = (rv.w > 0.f) ? gv.w : 0.f;
            ss += m.x * m.x + m.y * m.y + m.z * m.z + m.w * m.w;
            *(float4*)&sbuf[i * 4] = m;
        }
        __shared__ float red[16];
        #pragma unroll
        for (int o = 16; o; o >>= 1) ss += __shfl_xor_sync(0xffffffffu, ss, o);
        if ((tid & 31) == 0) red[tid >> 5] = ss;
        __syncthreads();
        if (tid < 16) {
            float t = red[tid];
            #pragma unroll
            for (int o = 8; o; o >>= 1) t += __shfl_xor_sync(0xffffu, t, o);
            if (tid == 0) red[0] = t;
        }
        __syncthreads();
        float inv = 1.0f / fmaxf(sqrtf(red[0]), 1e-12f);
        float* dst = x_out + (long)bk * In;   // 4B-aligned only
        for (int i = tid; i < In; i += 512) dst[i] = sbuf[i] * inv;
        uint32_t* dh = (uint32_t*)(xh + (size_t)bk * KPAD1);
        for (int i = tid; i < KPAD1 / 2; i += 512) {
            int i0 = 2 * i;
            float v0 = (i0     < In) ? sbuf[i0]     * inv : 0.f;
            float v1 = (i0 + 1 < In) ? sbuf[i0 + 1] * inv : 0.f;
            __half2 hp;
            hp.x = __float2half(v0);
            hp.y = __float2half(v1);
            dh[i] = *(uint32_t*)&hp;
        }
    } else if (blk < X_BLKS + W1_BLKS) {
        // ---- W1 [In,Hn] -> W1^T hi fp16 [NPAD1][KPAD1] ----
        int i = blk - X_BLKS;
        int kb = (i % W1_KT) * 32, nb = (i / W1_KT) * 32;
        int tx = tid & 31, ty = tid >> 5;    // 16 rows
        float (*t)[33] = (float(*)[33])sbuf;
        for (int j = ty; j < 32; j += 16) {
            int k = kb + j, n = nb + tx;
            t[j][tx] = (k < In && n < Hn) ? W1[(long)k * Hn + n] : 0.f;
        }
        __syncthreads();
        for (int j = ty; j < 32; j += 16) {
            int n = nb + j, k = kb + tx;
            w1h[(size_t)n * KPAD1 + k] = __float2half(t[tx][j]);
        }
    } else if (blk < X_BLKS + W1_BLKS + W2_BLKS) {
        // ---- W2 [Hn,ENCn] -> W2^T hi/lo*512 fp16 [NPADW][HPADK] ----
        int i = blk - X_BLKS - W1_BLKS;
        int kb = (i % W2_KT) * 32, nb = (i / W2_KT) * 32;
        int tx = tid & 31, ty = tid >> 5;
        float (*t)[33] = (float(*)[33])sbuf;
        for (int j = ty; j < 32; j += 16) {
            int k = kb + j, n = nb + tx;
            t[j][tx] = (k < Hn && n < ENCn) ? W2[(long)k * ENCn + n] : 0.f;
        }
        __syncthreads();
        for (int j = ty; j < 32; j += 16) {
            int n = nb + j, k = kb + tx;
            HF h, l;
            split_hf(t[tx][j], h, l);
            w2h[(size_t)n * HPADK + k] = h;
            w2l[(size_t)n * HPADK + k] = l;
        }
    } else {
        // ---- items l2-normalize -> fp16 hi/lo*512, [NPAD2][KPAD2] ----
        int i = blk - X_BLKS - W1_BLKS - W2_BLKS;
        int warp = i * 16 + (tid >> 5);
        int lane = tid & 31;
        if (warp >= NPAD2) return;
        HF* dh = ith + (size_t)warp * KPAD2;
        HF* dl = itl + (size_t)warp * KPAD2;
        if (warp >= In) {
            for (int j = lane; j < KPAD2; j += 32) { dh[j] = __float2half(0.f); dl[j] = __float2half(0.f); }
            return;
        }
        const float* src = items + (long)warp * LATn;
        float v[7];
        float ss = 0.f;
        int cnt = 0;
        for (int j = lane; j < LATn; j += 32) { float t = src[j]; v[cnt++] = t; ss += t * t; }
        #pragma unroll
        for (int o = 16; o; o >>= 1) ss += __shfl_xor_sync(0xffffffffu, ss, o);
        float inv = 1.0f / fmaxf(sqrtf(ss), 1e-12f);
        cnt = 0;
        for (int j = lane; j < KPAD2; j += 32) {
            float t = (j < LATn) ? v[cnt++] * inv : 0.f;
            HF h, l;
            split_hf(t, h, l);
            dh[j] = h;
            dl[j] = l;
        }
    }
}

// ---------------- enc postprocess: z, zn-hi(fp16), kl partial per block ----------------
__global__ void postenc_kernel(const float* __restrict__ enc, float* __restrict__ z_out,
                               HF* __restrict__ znh, double* __restrict__ klp)
{
    __shared__ float kred[8];
    int wib  = threadIdx.x >> 5;                      // warp in block (8)
    int warp = blockIdx.x * 8 + wib;                  // global row
    int lane = threadIdx.x & 31;
    const float* e = enc + (long)warp * ENCn;
    float mv[7];
    float ss = 0.f, kl = 0.f;
    int cnt = 0;
    for (int j = lane; j < LATn; j += 32) {
        float m  = e[j];
        float lv = e[j + LATn];
        mv[cnt++] = m;
        ss += m * m;
        kl += m * m + (expm1f(lv) - lv);
    }
    #pragma unroll
    for (int o = 16; o; o >>= 1) {
        ss += __shfl_xor_sync(0xffffffffu, ss, o);
        kl += __shfl_xor_sync(0xffffffffu, kl, o);
    }
    float inv = 1.0f / fmaxf(sqrtf(ss), 1e-12f);
    cnt = 0;
    for (int j = lane; j < KPAD2; j += 32) {
        float t = 0.f;
        if (j < LATn) {
            z_out[(long)warp * LATn + j] = mv[cnt];
            t = mv[cnt++] * inv;
        }
        znh[(size_t)warp * KPAD2 + j] = __float2half(t);
    }
    if (lane == 0) kred[wib] = kl;
    __syncthreads();
    if (threadIdx.x < 8) {
        float t = kred[threadIdx.x];
        #pragma unroll
        for (int o = 4; o; o >>= 1) t += __shfl_xor_sync(0xffu, t, o);
        if (threadIdx.x == 0) klp[blockIdx.x] = (double)t;
    }
}

// ---------------- launch ----------------
extern "C" void kernel_launch(void* const* d_in, const int* in_sizes, int n_in,
                              void* d_out, int out_size)
{
    const float* rating    = (const float*)d_in[0];
    const int*   items_idx = (const int*)  d_in[1];
    const float* gram      = (const float*)d_in[2];
    const float* W1        = (const float*)d_in[3];
    const float* b1        = (const float*)d_in[4];
    const float* W2        = (const float*)d_in[5];
    const float* b2        = (const float*)d_in[6];
    const float* items     = (const float*)d_in[7];

    float* out    = (float*)d_out;
    float* z_out  = out + Z_OFF;
    float* no_out = out + NO_OFF;
    float* kl_out = out + KL_OFF;
    float* x_out  = out + X_OFF;

    float* enc; double* klp;
    HF *xh, *w1h, *hh, *w2h, *w2l, *znh, *ith, *itl;
    cudaGetSymbolAddress((void**)&enc, g_enc);
    cudaGetSymbolAddress((void**)&klp, g_klp);
    cudaGetSymbolAddress((void**)&xh,  g_xh);
    cudaGetSymbolAddress((void**)&w1h, g_w1h);
    cudaGetSymbolAddress((void**)&hh,  g_hh);
    cudaGetSymbolAddress((void**)&w2h, g_w2h);
    cudaGetSymbolAddress((void**)&w2l, g_w2l);
    cudaGetSymbolAddress((void**)&znh, g_znh);
    cudaGetSymbolAddress((void**)&ith, g_ith);
    cudaGetSymbolAddress((void**)&itl, g_itl);

    cudaFuncSetAttribute(gemm1_mma, cudaFuncAttributeMaxDynamicSharedMemorySize, SMEM1);
    cudaFuncSetAttribute(gemm2_mma, cudaFuncAttributeMaxDynamicSharedMemorySize, SMEM2);
    cudaFuncSetAttribute(sim_mma,   cudaFuncAttributeMaxDynamicSharedMemorySize, SMEM2);

    // fused prep: x + W1^T(hi) + W2^T(hi/lo) + items norm
    prep_kernel<<<PREP_GRID, 512>>>(rating, items_idx, gram, W1, W2, items,
                                    x_out, xh, w1h, w2h, w2l, ith, itl);
    // h = tanh(x @ W1 + b1): 1-term fp16 HMMA, K-chunk 64, N-tile 160 (128 CTAs, single wave)
    gemm1_mma<<<dim3(NPAD1 / 160, ROWS / 128), 256, SMEM1>>>(xh, w1h, b1, hh);
    // enc = h @ W2 + b2: 2-term (128 CTAs)
    gemm2_mma<<<dim3(NPADW / 128, ROWS / 128), 256, SMEM2>>>(hh, w2h, w2l, b2, enc);
    postenc_kernel<<<ROWS / 8, 256>>>(enc, z_out, znh, klp);
    // new_output: 2-term fp16 HMMA with fused exp/mean/log epilogue (+ kl finalize in block 0)
    sim_mma<<<dim3(NPAD2 / 128, ROWS / 128), 256, SMEM2>>>(znh, ith, itl, no_out, klp, kl_out);
}

// round 13
// speedup vs baseline: 8.5924x; 1.1622x over previous
#include <cuda_runtime.h>
#include <cuda_fp16.h>
#include <math.h>
#include <stdint.h>

#define Bn   128
#define Kn   32
#define In   12000
#define Hn   600
#define LATn 200
#define ROWS (Bn*Kn)      // 4096
#define ENCn (2*LATn)     // 400

#define KPAD1 12032       // In padded to 64 (188 x 64-chunks)
#define NPAD1 640         // Hn padded to 160
#define KPAD2 224         // LATn padded (7 x 32-chunks)
#define NPAD2 12032       // In padded to 256 (47 x 256 n-tiles)
#define HPADK 608         // Hn padded to 32  (K of gemm2)
#define NPADW 512         // ENCn padded to 128 (N of gemm2)

#define Z_OFF  0
#define NO_OFF (ROWS*LATn)                 // 819200
#define KL_OFF (NO_OFF + Bn*In)            // 2355200
#define X_OFF  (KL_OFF + 1)                // 2355201

#define LO_SCALE   512.0f
#define LO_INV     (1.0f/512.0f)

typedef __half HF;

// ---------------- scratch (no allocation allowed) ----------------
__device__ float  g_enc[ROWS*ENCn];
__device__ double g_klp[512];
__device__ HF g_xh [(size_t)ROWS*KPAD1];
__device__ HF g_w1h[(size_t)NPAD1*KPAD1];
__device__ HF g_hh [(size_t)ROWS*HPADK];
__device__ HF g_w2h[(size_t)NPADW*HPADK];
__device__ HF g_w2l[(size_t)NPADW*HPADK];    // lo * 512
__device__ HF g_znh[(size_t)ROWS*KPAD2];
__device__ HF g_ith[(size_t)NPAD2*KPAD2];

// ==================== helpers ====================
__device__ __forceinline__ uint32_t smem_u32(const void* p) {
    uint32_t a;
    asm("{ .reg .u64 t; cvta.to.shared.u64 t, %1; cvt.u32.u64 %0, t; }" : "=r"(a) : "l"(p));
    return a;
}
#define CP16(dst, src) asm volatile("cp.async.cg.shared.global [%0], [%1], 16;" :: "r"(dst), "l"(src) : "memory")
#define CP_COMMIT()    asm volatile("cp.async.commit_group;" ::: "memory")
#define CP_WAIT1()     asm volatile("cp.async.wait_group 1;" ::: "memory")
#define CP_WAIT0()     asm volatile("cp.async.wait_group 0;" ::: "memory")

__device__ __forceinline__ void ldsm4(uint32_t r[4], uint32_t addr) {
    asm volatile("ldmatrix.sync.aligned.m8n8.x4.shared.b16 {%0,%1,%2,%3}, [%4];"
        : "=r"(r[0]), "=r"(r[1]), "=r"(r[2]), "=r"(r[3]) : "r"(addr));
}
__device__ __forceinline__ void mma16816h(float d[4], const uint32_t a[4], uint32_t b0, uint32_t b1) {
    asm volatile("mma.sync.aligned.m16n8k16.row.col.f32.f16.f16.f32 "
        "{%0,%1,%2,%3}, {%4,%5,%6,%7}, {%8,%9}, {%0,%1,%2,%3};"
        : "+f"(d[0]), "+f"(d[1]), "+f"(d[2]), "+f"(d[3])
        : "r"(a[0]), "r"(a[1]), "r"(a[2]), "r"(a[3]), "r"(b0), "r"(b1));
}
__device__ __forceinline__ void split_hf(float v, HF& hi, HF& lo) {
    hi = __float2half(v);
    lo = __float2half((v - __half2float(hi)) * LO_SCALE);
}

#define NSTAGE 3

// ================ gemm1 mainloop: 1-term fp16, K-chunk 64, row stride 144 ================
// A 128 rows, B 160 rows. Warp grid 4m x 2n; warp tile 32 x 80.
#define G1_ROWB  144
#define G1_OFF_B (128*G1_ROWB)                     // 18432
#define G1_STAGE (G1_OFF_B + 160*G1_ROWB)          // 41472
#define SMEM1    (NSTAGE*G1_STAGE)                 // 124416

__device__ __forceinline__ void mma_mainloop_g1(float (&acc)[2][10][4],
    const HF* __restrict__ Ah, const HF* __restrict__ Bh,
    long m0, long n0, uint32_t smem_base)
{
    const int tid = threadIdx.x, lane = tid & 31, wid = tid >> 5;
    const int wm = wid & 3, wn = wid >> 2;
    const long rowb = (long)KPAD1 * 2;
    const int nch = KPAD1 / 64;                    // 188

    const char* bA = (const char*)(Ah + m0 * (long)KPAD1);
    const char* bB = (const char*)(Bh + n0 * (long)KPAD1);

    auto issue = [&](int c) {
        uint32_t st = smem_base + (c % NSTAGE) * G1_STAGE;
        long go = (long)c * 128;
        #pragma unroll
        for (int i = 0; i < 4; i++) {              // A: 1024 16B units
            int idx = tid + i * 256;
            int r = idx >> 3, cc = (idx & 7) * 16;
            CP16(st + r * G1_ROWB + cc, bA + r * rowb + cc + go);
        }
        #pragma unroll
        for (int i = 0; i < 5; i++) {              // B: 1280 16B units
            int idx = tid + i * 256;
            int r = idx >> 3, cc = (idx & 7) * 16;
            CP16(st + G1_OFF_B + r * G1_ROWB + cc, bB + r * rowb + cc + go);
        }
        CP_COMMIT();
    };

    issue(0);
    issue(1);

    for (int c = 0; c < nch; c++) {
        if (c + 1 < nch) CP_WAIT1(); else CP_WAIT0();
        __syncthreads();

        uint32_t sA = smem_base + (c % NSTAGE) * G1_STAGE;
        #pragma unroll
        for (int s = 0; s < 4; s++) {
            uint32_t ah[2][4];
            #pragma unroll
            for (int t = 0; t < 2; t++) {
                uint32_t row = wm * 32 + t * 16 + (lane & 15);
                ldsm4(ah[t], sA + row * G1_ROWB + s * 32 + ((lane >> 4) & 1) * 16);
            }
            #pragma unroll
            for (int p = 0; p < 5; p++) {
                uint32_t bh[4];
                uint32_t row = wn * 80 + p * 16 + (lane & 7) + ((lane & 16) ? 8 : 0);
                ldsm4(bh, sA + G1_OFF_B + row * G1_ROWB + s * 32 + ((lane & 8) ? 16 : 0));
                #pragma unroll
                for (int t = 0; t < 2; t++)
                    #pragma unroll
                    for (int hh = 0; hh < 2; hh++)
                        mma16816h(acc[t][p * 2 + hh], ah[t], bh[hh * 2], bh[hh * 2 + 1]);
            }
        }
        if (c + 2 < nch) issue(c + 2);
    }
}

// ================ generic mainloop (gemm2 2-term / sim 1-term), K-chunk 32, stride 80 ================
template<int BR, int TERMS>
__device__ __forceinline__ void mma_mainloop2(float (&accM)[2][BR/16][4], float (&accC)[2][BR/16][4],
    const HF* __restrict__ Ah, const HF* __restrict__ Bh, const HF* __restrict__ Bl,
    long m0, long n0, int kpad, int nch, uint32_t smem_base)
{
    constexpr int OFF_B  = 10240;            // A hi = 128*80
    constexpr int STAGE  = 10240 + TERMS * BR * 80;
    constexpr int NP = BR / 32;

    const int tid = threadIdx.x, lane = tid & 31, wid = tid >> 5;
    const int wm = wid & 3, wn = wid >> 2;
    const long rowb = (long)kpad * 2;

    const char* bA  = (const char*)(Ah + m0 * (long)kpad);
    const char* bBh = (const char*)(Bh + n0 * (long)kpad);
    const char* bBl = (const char*)(Bl + n0 * (long)kpad);

    const int rA = tid >> 2, ccA = (tid & 3) * 16;

    auto issue = [&](int c) {
        uint32_t st = smem_base + (c % NSTAGE) * STAGE;
        long go = (long)c * 64;
        CP16(st + rA * 80 + ccA,        bA + rA * rowb + ccA + go);
        CP16(st + (rA + 64) * 80 + ccA, bA + (rA + 64) * rowb + ccA + go);
        #pragma unroll
        for (int i = 0; i < (BR * 4 + 255) / 256; i++) {
            int idx = tid + i * 256;
            if ((BR * 4) % 256 == 0 || idx < BR * 4) {
                int r = idx >> 2, cc = (idx & 3) * 16;
                CP16(st + OFF_B + r * 80 + cc, bBh + r * rowb + cc + go);
                if (TERMS == 2)
                    CP16(st + OFF_B + BR * 80 + r * 80 + cc, bBl + r * rowb + cc + go);
            }
        }
        CP_COMMIT();
    };

    issue(0);
    if (nch > 1) issue(1);

    for (int c = 0; c < nch; c++) {
        if (c + 1 < nch) CP_WAIT1(); else CP_WAIT0();
        __syncthreads();

        uint32_t sA = smem_base + (c % NSTAGE) * STAGE;
        #pragma unroll
        for (int s = 0; s < 2; s++) {
            uint32_t ah[2][4];
            #pragma unroll
            for (int t = 0; t < 2; t++) {
                uint32_t row = wm * 32 + t * 16 + (lane & 15);
                ldsm4(ah[t], sA + row * 80 + s * 32 + ((lane >> 4) & 1) * 16);
            }
            #pragma unroll
            for (int p = 0; p < NP; p++) {
                uint32_t bh[4], bl[4];
                uint32_t row = wn * (BR / 2) + p * 16 + (lane & 7) + ((lane & 16) ? 8 : 0);
                uint32_t ad = sA + OFF_B + row * 80 + s * 32 + ((lane & 8) ? 16 : 0);
                ldsm4(bh, ad);
                if (TERMS == 2) ldsm4(bl, ad + BR * 80);
                #pragma unroll
                for (int t = 0; t < 2; t++)
                    #pragma unroll
                    for (int hh = 0; hh < 2; hh++) {
                        int j = p * 2 + hh;
                        mma16816h(accM[t][j], ah[t], bh[hh * 2], bh[hh * 2 + 1]);
                        if (TERMS == 2)
                            mma16816h(accC[t][j], ah[t], bl[hh * 2], bl[hh * 2 + 1]);
                    }
            }
        }
        if (c + 2 < nch) issue(c + 2);
    }
}

#define SMEM2 (NSTAGE*(10240 + 2*128*80))    // gemm2 (2-term, BR=128): 92160
#define SMEMS (NSTAGE*(10240 + 256*80))      // sim (1-term, BR=256):   92160

// ---------------- GEMM1: h = tanh(x @ W1 + b1), 1-term fp16, N-tile 160 ----------------
__global__ void __launch_bounds__(256) gemm1_mma(const HF* __restrict__ Ah,
                                                 const HF* __restrict__ Bh,
                                                 const float* __restrict__ bias,
                                                 HF* __restrict__ Hh)
{
    extern __shared__ char smem[];
    float acc[2][10][4];
    #pragma unroll
    for (int t = 0; t < 2; t++)
        #pragma unroll
        for (int j = 0; j < 10; j++)
            #pragma unroll
            for (int v = 0; v < 4; v++) acc[t][j][v] = 0.f;

    long m0 = (long)blockIdx.y * 128, n0 = (long)blockIdx.x * 160;
    mma_mainloop_g1(acc, Ah, Bh, m0, n0, smem_u32(smem));

    const int tid = threadIdx.x, lane = tid & 31, wid = tid >> 5;
    const int wm = wid & 3, wn = wid >> 2;
    const int rr = lane >> 2, q = lane & 3;
    #pragma unroll
    for (int t = 0; t < 2; t++) {
        long m = m0 + wm * 32 + t * 16 + rr;
        #pragma unroll
        for (int j = 0; j < 10; j++) {
            int n = (int)n0 + wn * 80 + j * 8 + 2 * q;   // even
            if (n < HPADK) {
                float a0 = (n     < Hn) ? tanhf(acc[t][j][0] + bias[n])     : 0.f;
                float a1 = (n + 1 < Hn) ? tanhf(acc[t][j][1] + bias[n + 1]) : 0.f;
                float b0 = (n     < Hn) ? tanhf(acc[t][j][2] + bias[n])     : 0.f;
                float b1 = (n + 1 < Hn) ? tanhf(acc[t][j][3] + bias[n + 1]) : 0.f;
                __half2 ha; ha.x = __float2half(a0); ha.y = __float2half(a1);
                __half2 hb; hb.x = __float2half(b0); hb.y = __float2half(b1);
                *(__half2*)(Hh + m * HPADK + n)       = ha;
                *(__half2*)(Hh + (m + 8) * HPADK + n) = hb;
            }
        }
    }
}

// ---------------- GEMM2: enc = h @ W2 + b2 (fp32 out), 2-term ----------------
__global__ void __launch_bounds__(256) gemm2_mma(const HF* __restrict__ Ah,
                                                 const HF* __restrict__ Bh, const HF* __restrict__ Bl,
                                                 const float* __restrict__ bias, float* __restrict__ E)
{
    extern __shared__ char smem[];
    float accM[2][8][4], accC[2][8][4];
    #pragma unroll
    for (int t = 0; t < 2; t++)
        #pragma unroll
        for (int j = 0; j < 8; j++)
            #pragma unroll
            for (int v = 0; v < 4; v++) { accM[t][j][v] = 0.f; accC[t][j][v] = 0.f; }

    long m0 = (long)blockIdx.y * 128, n0 = (long)blockIdx.x * 128;
    mma_mainloop2<128, 2>(accM, accC, Ah, Bh, Bl, m0, n0, HPADK, HPADK / 32, smem_u32(smem));

    const int tid = threadIdx.x, lane = tid & 31, wid = tid >> 5;
    const int wm = wid & 3, wn = wid >> 2;
    const int rr = lane >> 2, q = lane & 3;
    #pragma unroll
    for (int t = 0; t < 2; t++) {
        long m = m0 + wm * 32 + t * 16 + rr;
        #pragma unroll
        for (int j = 0; j < 8; j++) {
            int n = (int)n0 + wn * 64 + j * 8 + 2 * q;   // even
            if (n < ENCn) {
                float2 va, vb;
                va.x = accM[t][j][0] + accC[t][j][0] * LO_INV + bias[n];
                va.y = accM[t][j][1] + accC[t][j][1] * LO_INV + bias[n + 1];
                vb.x = accM[t][j][2] + accC[t][j][2] * LO_INV + bias[n];
                vb.y = accM[t][j][3] + accC[t][j][3] * LO_INV + bias[n + 1];
                *(float2*)(E + m * ENCn + n)       = va;
                *(float2*)(E + (m + 8) * ENCn + n) = vb;
            }
        }
    }
}

// ---------------- sim: new_output = log(mean_k exp(zn @ itn^T / tau) + 1) ----------------
// 1-term fp16, N-tile 256 (BR=256). Block (0,0) also finalizes kl.
__global__ void __launch_bounds__(256) sim_mma(const HF* __restrict__ Ah,
                                               const HF* __restrict__ Bh,
                                               float* __restrict__ no_out,
                                               const double* __restrict__ klp, float* __restrict__ kl_out)
{
    extern __shared__ char smem[];
    if (blockIdx.x == 0 && blockIdx.y == 0) {
        __shared__ double red[8];
        int tid = threadIdx.x;
        double s = klp[tid] + klp[tid + 256];
        #pragma unroll
        for (int o = 16; o; o >>= 1) s += __shfl_xor_sync(0xffffffffu, s, o);
        if ((tid & 31) == 0) red[tid >> 5] = s;
        __syncthreads();
        if (tid < 8) {
            double t = red[tid];
            #pragma unroll
            for (int o = 4; o; o >>= 1) t += __shfl_xor_sync(0xffu, t, o);
            if (tid == 0) *kl_out = (float)(0.5 * t / (double)ROWS);
        }
        __syncthreads();
    }

    float accM[2][16][4];
    #pragma unroll
    for (int t = 0; t < 2; t++)
        #pragma unroll
        for (int j = 0; j < 16; j++)
            #pragma unroll
            for (int v = 0; v < 4; v++) accM[t][j][v] = 0.f;

    long m0 = (long)blockIdx.y * 128, n0 = (long)blockIdx.x * 256;
    mma_mainloop2<256, 1>(accM, accM, Ah, Bh, Bh, m0, n0, KPAD2, KPAD2 / 32, smem_u32(smem));

    const int tid = threadIdx.x, lane = tid & 31, wid = tid >> 5;
    const int wm = wid & 3, wn = wid >> 2;
    const int q = lane & 3;
    long b = blockIdx.y * 4 + wm;     // user; warp's 32 m-rows = this user's 32 K rows
    #pragma unroll
    for (int j = 0; j < 16; j++) {
        float s0 = __expf(10.0f * accM[0][j][0]) + __expf(10.0f * accM[0][j][2])
                 + __expf(10.0f * accM[1][j][0]) + __expf(10.0f * accM[1][j][2]);
        float s1 = __expf(10.0f * accM[0][j][1]) + __expf(10.0f * accM[0][j][3])
                 + __expf(10.0f * accM[1][j][1]) + __expf(10.0f * accM[1][j][3]);
        #pragma unroll
        for (int off = 4; off < 32; off <<= 1) {
            s0 += __shfl_xor_sync(0xffffffffu, s0, off);
            s1 += __shfl_xor_sync(0xffffffffu, s1, off);
        }
        if (lane < 4) {
            int n = (int)n0 + wn * 128 + j * 8 + 2 * q;   // even
            if (n + 1 < In) {
                float2 v;
                v.x = logf(s0 * (1.0f / 32.0f) + 1.0f);
                v.y = logf(s1 * (1.0f / 32.0f) + 1.0f);
                *(float2*)(no_out + b * In + n) = v;
            } else if (n < In) {
                no_out[b * In + n] = logf(s0 * (1.0f / 32.0f) + 1.0f);
            }
        }
    }
}

// ---------------- fused prep: x | convW1(hi) | convW2(hi+lo) | items_norm ----------------
#define X_BLKS  ROWS                       // 4096
#define W1_KT   (KPAD1/32)                 // 376
#define W1_BLKS (W1_KT*(NPAD1/32))         // 7520
#define W2_KT   (HPADK/32)                 // 19
#define W2_BLKS (W2_KT*(NPADW/32))         // 304
#define IT_BLKS (NPAD2/16)                 // 752
#define PREP_GRID (X_BLKS + W1_BLKS + W2_BLKS + IT_BLKS)

__global__ void __launch_bounds__(512) prep_kernel(
    const float* __restrict__ rating, const int* __restrict__ items_idx,
    const float* __restrict__ gram,   const float* __restrict__ W1,
    const float* __restrict__ W2,     const float* __restrict__ items,
    float* __restrict__ x_out, HF* __restrict__ xh,
    HF* __restrict__ w1h, HF* __restrict__ w2h, HF* __restrict__ w2l,
    HF* __restrict__ ith)
{
    __shared__ float sbuf[12032];
    const int tid = threadIdx.x;
    int blk = blockIdx.x;

    if (blk < X_BLKS) {
        // ---- x = masked gram row / l2norm ----
        int bk = blk, b = bk >> 5;
        int row = items_idx[bk];
        const float4* r4 = (const float4*)(rating + (long)b * In);
        const float4* g4 = (const float4*)(gram + (long)row * In);
        float ss = 0.f;
        for (int i = tid; i < In / 4; i += 512) {
            float4 rv = r4[i];
            float4 gv = g4[i];
            float4 m;
            m.x = (rv.x > 0.f) ? gv.x : 0.f;
            m.y = (rv.y > 0.f) ? gv.y : 0.f;
            m.z = (rv.z > 0.f) ? gv.z : 0.f;
            m.w = (rv.w > 0.f) ? gv.w : 0.f;
            ss += m.x * m.x + m.y * m.y + m.z * m.z + m.w * m.w;
            *(float4*)&sbuf[i * 4] = m;
        }
        __shared__ float red[16];
        #pragma unroll
        for (int o = 16; o; o >>= 1) ss += __shfl_xor_sync(0xffffffffu, ss, o);
        if ((tid & 31) == 0) red[tid >> 5] = ss;
        __syncthreads();
        if (tid < 16) {
            float t = red[tid];
            #pragma unroll
            for (int o = 8; o; o >>= 1) t += __shfl_xor_sync(0xffffu, t, o);
            if (tid == 0) red[0] = t;
        }
        __syncthreads();
        float inv = 1.0f / fmaxf(sqrtf(red[0]), 1e-12f);
        float* dst = x_out + (long)bk * In;   // 4B-aligned only
        for (int i = tid; i < In; i += 512) dst[i] = sbuf[i] * inv;
        uint32_t* dh = (uint32_t*)(xh + (size_t)bk * KPAD1);
        for (int i = tid; i < KPAD1 / 2; i += 512) {
            int i0 = 2 * i;
            float v0 = (i0     < In) ? sbuf[i0]     * inv : 0.f;
            float v1 = (i0 + 1 < In) ? sbuf[i0 + 1] * inv : 0.f;
            __half2 hp;
            hp.x = __float2half(v0);
            hp.y = __float2half(v1);
            dh[i] = *(uint32_t*)&hp;
        }
    } else if (blk < X_BLKS + W1_BLKS) {
        // ---- W1 [In,Hn] -> W1^T hi fp16 [NPAD1][KPAD1] ----
        int i = blk - X_BLKS;
        int kb = (i % W1_KT) * 32, nb = (i / W1_KT) * 32;
        int tx = tid & 31, ty = tid >> 5;    // 16 rows
        float (*t)[33] = (float(*)[33])sbuf;
        for (int j = ty; j < 32; j += 16) {
            int k = kb + j, n = nb + tx;
            t[j][tx] = (k < In && n < Hn) ? W1[(long)k * Hn + n] : 0.f;
        }
        __syncthreads();
        for (int j = ty; j < 32; j += 16) {
            int n = nb + j, k = kb + tx;
            w1h[(size_t)n * KPAD1 + k] = __float2half(t[tx][j]);
        }
    } else if (blk < X_BLKS + W1_BLKS + W2_BLKS) {
        // ---- W2 [Hn,ENCn] -> W2^T hi/lo*512 fp16 [NPADW][HPADK] ----
        int i = blk - X_BLKS - W1_BLKS;
        int kb = (i % W2_KT) * 32, nb = (i / W2_KT) * 32;
        int tx = tid & 31, ty = tid >> 5;
        float (*t)[33] = (float(*)[33])sbuf;
        for (int j = ty; j < 32; j += 16) {
            int k = kb + j, n = nb + tx;
            t[j][tx] = (k < Hn && n < ENCn) ? W2[(long)k * ENCn + n] : 0.f;
        }
        __syncthreads();
        for (int j = ty; j < 32; j += 16) {
            int n = nb + j, k = kb + tx;
            HF h, l;
            split_hf(t[tx][j], h, l);
            w2h[(size_t)n * HPADK + k] = h;
            w2l[(size_t)n * HPADK + k] = l;
        }
    } else {
        // ---- items l2-normalize -> fp16 hi, [NPAD2][KPAD2] ----
        int i = blk - X_BLKS - W1_BLKS - W2_BLKS;
        int warp = i * 16 + (tid >> 5);
        int lane = tid & 31;
        if (warp >= NPAD2) return;
        HF* dh = ith + (size_t)warp * KPAD2;
        if (warp >= In) {
            for (int j = lane; j < KPAD2; j += 32) dh[j] = __float2half(0.f);
            return;
        }
        const float* src = items + (long)warp * LATn;
        float v[7];
        float ss = 0.f;
        int cnt = 0;
        for (int j = lane; j < LATn; j += 32) { float t = src[j]; v[cnt++] = t; ss += t * t; }
        #pragma unroll
        for (int o = 16; o; o >>= 1) ss += __shfl_xor_sync(0xffffffffu, ss, o);
        float inv = 1.0f / fmaxf(sqrtf(ss), 1e-12f);
        cnt = 0;
        for (int j = lane; j < KPAD2; j += 32) {
            float t = (j < LATn) ? v[cnt++] * inv : 0.f;
            dh[j] = __float2half(t);
        }
    }
}

// ---------------- enc postprocess: z, zn-hi(fp16), kl partial per block ----------------
__global__ void postenc_kernel(const float* __restrict__ enc, float* __restrict__ z_out,
                               HF* __restrict__ znh, double* __restrict__ klp)
{
    __shared__ float kred[8];
    int wib  = threadIdx.x >> 5;                      // warp in block (8)
    int warp = blockIdx.x * 8 + wib;                  // global row
    int lane = threadIdx.x & 31;
    const float* e = enc + (long)warp * ENCn;
    float mv[7];
    float ss = 0.f, kl = 0.f;
    int cnt = 0;
    for (int j = lane; j < LATn; j += 32) {
        float m  = e[j];
        float lv = e[j + LATn];
        mv[cnt++] = m;
        ss += m * m;
        kl += m * m + (expm1f(lv) - lv);
    }
    #pragma unroll
    for (int o = 16; o; o >>= 1) {
        ss += __shfl_xor_sync(0xffffffffu, ss, o);
        kl += __shfl_xor_sync(0xffffffffu, kl, o);
    }
    float inv = 1.0f / fmaxf(sqrtf(ss), 1e-12f);
    cnt = 0;
    for (int j = lane; j < KPAD2; j += 32) {
        float t = 0.f;
        if (j < LATn) {
            z_out[(long)warp * LATn + j] = mv[cnt];
            t = mv[cnt++] * inv;
        }
        znh[(size_t)warp * KPAD2 + j] = __float2half(t);
    }
    if (lane == 0) kred[wib] = kl;
    __syncthreads();
    if (threadIdx.x < 8) {
        float t = kred[threadIdx.x];
        #pragma unroll
        for (int o = 4; o; o >>= 1) t += __shfl_xor_sync(0xffu, t, o);
        if (threadIdx.x == 0) klp[blockIdx.x] = (double)t;
    }
}

// ---------------- launch ----------------
extern "C" void kernel_launch(void* const* d_in, const int* in_sizes, int n_in,
                              void* d_out, int out_size)
{
    const float* rating    = (const float*)d_in[0];
    const int*   items_idx = (const int*)  d_in[1];
    const float* gram      = (const float*)d_in[2];
    const float* W1        = (const float*)d_in[3];
    const float* b1        = (const float*)d_in[4];
    const float* W2        = (const float*)d_in[5];
    const float* b2        = (const float*)d_in[6];
    const float* items     = (const float*)d_in[7];

    float* out    = (float*)d_out;
    float* z_out  = out + Z_OFF;
    float* no_out = out + NO_OFF;
    float* kl_out = out + KL_OFF;
    float* x_out  = out + X_OFF;

    float* enc; double* klp;
    HF *xh, *w1h, *hh, *w2h, *w2l, *znh, *ith;
    cudaGetSymbolAddress((void**)&enc, g_enc);
    cudaGetSymbolAddress((void**)&klp, g_klp);
    cudaGetSymbolAddress((void**)&xh,  g_xh);
    cudaGetSymbolAddress((void**)&w1h, g_w1h);
    cudaGetSymbolAddress((void**)&hh,  g_hh);
    cudaGetSymbolAddress((void**)&w2h, g_w2h);
    cudaGetSymbolAddress((void**)&w2l, g_w2l);
    cudaGetSymbolAddress((void**)&znh, g_znh);
    cudaGetSymbolAddress((void**)&ith, g_ith);

    cudaFuncSetAttribute(gemm1_mma, cudaFuncAttributeMaxDynamicSharedMemorySize, SMEM1);
    cudaFuncSetAttribute(gemm2_mma, cudaFuncAttributeMaxDynamicSharedMemorySize, SMEM2);
    cudaFuncSetAttribute(sim_mma,   cudaFuncAttributeMaxDynamicSharedMemorySize, SMEMS);

    // fused prep: x + W1^T(hi) + W2^T(hi/lo) + items norm
    prep_kernel<<<PREP_GRID, 512>>>(rating, items_idx, gram, W1, W2, items,
                                    x_out, xh, w1h, w2h, w2l, ith);
    // h = tanh(x @ W1 + b1): 1-term fp16 HMMA, K-chunk 64, N-tile 160 (128 CTAs, single wave)
    gemm1_mma<<<dim3(NPAD1 / 160, ROWS / 128), 256, SMEM1>>>(xh, w1h, b1, hh);
    // enc = h @ W2 + b2: 2-term (128 CTAs)
    gemm2_mma<<<dim3(NPADW / 128, ROWS / 128), 256, SMEM2>>>(hh, w2h, w2l, b2, enc);
    postenc_kernel<<<ROWS / 8, 256>>>(enc, z_out, znh, klp);
    // new_output: 1-term fp16 HMMA, N-tile 256, fused exp/mean/log (+ kl finalize in block 0)
    sim_mma<<<dim3(NPAD2 / 256, ROWS / 128), 256, SMEMS>>>(znh, ith, no_out, klp, kl_out);
}